// round 2
// baseline (speedup 1.0000x reference)
#include <cuda_runtime.h>
#include <math.h>

#define BSZ  8
#define CH   256
#define NPIX 4096
#define IMW  64

// ---------------- scratch (device globals; alloc-free) ----------------
__device__ float g_Q[BSZ*CH*NPIX];
__device__ float g_K[BSZ*CH*NPIX];
__device__ float g_V[BSZ*CH*NPIX];
__device__ float g_attn[BSZ*CH*NPIX];
__device__ float g_h1[BSZ*CH*NPIX];
__device__ float g_invQ[BSZ*NPIX];
__device__ float g_invK[BSZ*NPIX];
__device__ float g_ksum[BSZ*CH];
__device__ float g_vsum[BSZ*CH];
__device__ float g_kv[BSZ*CH*CH];     // kv[b][k][c]
__device__ float g_A[BSZ*CH*CH];      // A[b][o][k] = sum_c rw[o,c]*kv[k,c]
__device__ float g_rv[BSZ*CH];        // rw @ vsum
__device__ float g_denom[BSZ*NPIX];

// ---------------- 1x1 conv GEMM: out[b,o,n] = sum_c w[o,c]*in[b,c,n] + bias[o]
// 128x128 tile, BK=16, 256 threads, 8x8 micro-tile
__global__ __launch_bounds__(256) void k_proj(const float* __restrict__ w,
                                              const float* __restrict__ bias,
                                              const float* __restrict__ in,
                                              float* __restrict__ out)
{
    __shared__ __align__(16) float ws[16][132];   // [k][o], padded rows
    __shared__ __align__(16) float xs[16][128];   // [k][n]
    const int b  = blockIdx.z;
    const int o0 = blockIdx.y * 128;
    const int n0 = blockIdx.x * 128;
    const float* inb = in + (size_t)b*CH*NPIX;
    const int tid = threadIdx.x;
    const int ty = tid >> 4, tx = tid & 15;
    float acc[8][8];
    #pragma unroll
    for (int i = 0; i < 8; i++) {
        #pragma unroll
        for (int j = 0; j < 8; j++) acc[i][j] = 0.f;
    }

    for (int c0 = 0; c0 < CH; c0 += 16) {
        #pragma unroll
        for (int r = 0; r < 8; r++) {
            int e = tid + r*256;
            int oo = e >> 4, kk = e & 15;
            ws[kk][oo] = w[(size_t)(o0+oo)*CH + c0 + kk];
        }
        #pragma unroll
        for (int r = 0; r < 8; r++) {
            int e = tid + r*256;
            int kk = e >> 7, nn = e & 127;
            xs[kk][nn] = inb[(size_t)(c0+kk)*NPIX + n0 + nn];
        }
        __syncthreads();
        #pragma unroll
        for (int kk = 0; kk < 16; kk++) {
            float wr[8], xr[8];
            float4 w0 = *(const float4*)&ws[kk][ty*8];
            float4 w1 = *(const float4*)&ws[kk][ty*8+4];
            wr[0]=w0.x; wr[1]=w0.y; wr[2]=w0.z; wr[3]=w0.w;
            wr[4]=w1.x; wr[5]=w1.y; wr[6]=w1.z; wr[7]=w1.w;
            float4 x0 = *(const float4*)&xs[kk][tx*8];
            float4 x1 = *(const float4*)&xs[kk][tx*8+4];
            xr[0]=x0.x; xr[1]=x0.y; xr[2]=x0.z; xr[3]=x0.w;
            xr[4]=x1.x; xr[5]=x1.y; xr[6]=x1.z; xr[7]=x1.w;
            #pragma unroll
            for (int i = 0; i < 8; i++) {
                #pragma unroll
                for (int j = 0; j < 8; j++)
                    acc[i][j] = fmaf(wr[i], xr[j], acc[i][j]);
            }
        }
        __syncthreads();
    }
    float* outb = out + (size_t)b*CH*NPIX;
    #pragma unroll
    for (int i = 0; i < 8; i++) {
        int o = o0 + ty*8 + i;
        float bv = bias[o];
        float* op = outb + (size_t)o*NPIX + n0 + tx*8;
        float4 v0, v1;
        v0.x=acc[i][0]+bv; v0.y=acc[i][1]+bv; v0.z=acc[i][2]+bv; v0.w=acc[i][3]+bv;
        v1.x=acc[i][4]+bv; v1.y=acc[i][5]+bv; v1.z=acc[i][6]+bv; v1.w=acc[i][7]+bv;
        *(float4*)op     = v0;
        *(float4*)(op+4) = v1;
    }
}

// ---------------- per-token inverse norms of Q and K ----------------
__global__ __launch_bounds__(256) void k_norms()
{
    int idx = blockIdx.x*256 + threadIdx.x;        // b*NPIX + n
    int b = idx >> 12, n = idx & 4095;
    const float* Qp = g_Q + (size_t)b*CH*NPIX + n;
    const float* Kp = g_K + (size_t)b*CH*NPIX + n;
    float sq = 0.f, sk = 0.f;
    #pragma unroll 8
    for (int c = 0; c < CH; c++) {
        float q = Qp[(size_t)c*NPIX]; sq = fmaf(q, q, sq);
        float k = Kp[(size_t)c*NPIX]; sk = fmaf(k, k, sk);
    }
    g_invQ[idx] = 1.0f / sqrtf(sq);
    g_invK[idx] = 1.0f / sqrtf(sk);
}

// ---------------- ksum[b,c] = sum_n Kn;  vsum[b,c] = sum_n V ----------------
__global__ __launch_bounds__(256) void k_colsums()
{
    int bc = blockIdx.x;
    int b = bc >> 8;
    const float* Kp = g_K + (size_t)bc*NPIX;
    const float* Vp = g_V + (size_t)bc*NPIX;
    const float* ik = g_invK + (size_t)b*NPIX;
    int tid = threadIdx.x;
    float sk = 0.f, sv = 0.f;
    for (int n = tid; n < NPIX; n += 256) {
        sk = fmaf(Kp[n], ik[n], sk);
        sv += Vp[n];
    }
    __shared__ float rk[256], rv[256];
    rk[tid] = sk; rv[tid] = sv;
    __syncthreads();
    for (int s = 128; s > 0; s >>= 1) {
        if (tid < s) { rk[tid] += rk[tid+s]; rv[tid] += rv[tid+s]; }
        __syncthreads();
    }
    if (tid == 0) { g_ksum[bc] = rk[0]; g_vsum[bc] = rv[0]; }
}

// ---------------- generic NT GEMM: out[b,i,j] = sum_l A[i,l]*(scale[l])*B[j,l]
// out is 256x256 per batch; 64x64 tile, BK=32, 4x4 micro
__global__ __launch_bounds__(256) void k_nt(const float* __restrict__ Ap, long strideA,
                                            const float* __restrict__ Bp, long strideB,
                                            const float* __restrict__ scale, long strideS,
                                            int L, float* __restrict__ out)
{
    __shared__ float As[32][65];
    __shared__ float Bs[32][65];
    const int b = blockIdx.z;
    const int i0 = blockIdx.y*64, j0 = blockIdx.x*64;
    const float* A = Ap + (size_t)b*strideA;
    const float* B = Bp + (size_t)b*strideB;
    const float* sc = scale ? scale + (size_t)b*strideS : (const float*)0;
    const int tid = threadIdx.x;
    const int ty = tid >> 4, tx = tid & 15;
    float acc[4][4];
    #pragma unroll
    for (int i = 0; i < 4; i++) {
        #pragma unroll
        for (int j = 0; j < 4; j++) acc[i][j] = 0.f;
    }

    for (int l0 = 0; l0 < L; l0 += 32) {
        #pragma unroll
        for (int r = 0; r < 8; r++) {
            int e = tid + r*256;
            int ii = e >> 5, ll = e & 31;
            float v = A[(size_t)(i0+ii)*L + l0 + ll];
            if (sc) v *= sc[l0 + ll];
            As[ll][ii] = v;
        }
        #pragma unroll
        for (int r = 0; r < 8; r++) {
            int e = tid + r*256;
            int jj = e >> 5, ll = e & 31;
            Bs[ll][jj] = B[(size_t)(j0+jj)*L + l0 + ll];
        }
        __syncthreads();
        #pragma unroll
        for (int ll = 0; ll < 32; ll++) {
            float ar[4], br[4];
            #pragma unroll
            for (int i = 0; i < 4; i++) ar[i] = As[ll][ty*4+i];
            #pragma unroll
            for (int j = 0; j < 4; j++) br[j] = Bs[ll][tx*4+j];
            #pragma unroll
            for (int i = 0; i < 4; i++) {
                #pragma unroll
                for (int j = 0; j < 4; j++)
                    acc[i][j] = fmaf(ar[i], br[j], acc[i][j]);
            }
        }
        __syncthreads();
    }
    float* ob = out + (size_t)b*CH*CH;
    #pragma unroll
    for (int i = 0; i < 4; i++) {
        #pragma unroll
        for (int j = 0; j < 4; j++)
            ob[(size_t)(i0+ty*4+i)*CH + j0 + tx*4 + j] = acc[i][j];
    }
}

// ---------------- rv[b,o] = sum_c rw[o,c]*vsum[b,c] ----------------
__global__ __launch_bounds__(256) void k_rv(const float* __restrict__ rw)
{
    int b = blockIdx.x, o = threadIdx.x;
    __shared__ float vs[256];
    vs[o] = g_vsum[b*CH + o];
    __syncthreads();
    float s = 0.f;
    const float* rp = rw + (size_t)o*CH;
    #pragma unroll 8
    for (int c = 0; c < CH; c++) s = fmaf(rp[c], vs[c], s);
    g_rv[b*CH + o] = s;
}

// ---------------- denom[b,n] = 1/(4096 + invQ[n]*sum_k Q[k,n]*ksum[k] + eps)
__global__ __launch_bounds__(256) void k_denom()
{
    int idx = blockIdx.x*256 + threadIdx.x;
    int b = idx >> 12, n = idx & 4095;
    __shared__ float ks[256];
    ks[threadIdx.x] = g_ksum[b*CH + threadIdx.x];
    __syncthreads();
    const float* Qp = g_Q + (size_t)b*CH*NPIX + n;
    float s = 0.f;
    #pragma unroll 8
    for (int c = 0; c < CH; c++) s = fmaf(Qp[(size_t)c*NPIX], ks[c], s);
    float agg = s * g_invQ[idx];
    g_denom[idx] = 1.0f / (4096.0f + agg + 1e-6f);
}

// ---------------- attn[b,o,n] = (rv[o] + invQ[n]*sum_k A[o,k]*Q[k,n])*denom[n] + rb[o]
__global__ __launch_bounds__(256) void k_attn(const float* __restrict__ rb)
{
    __shared__ __align__(16) float ws[16][132];
    __shared__ __align__(16) float xs[16][128];
    const int b  = blockIdx.z;
    const int o0 = blockIdx.y * 128;
    const int n0 = blockIdx.x * 128;
    const float* Aop = g_A + (size_t)b*CH*CH;
    const float* Qb  = g_Q + (size_t)b*CH*NPIX;
    const int tid = threadIdx.x;
    const int ty = tid >> 4, tx = tid & 15;
    float acc[8][8];
    #pragma unroll
    for (int i = 0; i < 8; i++) {
        #pragma unroll
        for (int j = 0; j < 8; j++) acc[i][j] = 0.f;
    }

    for (int c0 = 0; c0 < CH; c0 += 16) {
        #pragma unroll
        for (int r = 0; r < 8; r++) {
            int e = tid + r*256;
            int oo = e >> 4, kk = e & 15;
            ws[kk][oo] = Aop[(size_t)(o0+oo)*CH + c0 + kk];
        }
        #pragma unroll
        for (int r = 0; r < 8; r++) {
            int e = tid + r*256;
            int kk = e >> 7, nn = e & 127;
            xs[kk][nn] = Qb[(size_t)(c0+kk)*NPIX + n0 + nn];
        }
        __syncthreads();
        #pragma unroll
        for (int kk = 0; kk < 16; kk++) {
            float wr[8], xr[8];
            float4 w0 = *(const float4*)&ws[kk][ty*8];
            float4 w1 = *(const float4*)&ws[kk][ty*8+4];
            wr[0]=w0.x; wr[1]=w0.y; wr[2]=w0.z; wr[3]=w0.w;
            wr[4]=w1.x; wr[5]=w1.y; wr[6]=w1.z; wr[7]=w1.w;
            float4 x0 = *(const float4*)&xs[kk][tx*8];
            float4 x1 = *(const float4*)&xs[kk][tx*8+4];
            xr[0]=x0.x; xr[1]=x0.y; xr[2]=x0.z; xr[3]=x0.w;
            xr[4]=x1.x; xr[5]=x1.y; xr[6]=x1.z; xr[7]=x1.w;
            #pragma unroll
            for (int i = 0; i < 8; i++) {
                #pragma unroll
                for (int j = 0; j < 8; j++)
                    acc[i][j] = fmaf(wr[i], xr[j], acc[i][j]);
            }
        }
        __syncthreads();
    }
    const int nbase = n0 + tx*8;
    float iq[8], dn[8];
    #pragma unroll
    for (int j = 0; j < 8; j++) {
        iq[j] = g_invQ[b*NPIX + nbase + j];
        dn[j] = g_denom[b*NPIX + nbase + j];
    }
    float* ob = g_attn + (size_t)b*CH*NPIX;
    #pragma unroll
    for (int i = 0; i < 8; i++) {
        int o = o0 + ty*8 + i;
        float rv0 = g_rv[b*CH + o];
        float rbv = rb[o];
        float* op = ob + (size_t)o*NPIX + nbase;
        #pragma unroll
        for (int j = 0; j < 8; j++)
            op[j] = fmaf(fmaf(iq[j], acc[i][j], rv0), dn[j], rbv);
    }
}

// ---------------- 3x3 SAME conv, optional fused (h*x + x) epilogue ----------------
// tile: 128 out-channels x 128 px (2 image rows); 256 threads; 8o x 8px micro
#define KC 8
__global__ __launch_bounds__(256) void k_conv(const float* __restrict__ in,
                                              const float* __restrict__ wt,
                                              const float* __restrict__ bias,
                                              const float* __restrict__ xres,
                                              float* __restrict__ out, int fuse)
{
    __shared__ __align__(16) float ws[KC*9*128];   // [(c*9+t)*128 + o]
    __shared__ __align__(16) float xs[KC][4][72];  // [c][row ry][col+1]
    const int b  = blockIdx.z;
    const int o0 = blockIdx.y * 128;
    const int r0 = blockIdx.x * 2;
    const int tid = threadIdx.x;
    const int ty = tid >> 4;           // output-channel group (8 each)
    const int tx = tid & 15;
    const int rowsel = tx >> 3;        // which of the 2 output rows
    const int col0 = (tx & 7) * 8;     // 8 pixels per thread
    const float* inb = in + (size_t)b*CH*NPIX;

    float acc[8][8];
    #pragma unroll
    for (int i = 0; i < 8; i++) {
        #pragma unroll
        for (int j = 0; j < 8; j++) acc[i][j] = 0.f;
    }

    for (int c0 = 0; c0 < CH; c0 += KC) {
        #pragma unroll
        for (int r = 0; r < (KC*9*128)/256; r++) {
            int e = tid + r*256;
            int o = e & 127;
            int ct = e >> 7;
            int c = ct / 9, t = ct - c*9;
            ws[e] = wt[(size_t)(o0+o)*(CH*9) + (size_t)(c0+c)*9 + t];
        }
        #pragma unroll
        for (int r = 0; r < (KC*4*72)/256; r++) {
            int e = tid + r*256;
            int ix = e % 72;
            int cr = e / 72;
            int ry = cr & 3, c = cr >> 2;
            int grow = r0 - 1 + ry;
            int gcol = ix - 1;
            float v = 0.f;
            if (grow >= 0 && grow < IMW && gcol >= 0 && gcol < IMW)
                v = inb[(size_t)(c0+c)*NPIX + grow*IMW + gcol];
            xs[c][ry][ix] = v;
        }
        __syncthreads();
        #pragma unroll
        for (int c = 0; c < KC; c++) {
            #pragma unroll
            for (int dy = 0; dy < 3; dy++) {
                float xv[12];
                const float* xrow = &xs[c][rowsel + dy][col0];
                #pragma unroll
                for (int m = 0; m < 3; m++) {
                    float4 t4 = *(const float4*)(xrow + m*4);
                    xv[m*4+0]=t4.x; xv[m*4+1]=t4.y; xv[m*4+2]=t4.z; xv[m*4+3]=t4.w;
                }
                #pragma unroll
                for (int dx = 0; dx < 3; dx++) {
                    int t = dy*3 + dx;
                    const float* wp = &ws[(c*9+t)*128 + ty*8];
                    float4 w0 = *(const float4*)wp;
                    float4 w1 = *(const float4*)(wp+4);
                    float wv[8];
                    wv[0]=w0.x; wv[1]=w0.y; wv[2]=w0.z; wv[3]=w0.w;
                    wv[4]=w1.x; wv[5]=w1.y; wv[6]=w1.z; wv[7]=w1.w;
                    #pragma unroll
                    for (int i = 0; i < 8; i++) {
                        #pragma unroll
                        for (int j = 0; j < 8; j++)
                            acc[i][j] = fmaf(wv[i], xv[j+dx], acc[i][j]);
                    }
                }
            }
        }
        __syncthreads();
    }
    const int r = r0 + rowsel;
    const float* xb = xres + (size_t)b*CH*NPIX;
    float* ob = out + (size_t)b*CH*NPIX;
    #pragma unroll
    for (int i = 0; i < 8; i++) {
        int o = o0 + ty*8 + i;
        float bv = bias[o];
        size_t base = (size_t)o*NPIX + r*IMW + col0;
        #pragma unroll
        for (int j = 0; j < 8; j++) {
            float v = acc[i][j] + bv;
            if (fuse) { float xv_ = xb[base + j]; v = fmaf(v, xv_, xv_); }
            ob[base + j] = v;
        }
    }
}

// ---------------- launcher ----------------
extern "C" void kernel_launch(void* const* d_in, const int* in_sizes, int n_in,
                              void* d_out, int out_size)
{
    (void)in_sizes; (void)n_in; (void)out_size;
    const float* x   = (const float*)d_in[0];
    const float* qw  = (const float*)d_in[1];
    const float* qb  = (const float*)d_in[2];
    const float* kw  = (const float*)d_in[3];
    const float* kb  = (const float*)d_in[4];
    const float* vw  = (const float*)d_in[5];
    const float* vb  = (const float*)d_in[6];
    const float* rw  = (const float*)d_in[7];
    const float* rb  = (const float*)d_in[8];
    const float* c1w = (const float*)d_in[9];
    const float* c1b = (const float*)d_in[10];
    const float* c2w = (const float*)d_in[11];
    const float* c2b = (const float*)d_in[12];
    float* out = (float*)d_out;

    float *pQ, *pK, *pV, *pattn, *ph1, *pkv, *pA, *pinvK;
    cudaGetSymbolAddress((void**)&pQ,    g_Q);
    cudaGetSymbolAddress((void**)&pK,    g_K);
    cudaGetSymbolAddress((void**)&pV,    g_V);
    cudaGetSymbolAddress((void**)&pattn, g_attn);
    cudaGetSymbolAddress((void**)&ph1,   g_h1);
    cudaGetSymbolAddress((void**)&pkv,   g_kv);
    cudaGetSymbolAddress((void**)&pA,    g_A);
    cudaGetSymbolAddress((void**)&pinvK, g_invK);

    dim3 gproj(32, 2, BSZ);     // n-tiles, o-tiles, batch
    dim3 gnt(4, 4, BSZ);
    dim3 gconv(32, 2, BSZ);

    // 1) Q, K, V projections
    k_proj<<<gproj, 256>>>(qw, qb, x, pQ);
    k_proj<<<gproj, 256>>>(kw, kb, x, pK);
    k_proj<<<gproj, 256>>>(vw, vb, x, pV);
    // 2) per-token inverse norms
    k_norms<<<(BSZ*NPIX)/256, 256>>>();
    // 3) ksum (normalized) and vsum
    k_colsums<<<BSZ*CH, 256>>>();
    // 4) kv[b,k,c] = sum_n (K*invK)[k,n] * V[c,n]
    k_nt<<<gnt, 256>>>(pK, (long)CH*NPIX, pV, (long)CH*NPIX, pinvK, (long)NPIX, NPIX, pkv);
    // 5) A[b,o,k] = sum_c rw[o,c] * kv[b,k,c]
    k_nt<<<gnt, 256>>>(rw, 0L, pkv, (long)CH*CH, (const float*)0, 0L, CH, pA);
    // 6) rv = rw @ vsum
    k_rv<<<BSZ, 256>>>(rw);
    // 7) denom
    k_denom<<<(BSZ*NPIX)/256, 256>>>();
    // 8) attn = (rv + invQ * A@Q) * denom + rb
    k_attn<<<gproj, 256>>>(rb);
    // 9) conv1
    k_conv<<<gconv, 256>>>(pattn, c1w, c1b, (const float*)0, ph1, 0);
    // 10) conv2 fused with h*x + x
    k_conv<<<gconv, 256>>>(ph1, c2w, c2b, x, out, 1);
}

// round 4
// speedup vs baseline: 2.8973x; 2.8973x over previous
#include <cuda_runtime.h>
#include <cuda_bf16.h>
#include <math.h>
#include <cstdint>

#define BSZ  8
#define CH   256
#define NPIX 4096
#define IMW  64
#define LDA  40   // bf16 elems per smem row (80B, conflict-free ldmatrix)

// ---------------- scratch (device globals; alloc-free) ----------------
__device__ float g_Q[BSZ*CH*NPIX];
__device__ float g_K[BSZ*CH*NPIX];
__device__ float g_V[BSZ*CH*NPIX];
__device__ float g_attn[BSZ*CH*NPIX];
__device__ float g_h1[BSZ*CH*NPIX];
__device__ float g_invQ[BSZ*NPIX];
__device__ float g_invK[BSZ*NPIX];
__device__ float g_ksum[BSZ*CH];
__device__ float g_vsum[BSZ*CH];
__device__ float g_kv[BSZ*CH*CH];
__device__ float g_A[BSZ*CH*CH];
__device__ float g_rv[BSZ*CH];
__device__ float g_denom[BSZ*NPIX];

// ================= warp-MMA helpers (baseline sm_103 PTX features) =================
__device__ __forceinline__ uint32_t smem_u32(const void* p) {
    uint32_t a;
    asm("{ .reg .u64 t; cvta.to.shared.u64 t, %1; cvt.u32.u64 %0, t; }" : "=r"(a) : "l"(p));
    return a;
}
__device__ __forceinline__ void ldsm_x4(uint32_t (&r)[4], uint32_t addr) {
    asm volatile("ldmatrix.sync.aligned.m8n8.x4.shared.b16 {%0,%1,%2,%3}, [%4];"
        : "=r"(r[0]), "=r"(r[1]), "=r"(r[2]), "=r"(r[3]) : "r"(addr));
}
__device__ __forceinline__ void mma16816(float (&d)[4], const uint32_t (&a)[4],
                                         uint32_t b0, uint32_t b1) {
    asm volatile("mma.sync.aligned.m16n8k16.row.col.f32.bf16.bf16.f32 "
        "{%0,%1,%2,%3}, {%4,%5,%6,%7}, {%8,%9}, {%0,%1,%2,%3};"
        : "+f"(d[0]), "+f"(d[1]), "+f"(d[2]), "+f"(d[3])
        : "r"(a[0]), "r"(a[1]), "r"(a[2]), "r"(a[3]), "r"(b0), "r"(b1));
}

// Shared mainloop compute step for one 32-wide K chunk.
// As: [128][LDA] (M x K), Bs: [128][LDA] (N x K). Warp (wm 0-3, wn 0-1) -> 32M x 64N.
#define MMA_CHUNK(As, Bs, acc, lane, wm, wn) do {                                   \
    _Pragma("unroll")                                                               \
    for (int ks = 0; ks < 2; ks++) {                                                \
        uint32_t a_[2][4];                                                          \
        _Pragma("unroll")                                                           \
        for (int mi = 0; mi < 2; mi++)                                              \
            ldsm_x4(a_[mi], smem_u32(&(As)[(wm)*32 + mi*16 + ((lane)&15)]           \
                                         [ks*16 + ((lane)>>4)*8]));                 \
        uint32_t b_[4][4];                                                          \
        _Pragma("unroll")                                                           \
        for (int ni = 0; ni < 4; ni++)                                              \
            ldsm_x4(b_[ni], smem_u32(&(Bs)[(wn)*64 + ni*16 + (((lane)>>4)&1)*8      \
                                           + ((lane)&7)]                            \
                                          [ks*16 + (((lane)>>3)&1)*8]));            \
        _Pragma("unroll")                                                           \
        for (int mi = 0; mi < 2; mi++) {                                            \
            _Pragma("unroll")                                                       \
            for (int ni = 0; ni < 4; ni++) {                                        \
                mma16816(acc[mi][ni*2],   a_[mi], b_[ni][0], b_[ni][1]);            \
                mma16816(acc[mi][ni*2+1], a_[mi], b_[ni][2], b_[ni][3]);            \
            }                                                                       \
        }                                                                           \
    }                                                                               \
} while (0)

// ---------------- bf16 MMA 1x1-conv GEMM: out[b,o,n] = w@in + bias ----------------
__global__ __launch_bounds__(256) void k_proj_tc(const float* __restrict__ w,
                                                 const float* __restrict__ bias,
                                                 const float* __restrict__ in,
                                                 float* __restrict__ out)
{
    __shared__ __align__(16) __nv_bfloat16 As[2][128][LDA];
    __shared__ __align__(16) __nv_bfloat16 Bs[2][128][LDA];
    const int b  = blockIdx.z;
    const int o0 = blockIdx.y * 128;
    const int n0 = blockIdx.x * 128;
    const float* inb = in + (size_t)b*CH*NPIX;
    const int tid = threadIdx.x;
    const int wid = tid >> 5, lane = tid & 31;
    const int wm = wid & 3, wn = wid >> 2;

    float acc[2][8][4];
    #pragma unroll
    for (int i = 0; i < 2; i++) {
        #pragma unroll
        for (int j = 0; j < 8; j++) {
            #pragma unroll
            for (int q = 0; q < 4; q++) acc[i][j][q] = 0.f;
        }
    }

    // prefetch chunk 0
    #pragma unroll
    for (int i = 0; i < 16; i++) {
        int e = tid + i*256;
        int o = e >> 5, c = e & 31;
        As[0][o][c] = __float2bfloat16(w[(size_t)(o0+o)*CH + c]);
    }
    #pragma unroll
    for (int i = 0; i < 16; i++) {
        int e = tid + i*256;
        int c = e >> 7, n = e & 127;
        Bs[0][n][c] = __float2bfloat16(inb[(size_t)c*NPIX + n0 + n]);
    }

    for (int kc = 0; kc < 8; kc++) {
        __syncthreads();
        int buf = kc & 1;
        if (kc + 1 < 8) {
            int cb = (kc + 1) * 32;
            #pragma unroll
            for (int i = 0; i < 16; i++) {
                int e = tid + i*256;
                int o = e >> 5, c = e & 31;
                As[buf^1][o][c] = __float2bfloat16(w[(size_t)(o0+o)*CH + cb + c]);
            }
            #pragma unroll
            for (int i = 0; i < 16; i++) {
                int e = tid + i*256;
                int c = e >> 7, n = e & 127;
                Bs[buf^1][n][c] = __float2bfloat16(inb[(size_t)(cb+c)*NPIX + n0 + n]);
            }
        }
        MMA_CHUNK(As[buf], Bs[buf], acc, lane, wm, wn);
    }

    float* ob = out + (size_t)b*CH*NPIX;
    const int r0 = lane >> 2, c2 = (lane & 3)*2;
    #pragma unroll
    for (int mi = 0; mi < 2; mi++) {
        int o_lo = o0 + wm*32 + mi*16 + r0;
        int o_hi = o_lo + 8;
        float blo = bias[o_lo], bhi = bias[o_hi];
        #pragma unroll
        for (int nj = 0; nj < 8; nj++) {
            int n = n0 + wn*64 + nj*8 + c2;
            float2 vlo = make_float2(acc[mi][nj][0] + blo, acc[mi][nj][1] + blo);
            float2 vhi = make_float2(acc[mi][nj][2] + bhi, acc[mi][nj][3] + bhi);
            *(float2*)(ob + (size_t)o_lo*NPIX + n) = vlo;
            *(float2*)(ob + (size_t)o_hi*NPIX + n) = vhi;
        }
    }
}

// ---------------- bf16 MMA attn GEMM + epilogue ----------------
// attn[b,o,n] = (rv[o] + invQ[n]*sum_k A[o,k]*Q[k,n])*denom[n] + rb[o]
__global__ __launch_bounds__(256) void k_attn_tc(const float* __restrict__ rb)
{
    __shared__ __align__(16) __nv_bfloat16 As[2][128][LDA];
    __shared__ __align__(16) __nv_bfloat16 Bs[2][128][LDA];
    const int b  = blockIdx.z;
    const int o0 = blockIdx.y * 128;
    const int n0 = blockIdx.x * 128;
    const float* Am = g_A + (size_t)b*CH*CH;
    const float* Qb = g_Q + (size_t)b*CH*NPIX;
    const int tid = threadIdx.x;
    const int wid = tid >> 5, lane = tid & 31;
    const int wm = wid & 3, wn = wid >> 2;

    float acc[2][8][4];
    #pragma unroll
    for (int i = 0; i < 2; i++) {
        #pragma unroll
        for (int j = 0; j < 8; j++) {
            #pragma unroll
            for (int q = 0; q < 4; q++) acc[i][j][q] = 0.f;
        }
    }

    #pragma unroll
    for (int i = 0; i < 16; i++) {
        int e = tid + i*256;
        int o = e >> 5, c = e & 31;
        As[0][o][c] = __float2bfloat16(Am[(size_t)(o0+o)*CH + c]);
    }
    #pragma unroll
    for (int i = 0; i < 16; i++) {
        int e = tid + i*256;
        int c = e >> 7, n = e & 127;
        Bs[0][n][c] = __float2bfloat16(Qb[(size_t)c*NPIX + n0 + n]);
    }

    for (int kc = 0; kc < 8; kc++) {
        __syncthreads();
        int buf = kc & 1;
        if (kc + 1 < 8) {
            int cb = (kc + 1) * 32;
            #pragma unroll
            for (int i = 0; i < 16; i++) {
                int e = tid + i*256;
                int o = e >> 5, c = e & 31;
                As[buf^1][o][c] = __float2bfloat16(Am[(size_t)(o0+o)*CH + cb + c]);
            }
            #pragma unroll
            for (int i = 0; i < 16; i++) {
                int e = tid + i*256;
                int c = e >> 7, n = e & 127;
                Bs[buf^1][n][c] = __float2bfloat16(Qb[(size_t)(cb+c)*NPIX + n0 + n]);
            }
        }
        MMA_CHUNK(As[buf], Bs[buf], acc, lane, wm, wn);
    }

    float* ob = g_attn + (size_t)b*CH*NPIX;
    const int r0 = lane >> 2, c2 = (lane & 3)*2;
    #pragma unroll
    for (int mi = 0; mi < 2; mi++) {
        int o_lo = o0 + wm*32 + mi*16 + r0;
        int o_hi = o_lo + 8;
        float rvlo = g_rv[b*CH + o_lo], rvhi = g_rv[b*CH + o_hi];
        float rblo = rb[o_lo], rbhi = rb[o_hi];
        #pragma unroll
        for (int nj = 0; nj < 8; nj++) {
            int n = n0 + wn*64 + nj*8 + c2;
            float iq0 = g_invQ[b*NPIX + n],     dn0 = g_denom[b*NPIX + n];
            float iq1 = g_invQ[b*NPIX + n + 1], dn1 = g_denom[b*NPIX + n + 1];
            float2 vlo, vhi;
            vlo.x = fmaf(fmaf(iq0, acc[mi][nj][0], rvlo), dn0, rblo);
            vlo.y = fmaf(fmaf(iq1, acc[mi][nj][1], rvlo), dn1, rblo);
            vhi.x = fmaf(fmaf(iq0, acc[mi][nj][2], rvhi), dn0, rbhi);
            vhi.y = fmaf(fmaf(iq1, acc[mi][nj][3], rvhi), dn1, rbhi);
            *(float2*)(ob + (size_t)o_lo*NPIX + n) = vlo;
            *(float2*)(ob + (size_t)o_hi*NPIX + n) = vhi;
        }
    }
}

// ---------------- bf16 MMA 3x3 conv (implicit GEMM over 9 taps x 8 c-blocks) ----------------
__global__ __launch_bounds__(256) void k_conv_tc(const float* __restrict__ in,
                                                 const float* __restrict__ wt,
                                                 const float* __restrict__ bias,
                                                 const float* __restrict__ xres,
                                                 float* __restrict__ out, int fuse)
{
    __shared__ __align__(16) __nv_bfloat16 As[2][128][LDA];
    __shared__ __align__(16) __nv_bfloat16 Bs[2][128][LDA];
    const int b   = blockIdx.z;
    const int o0  = blockIdx.y * 128;
    const int pr0 = blockIdx.x * 2;          // first of 2 image rows (128 px)
    const float* inb = in + (size_t)b*CH*NPIX;
    const int tid = threadIdx.x;
    const int wid = tid >> 5, lane = tid & 31;
    const int wm = wid & 3, wn = wid >> 2;

    float acc[2][8][4];
    #pragma unroll
    for (int i = 0; i < 2; i++) {
        #pragma unroll
        for (int j = 0; j < 8; j++) {
            #pragma unroll
            for (int q = 0; q < 4; q++) acc[i][j][q] = 0.f;
        }
    }

    // chunk kc: t = kc/8 (tap), cb = (kc%8)*32
    // prefetch chunk 0 (t=0 -> dy=-1, dx=-1)
    #pragma unroll
    for (int i = 0; i < 16; i++) {
        int e = tid + i*256;
        int o = e >> 5, c = e & 31;
        As[0][o][c] = __float2bfloat16(wt[(size_t)(o0+o)*(CH*9) + (size_t)c*9 + 0]);
    }
    #pragma unroll
    for (int i = 0; i < 16; i++) {
        int e = tid + i*256;
        int c = e >> 7, px = e & 127;
        int prow = pr0 + (px >> 6) - 1;
        int pcol = (px & 63) - 1;
        float v = 0.f;
        if (prow >= 0 && prow < IMW && pcol >= 0 && pcol < IMW)
            v = inb[(size_t)c*NPIX + prow*IMW + pcol];
        Bs[0][px][c] = __float2bfloat16(v);
    }

    for (int kc = 0; kc < 72; kc++) {
        __syncthreads();
        int buf = kc & 1;
        if (kc + 1 < 72) {
            int kn = kc + 1;
            int t = kn >> 3, cb = (kn & 7) * 32;
            int dy = t / 3 - 1, dx = t % 3 - 1;
            #pragma unroll
            for (int i = 0; i < 16; i++) {
                int e = tid + i*256;
                int o = e >> 5, c = e & 31;
                As[buf^1][o][c] = __float2bfloat16(
                    wt[(size_t)(o0+o)*(CH*9) + (size_t)(cb+c)*9 + t]);
            }
            #pragma unroll
            for (int i = 0; i < 16; i++) {
                int e = tid + i*256;
                int c = e >> 7, px = e & 127;
                int prow = pr0 + (px >> 6) + dy;
                int pcol = (px & 63) + dx;
                float v = 0.f;
                if (prow >= 0 && prow < IMW && pcol >= 0 && pcol < IMW)
                    v = inb[(size_t)(cb+c)*NPIX + prow*IMW + pcol];
                Bs[buf^1][px][c] = __float2bfloat16(v);
            }
        }
        MMA_CHUNK(As[buf], Bs[buf], acc, lane, wm, wn);
    }

    const float* xb = xres + (size_t)b*CH*NPIX;
    float* ob = out + (size_t)b*CH*NPIX;
    const int r0 = lane >> 2, c2 = (lane & 3)*2;
    const int pxbase = pr0*64;               // CTA's 128-px window start
    #pragma unroll
    for (int mi = 0; mi < 2; mi++) {
        int o_lo = o0 + wm*32 + mi*16 + r0;
        int o_hi = o_lo + 8;
        float blo = bias[o_lo], bhi = bias[o_hi];
        #pragma unroll
        for (int nj = 0; nj < 8; nj++) {
            int px = pxbase + wn*64 + nj*8 + c2;
            float v0 = acc[mi][nj][0] + blo, v1 = acc[mi][nj][1] + blo;
            float v2 = acc[mi][nj][2] + bhi, v3 = acc[mi][nj][3] + bhi;
            if (fuse) {
                float2 xlo = *(const float2*)(xb + (size_t)o_lo*NPIX + px);
                float2 xhi = *(const float2*)(xb + (size_t)o_hi*NPIX + px);
                v0 = fmaf(v0, xlo.x, xlo.x);
                v1 = fmaf(v1, xlo.y, xlo.y);
                v2 = fmaf(v2, xhi.x, xhi.x);
                v3 = fmaf(v3, xhi.y, xhi.y);
            }
            *(float2*)(ob + (size_t)o_lo*NPIX + px) = make_float2(v0, v1);
            *(float2*)(ob + (size_t)o_hi*NPIX + px) = make_float2(v2, v3);
        }
    }
}

// ---------------- per-token inverse norms of Q and K ----------------
__global__ __launch_bounds__(256) void k_norms()
{
    int idx = blockIdx.x*256 + threadIdx.x;
    int b = idx >> 12, n = idx & 4095;
    const float* Qp = g_Q + (size_t)b*CH*NPIX + n;
    const float* Kp = g_K + (size_t)b*CH*NPIX + n;
    float sq = 0.f, sk = 0.f;
    #pragma unroll 8
    for (int c = 0; c < CH; c++) {
        float q = Qp[(size_t)c*NPIX]; sq = fmaf(q, q, sq);
        float k = Kp[(size_t)c*NPIX]; sk = fmaf(k, k, sk);
    }
    g_invQ[idx] = 1.0f / sqrtf(sq);
    g_invK[idx] = 1.0f / sqrtf(sk);
}

// ---------------- ksum / vsum ----------------
__global__ __launch_bounds__(256) void k_colsums()
{
    int bc = blockIdx.x;
    int b = bc >> 8;
    const float* Kp = g_K + (size_t)bc*NPIX;
    const float* Vp = g_V + (size_t)bc*NPIX;
    const float* ik = g_invK + (size_t)b*NPIX;
    int tid = threadIdx.x;
    float sk = 0.f, sv = 0.f;
    for (int n = tid; n < NPIX; n += 256) {
        sk = fmaf(Kp[n], ik[n], sk);
        sv += Vp[n];
    }
    __shared__ float rk[256], rv[256];
    rk[tid] = sk; rv[tid] = sv;
    __syncthreads();
    for (int s = 128; s > 0; s >>= 1) {
        if (tid < s) { rk[tid] += rk[tid+s]; rv[tid] += rv[tid+s]; }
        __syncthreads();
    }
    if (tid == 0) { g_ksum[bc] = rk[0]; g_vsum[bc] = rv[0]; }
}

// ---------------- generic NT GEMM (fp32, small) ----------------
__global__ __launch_bounds__(256) void k_nt(const float* __restrict__ Ap, long strideA,
                                            const float* __restrict__ Bp, long strideB,
                                            const float* __restrict__ scale, long strideS,
                                            int L, float* __restrict__ out)
{
    __shared__ float As[32][65];
    __shared__ float Bs[32][65];
    const int b = blockIdx.z;
    const int i0 = blockIdx.y*64, j0 = blockIdx.x*64;
    const float* A = Ap + (size_t)b*strideA;
    const float* B = Bp + (size_t)b*strideB;
    const float* sc = scale ? scale + (size_t)b*strideS : (const float*)0;
    const int tid = threadIdx.x;
    const int ty = tid >> 4, tx = tid & 15;
    float acc[4][4];
    #pragma unroll
    for (int i = 0; i < 4; i++) {
        #pragma unroll
        for (int j = 0; j < 4; j++) acc[i][j] = 0.f;
    }

    for (int l0 = 0; l0 < L; l0 += 32) {
        #pragma unroll
        for (int r = 0; r < 8; r++) {
            int e = tid + r*256;
            int ii = e >> 5, ll = e & 31;
            float v = A[(size_t)(i0+ii)*L + l0 + ll];
            if (sc) v *= sc[l0 + ll];
            As[ll][ii] = v;
        }
        #pragma unroll
        for (int r = 0; r < 8; r++) {
            int e = tid + r*256;
            int jj = e >> 5, ll = e & 31;
            Bs[ll][jj] = B[(size_t)(j0+jj)*L + l0 + ll];
        }
        __syncthreads();
        #pragma unroll
        for (int ll = 0; ll < 32; ll++) {
            float ar[4], br[4];
            #pragma unroll
            for (int i = 0; i < 4; i++) ar[i] = As[ll][ty*4+i];
            #pragma unroll
            for (int j = 0; j < 4; j++) br[j] = Bs[ll][tx*4+j];
            #pragma unroll
            for (int i = 0; i < 4; i++) {
                #pragma unroll
                for (int j = 0; j < 4; j++)
                    acc[i][j] = fmaf(ar[i], br[j], acc[i][j]);
            }
        }
        __syncthreads();
    }
    float* ob = out + (size_t)b*CH*CH;
    #pragma unroll
    for (int i = 0; i < 4; i++) {
        #pragma unroll
        for (int j = 0; j < 4; j++)
            ob[(size_t)(i0+ty*4+i)*CH + j0 + tx*4 + j] = acc[i][j];
    }
}

// ---------------- rv[b,o] = rw @ vsum ----------------
__global__ __launch_bounds__(256) void k_rv(const float* __restrict__ rw)
{
    int b = blockIdx.x, o = threadIdx.x;
    __shared__ float vs[256];
    vs[o] = g_vsum[b*CH + o];
    __syncthreads();
    float s = 0.f;
    const float* rp = rw + (size_t)o*CH;
    #pragma unroll 8
    for (int c = 0; c < CH; c++) s = fmaf(rp[c], vs[c], s);
    g_rv[b*CH + o] = s;
}

// ---------------- denom ----------------
__global__ __launch_bounds__(256) void k_denom()
{
    int idx = blockIdx.x*256 + threadIdx.x;
    int b = idx >> 12, n = idx & 4095;
    __shared__ float ks[256];
    ks[threadIdx.x] = g_ksum[b*CH + threadIdx.x];
    __syncthreads();
    const float* Qp = g_Q + (size_t)b*CH*NPIX + n;
    float s = 0.f;
    #pragma unroll 8
    for (int c = 0; c < CH; c++) s = fmaf(Qp[(size_t)c*NPIX], ks[c], s);
    float agg = s * g_invQ[idx];
    g_denom[idx] = 1.0f / (4096.0f + agg + 1e-6f);
}

// ---------------- launcher ----------------
extern "C" void kernel_launch(void* const* d_in, const int* in_sizes, int n_in,
                              void* d_out, int out_size)
{
    (void)in_sizes; (void)n_in; (void)out_size;
    const float* x   = (const float*)d_in[0];
    const float* qw  = (const float*)d_in[1];
    const float* qb  = (const float*)d_in[2];
    const float* kw  = (const float*)d_in[3];
    const float* kb  = (const float*)d_in[4];
    const float* vw  = (const float*)d_in[5];
    const float* vb  = (const float*)d_in[6];
    const float* rw  = (const float*)d_in[7];
    const float* rb  = (const float*)d_in[8];
    const float* c1w = (const float*)d_in[9];
    const float* c1b = (const float*)d_in[10];
    const float* c2w = (const float*)d_in[11];
    const float* c2b = (const float*)d_in[12];
    float* out = (float*)d_out;

    float *pQ, *pK, *pV, *pattn, *ph1, *pkv, *pinvK, *pA;
    cudaGetSymbolAddress((void**)&pQ,    g_Q);
    cudaGetSymbolAddress((void**)&pK,    g_K);
    cudaGetSymbolAddress((void**)&pV,    g_V);
    cudaGetSymbolAddress((void**)&pattn, g_attn);
    cudaGetSymbolAddress((void**)&ph1,   g_h1);
    cudaGetSymbolAddress((void**)&pkv,   g_kv);
    cudaGetSymbolAddress((void**)&pA,    g_A);
    cudaGetSymbolAddress((void**)&pinvK, g_invK);

    dim3 gproj(32, 2, BSZ);
    dim3 gnt(4, 4, BSZ);
    dim3 gconv(32, 2, BSZ);

    k_proj_tc<<<gproj, 256>>>(qw, qb, x, pQ);
    k_proj_tc<<<gproj, 256>>>(kw, kb, x, pK);
    k_proj_tc<<<gproj, 256>>>(vw, vb, x, pV);
    k_norms<<<(BSZ*NPIX)/256, 256>>>();
    k_colsums<<<BSZ*CH, 256>>>();
    k_nt<<<gnt, 256>>>(pK, (long)CH*NPIX, pV, (long)CH*NPIX, pinvK, (long)NPIX, NPIX, pkv);
    k_nt<<<gnt, 256>>>(rw, 0L, pkv, (long)CH*CH, (const float*)0, 0L, CH, pA);
    k_rv<<<BSZ, 256>>>(rw);
    k_denom<<<(BSZ*NPIX)/256, 256>>>();
    k_attn_tc<<<gproj, 256>>>(rb);
    k_conv_tc<<<gconv, 256>>>(pattn, c1w, c1b, (const float*)0, ph1, 0);
    k_conv_tc<<<gconv, 256>>>(ph1, c2w, c2b, x, out, 1);
}

// round 5
// speedup vs baseline: 3.8990x; 1.3457x over previous
#include <cuda_runtime.h>
#include <cuda_bf16.h>
#include <math.h>
#include <cstdint>

#define BSZ  8
#define CH   256
#define NPIX 4096
#define IMW  64
#define LDA  40   // bf16 elems per smem row (80B, conflict-free ldmatrix)

// ---------------- scratch (device globals; alloc-free) ----------------
__device__ float g_Q[BSZ*CH*NPIX];
__device__ float g_K[BSZ*CH*NPIX];
__device__ float g_V[BSZ*CH*NPIX];
__device__ float g_invQ[BSZ*NPIX];
__device__ float g_invK[BSZ*NPIX];
__device__ float g_ksum[BSZ*CH];
__device__ float g_vsum[BSZ*CH];
__device__ float g_kv[BSZ*CH*CH];
__device__ float g_A[BSZ*CH*CH];
__device__ float g_rv[BSZ*CH];
__device__ float g_denom[BSZ*NPIX];
// bf16 operands
__device__ __nv_bfloat16 g_xbf[BSZ*CH*NPIX];
__device__ __nv_bfloat16 g_attnbf[BSZ*CH*NPIX];
__device__ __nv_bfloat16 g_h1bf[BSZ*CH*NPIX];
__device__ __nv_bfloat16 g_wqb[CH*CH];
__device__ __nv_bfloat16 g_wkb[CH*CH];
__device__ __nv_bfloat16 g_wvb[CH*CH];
__device__ __nv_bfloat16 g_wc1b[9*CH*CH];   // [t][o][c]
__device__ __nv_bfloat16 g_wc2b[9*CH*CH];

// ================= warp-MMA helpers =================
__device__ __forceinline__ uint32_t smem_u32(const void* p) {
    uint32_t a;
    asm("{ .reg .u64 t; cvta.to.shared.u64 t, %1; cvt.u32.u64 %0, t; }" : "=r"(a) : "l"(p));
    return a;
}
__device__ __forceinline__ void ldsm_x4(uint32_t (&r)[4], uint32_t addr) {
    asm volatile("ldmatrix.sync.aligned.m8n8.x4.shared.b16 {%0,%1,%2,%3}, [%4];"
        : "=r"(r[0]), "=r"(r[1]), "=r"(r[2]), "=r"(r[3]) : "r"(addr));
}
__device__ __forceinline__ void mma16816(float (&d)[4], const uint32_t (&a)[4],
                                         uint32_t b0, uint32_t b1) {
    asm volatile("mma.sync.aligned.m16n8k16.row.col.f32.bf16.bf16.f32 "
        "{%0,%1,%2,%3}, {%4,%5,%6,%7}, {%8,%9}, {%0,%1,%2,%3};"
        : "+f"(d[0]), "+f"(d[1]), "+f"(d[2]), "+f"(d[3])
        : "r"(a[0]), "r"(a[1]), "r"(a[2]), "r"(a[3]), "r"(b0), "r"(b1));
}

// MMA chunk for ldmatrix-based kernels (proj/attn): As/Bs [128][LDA]
#define MMA_CHUNK(As, Bs, acc, lane, wm, wn) do {                                   \
    _Pragma("unroll")                                                               \
    for (int ks = 0; ks < 2; ks++) {                                                \
        uint32_t a_[2][4];                                                          \
        _Pragma("unroll")                                                           \
        for (int mi = 0; mi < 2; mi++)                                              \
            ldsm_x4(a_[mi], smem_u32(&(As)[(wm)*32 + mi*16 + ((lane)&15)]           \
                                         [ks*16 + ((lane)>>4)*8]));                 \
        uint32_t b_[4][4];                                                          \
        _Pragma("unroll")                                                           \
        for (int ni = 0; ni < 4; ni++)                                              \
            ldsm_x4(b_[ni], smem_u32(&(Bs)[(wn)*64 + ni*16 + (((lane)>>4)&1)*8      \
                                           + ((lane)&7)]                            \
                                          [ks*16 + (((lane)>>3)&1)*8]));            \
        _Pragma("unroll")                                                           \
        for (int mi = 0; mi < 2; mi++) {                                            \
            _Pragma("unroll")                                                       \
            for (int ni = 0; ni < 4; ni++) {                                        \
                mma16816(acc[mi][ni*2],   a_[mi], b_[ni][0], b_[ni][1]);            \
                mma16816(acc[mi][ni*2+1], a_[mi], b_[ni][2], b_[ni][3]);            \
            }                                                                       \
        }                                                                           \
    }                                                                               \
} while (0)

// ---------------- conversion kernels ----------------
__global__ __launch_bounds__(256) void k_cvt(const float* __restrict__ src,
                                             __nv_bfloat16* __restrict__ dst)
{
    int i = (blockIdx.x*256 + threadIdx.x) * 4;
    float4 v = *(const float4*)(src + i);
    dst[i+0] = __float2bfloat16(v.x);
    dst[i+1] = __float2bfloat16(v.y);
    dst[i+2] = __float2bfloat16(v.z);
    dst[i+3] = __float2bfloat16(v.w);
}
// conv weights: [o][c][t] float -> [t][o][c] bf16
__global__ __launch_bounds__(256) void k_cvt_wc(const float* __restrict__ w,
                                                __nv_bfloat16* __restrict__ dst)
{
    int i = blockIdx.x*256 + threadIdx.x;       // 589824 total
    int c = i & 255, o = (i >> 8) & 255, t = i >> 16;
    dst[i] = __float2bfloat16(w[o*2304 + c*9 + t]);
}

// ---------------- bf16 MMA 1x1-conv GEMM ----------------
__global__ __launch_bounds__(256) void k_proj_tc(const __nv_bfloat16* __restrict__ w,
                                                 const float* __restrict__ bias,
                                                 const __nv_bfloat16* __restrict__ in,
                                                 float* __restrict__ out)
{
    __shared__ __align__(16) __nv_bfloat16 As[2][128][LDA];
    __shared__ __align__(16) __nv_bfloat16 Bs[2][128][LDA];
    const int b  = blockIdx.z;
    const int o0 = blockIdx.y * 128;
    const int n0 = blockIdx.x * 128;
    const __nv_bfloat16* inb = in + (size_t)b*CH*NPIX;
    const int tid = threadIdx.x;
    const int wid = tid >> 5, lane = tid & 31;
    const int wm = wid & 3, wn = wid >> 2;

    float acc[2][8][4];
    #pragma unroll
    for (int i = 0; i < 2; i++) {
        #pragma unroll
        for (int j = 0; j < 8; j++) {
            #pragma unroll
            for (int q = 0; q < 4; q++) acc[i][j][q] = 0.f;
        }
    }

    // prefetch chunk 0
    #pragma unroll
    for (int i = 0; i < 2; i++) {
        int e = tid + i*256;
        int o = e >> 2, cq = e & 3;
        *(uint4*)&As[0][o][cq*8] = *(const uint4*)(w + (size_t)(o0+o)*CH + cq*8);
    }
    #pragma unroll
    for (int i = 0; i < 16; i++) {
        int e = tid + i*256;
        int c = e >> 7, n = e & 127;
        Bs[0][n][c] = inb[(size_t)c*NPIX + n0 + n];
    }

    for (int kc = 0; kc < 8; kc++) {
        __syncthreads();
        int buf = kc & 1;
        if (kc + 1 < 8) {
            int cb = (kc + 1) * 32;
            #pragma unroll
            for (int i = 0; i < 2; i++) {
                int e = tid + i*256;
                int o = e >> 2, cq = e & 3;
                *(uint4*)&As[buf^1][o][cq*8] =
                    *(const uint4*)(w + (size_t)(o0+o)*CH + cb + cq*8);
            }
            #pragma unroll
            for (int i = 0; i < 16; i++) {
                int e = tid + i*256;
                int c = e >> 7, n = e & 127;
                Bs[buf^1][n][c] = inb[(size_t)(cb+c)*NPIX + n0 + n];
            }
        }
        MMA_CHUNK(As[buf], Bs[buf], acc, lane, wm, wn);
    }

    float* ob = out + (size_t)b*CH*NPIX;
    const int r0 = lane >> 2, c2 = (lane & 3)*2;
    #pragma unroll
    for (int mi = 0; mi < 2; mi++) {
        int o_lo = o0 + wm*32 + mi*16 + r0;
        int o_hi = o_lo + 8;
        float blo = bias[o_lo], bhi = bias[o_hi];
        #pragma unroll
        for (int nj = 0; nj < 8; nj++) {
            int n = n0 + wn*64 + nj*8 + c2;
            *(float2*)(ob + (size_t)o_lo*NPIX + n) =
                make_float2(acc[mi][nj][0] + blo, acc[mi][nj][1] + blo);
            *(float2*)(ob + (size_t)o_hi*NPIX + n) =
                make_float2(acc[mi][nj][2] + bhi, acc[mi][nj][3] + bhi);
        }
    }
}

// ---------------- bf16 MMA attn GEMM + epilogue (writes bf16) ----------------
__global__ __launch_bounds__(256) void k_attn_tc(const float* __restrict__ rb)
{
    __shared__ __align__(16) __nv_bfloat16 As[2][128][LDA];
    __shared__ __align__(16) __nv_bfloat16 Bs[2][128][LDA];
    const int b  = blockIdx.z;
    const int o0 = blockIdx.y * 128;
    const int n0 = blockIdx.x * 128;
    const float* Am = g_A + (size_t)b*CH*CH;
    const float* Qb = g_Q + (size_t)b*CH*NPIX;
    const int tid = threadIdx.x;
    const int wid = tid >> 5, lane = tid & 31;
    const int wm = wid & 3, wn = wid >> 2;

    float acc[2][8][4];
    #pragma unroll
    for (int i = 0; i < 2; i++) {
        #pragma unroll
        for (int j = 0; j < 8; j++) {
            #pragma unroll
            for (int q = 0; q < 4; q++) acc[i][j][q] = 0.f;
        }
    }

    #pragma unroll
    for (int i = 0; i < 16; i++) {
        int e = tid + i*256;
        int o = e >> 5, c = e & 31;
        As[0][o][c] = __float2bfloat16(Am[(size_t)(o0+o)*CH + c]);
    }
    #pragma unroll
    for (int i = 0; i < 16; i++) {
        int e = tid + i*256;
        int c = e >> 7, n = e & 127;
        Bs[0][n][c] = __float2bfloat16(Qb[(size_t)c*NPIX + n0 + n]);
    }

    for (int kc = 0; kc < 8; kc++) {
        __syncthreads();
        int buf = kc & 1;
        if (kc + 1 < 8) {
            int cb = (kc + 1) * 32;
            #pragma unroll
            for (int i = 0; i < 16; i++) {
                int e = tid + i*256;
                int o = e >> 5, c = e & 31;
                As[buf^1][o][c] = __float2bfloat16(Am[(size_t)(o0+o)*CH + cb + c]);
            }
            #pragma unroll
            for (int i = 0; i < 16; i++) {
                int e = tid + i*256;
                int c = e >> 7, n = e & 127;
                Bs[buf^1][n][c] = __float2bfloat16(Qb[(size_t)(cb+c)*NPIX + n0 + n]);
            }
        }
        MMA_CHUNK(As[buf], Bs[buf], acc, lane, wm, wn);
    }

    __nv_bfloat16* ob = g_attnbf + (size_t)b*CH*NPIX;
    const int r0 = lane >> 2, c2 = (lane & 3)*2;
    #pragma unroll
    for (int mi = 0; mi < 2; mi++) {
        int o_lo = o0 + wm*32 + mi*16 + r0;
        int o_hi = o_lo + 8;
        float rvlo = g_rv[b*CH + o_lo], rvhi = g_rv[b*CH + o_hi];
        float rblo = rb[o_lo], rbhi = rb[o_hi];
        #pragma unroll
        for (int nj = 0; nj < 8; nj++) {
            int n = n0 + wn*64 + nj*8 + c2;
            float iq0 = g_invQ[b*NPIX + n],     dn0 = g_denom[b*NPIX + n];
            float iq1 = g_invQ[b*NPIX + n + 1], dn1 = g_denom[b*NPIX + n + 1];
            __nv_bfloat162 vlo, vhi;
            vlo.x = __float2bfloat16(fmaf(fmaf(iq0, acc[mi][nj][0], rvlo), dn0, rblo));
            vlo.y = __float2bfloat16(fmaf(fmaf(iq1, acc[mi][nj][1], rvlo), dn1, rblo));
            vhi.x = __float2bfloat16(fmaf(fmaf(iq0, acc[mi][nj][2], rvhi), dn0, rbhi));
            vhi.y = __float2bfloat16(fmaf(fmaf(iq1, acc[mi][nj][3], rvhi), dn1, rbhi));
            *(__nv_bfloat162*)(ob + (size_t)o_lo*NPIX + n) = vlo;
            *(__nv_bfloat162*)(ob + (size_t)o_hi*NPIX + n) = vhi;
        }
    }
}

// ---------------- bf16 MMA 3x3 conv: halo tile + direct-lds B fragments ----------------
// B smem: [16 kw][4 rows][66 cols] uint32 words (2 channels packed). 264-word planes.
__global__ __launch_bounds__(256) void k_conv_tc(const __nv_bfloat16* __restrict__ in,
                                                 const __nv_bfloat16* __restrict__ wt,   // [t][o][c]
                                                 const float* __restrict__ bias,
                                                 const float* __restrict__ xres,
                                                 float* __restrict__ out_f,
                                                 __nv_bfloat16* __restrict__ out_bf,
                                                 int fuse)
{
    __shared__ __align__(16) __nv_bfloat16 As[2][128][LDA];
    __shared__ __align__(16) uint32_t Bw[16*264];
    const int b   = blockIdx.z;
    const int o0  = blockIdx.y * 128;
    const int pr0 = blockIdx.x * 2;
    const __nv_bfloat16* inb = in + (size_t)b*CH*NPIX;
    const int tid = threadIdx.x;
    const int wid = tid >> 5, lane = tid & 31;
    const int wm = wid & 3, wn = wid >> 2;

    float acc[2][8][4];
    #pragma unroll
    for (int i = 0; i < 2; i++) {
        #pragma unroll
        for (int j = 0; j < 8; j++) {
            #pragma unroll
            for (int q = 0; q < 4; q++) acc[i][j][q] = 0.f;
        }
    }

    // A prefill for s=0 (t=0, cb=0)
    #pragma unroll
    for (int i = 0; i < 2; i++) {
        int e = tid + i*256;
        int o = e >> 2, cq = e & 3;
        *(uint4*)&As[0][o][cq*8] = *(const uint4*)(wt + ((size_t)0*256 + o0 + o)*256 + cq*8);
    }

    int s = 0;
    for (int cb = 0; cb < 8; cb++) {
        // ---- fill B halo tile for this channel block (single-buffered) ----
        const int cbase = cb * 32;
        for (int i = tid; i < 16*264; i += 256) {
            int kw = i / 264, p = i - kw*264;
            int row = p / 66, col = p - row*66;
            int gr = pr0 - 1 + row, gc = col - 1;
            uint32_t wv = 0;
            if ((unsigned)gr < IMW && (unsigned)gc < IMW) {
                const __nv_bfloat16* q = inb + (size_t)(cbase + kw*2)*NPIX + gr*IMW + gc;
                uint32_t lo = __bfloat16_as_ushort(q[0]);
                uint32_t hi = __bfloat16_as_ushort(q[NPIX]);
                wv = lo | (hi << 16);
            }
            Bw[i] = wv;
        }
        __syncthreads();
        for (int t = 0; t < 9; t++, s++) {
            const int pa = s & 1;
            // prefetch next A (next tap, or next c-block's tap 0)
            if (s + 1 < 72) {
                int tn = (t + 1 == 9) ? 0 : t + 1;
                int cbn = (t + 1 == 9) ? (cb + 1) : cb;
                const __nv_bfloat16* wsrc = wt + ((size_t)tn*256 + o0)*256 + cbn*32;
                #pragma unroll
                for (int i = 0; i < 2; i++) {
                    int e = tid + i*256;
                    int o = e >> 2, cq = e & 3;
                    *(uint4*)&As[pa^1][o][cq*8] = *(const uint4*)(wsrc + (size_t)o*256 + cq*8);
                }
            }
            // ---- compute tap t on channel block cb ----
            {
                const int dy = t / 3 - 1, dx = t % 3 - 1;
                const int rowoff = (1 + wn + dy) * 66 + 1 + dx;
                #pragma unroll
                for (int ks = 0; ks < 2; ks++) {
                    uint32_t a0[4], a1[4];
                    ldsm_x4(a0, smem_u32(&As[pa][wm*32 + (lane&15)][ks*16 + (lane>>4)*8]));
                    ldsm_x4(a1, smem_u32(&As[pa][wm*32 + 16 + (lane&15)][ks*16 + (lane>>4)*8]));
                    const uint32_t* bp = &Bw[(ks*8 + (lane&3))*264 + rowoff + (lane>>2)];
                    #pragma unroll
                    for (int f = 0; f < 8; f++) {
                        uint32_t b0 = bp[f*8];
                        uint32_t b1 = bp[f*8 + 4*264];
                        mma16816(acc[0][f], a0, b0, b1);
                        mma16816(acc[1][f], a1, b0, b1);
                    }
                }
            }
            __syncthreads();
        }
    }

    // ---- epilogue ----
    const int r0 = lane >> 2, c2 = (lane & 3)*2;
    const int pxbase = pr0*64;
    if (fuse) {
        const float* xb = xres + (size_t)b*CH*NPIX;
        float* ob = out_f + (size_t)b*CH*NPIX;
        #pragma unroll
        for (int mi = 0; mi < 2; mi++) {
            int o_lo = o0 + wm*32 + mi*16 + r0;
            int o_hi = o_lo + 8;
            float blo = bias[o_lo], bhi = bias[o_hi];
            #pragma unroll
            for (int f = 0; f < 8; f++) {
                int px = pxbase + wn*64 + f*8 + c2;
                float v0 = acc[0+mi*0][f][0]; // placeholder (never used)
                (void)v0;
                float a0 = acc[mi][f][0] + blo, a1 = acc[mi][f][1] + blo;
                float a2 = acc[mi][f][2] + bhi, a3 = acc[mi][f][3] + bhi;
                float2 xlo = *(const float2*)(xb + (size_t)o_lo*NPIX + px);
                float2 xhi = *(const float2*)(xb + (size_t)o_hi*NPIX + px);
                a0 = fmaf(a0, xlo.x, xlo.x);
                a1 = fmaf(a1, xlo.y, xlo.y);
                a2 = fmaf(a2, xhi.x, xhi.x);
                a3 = fmaf(a3, xhi.y, xhi.y);
                *(float2*)(ob + (size_t)o_lo*NPIX + px) = make_float2(a0, a1);
                *(float2*)(ob + (size_t)o_hi*NPIX + px) = make_float2(a2, a3);
            }
        }
    } else {
        __nv_bfloat16* ob = out_bf + (size_t)b*CH*NPIX;
        #pragma unroll
        for (int mi = 0; mi < 2; mi++) {
            int o_lo = o0 + wm*32 + mi*16 + r0;
            int o_hi = o_lo + 8;
            float blo = bias[o_lo], bhi = bias[o_hi];
            #pragma unroll
            for (int f = 0; f < 8; f++) {
                int px = pxbase + wn*64 + f*8 + c2;
                __nv_bfloat162 vlo, vhi;
                vlo.x = __float2bfloat16(acc[mi][f][0] + blo);
                vlo.y = __float2bfloat16(acc[mi][f][1] + blo);
                vhi.x = __float2bfloat16(acc[mi][f][2] + bhi);
                vhi.y = __float2bfloat16(acc[mi][f][3] + bhi);
                *(__nv_bfloat162*)(ob + (size_t)o_lo*NPIX + px) = vlo;
                *(__nv_bfloat162*)(ob + (size_t)o_hi*NPIX + px) = vhi;
            }
        }
    }
}

// ---------------- per-token inverse norms of Q and K ----------------
__global__ __launch_bounds__(256) void k_norms()
{
    int idx = blockIdx.x*256 + threadIdx.x;
    int b = idx >> 12, n = idx & 4095;
    const float* Qp = g_Q + (size_t)b*CH*NPIX + n;
    const float* Kp = g_K + (size_t)b*CH*NPIX + n;
    float sq = 0.f, sk = 0.f;
    #pragma unroll 8
    for (int c = 0; c < CH; c++) {
        float q = Qp[(size_t)c*NPIX]; sq = fmaf(q, q, sq);
        float k = Kp[(size_t)c*NPIX]; sk = fmaf(k, k, sk);
    }
    g_invQ[idx] = 1.0f / sqrtf(sq);
    g_invK[idx] = 1.0f / sqrtf(sk);
}

// ---------------- ksum / vsum ----------------
__global__ __launch_bounds__(256) void k_colsums()
{
    int bc = blockIdx.x;
    int b = bc >> 8;
    const float* Kp = g_K + (size_t)bc*NPIX;
    const float* Vp = g_V + (size_t)bc*NPIX;
    const float* ik = g_invK + (size_t)b*NPIX;
    int tid = threadIdx.x;
    float sk = 0.f, sv = 0.f;
    for (int n = tid; n < NPIX; n += 256) {
        sk = fmaf(Kp[n], ik[n], sk);
        sv += Vp[n];
    }
    __shared__ float rk[256], rv[256];
    rk[tid] = sk; rv[tid] = sv;
    __syncthreads();
    for (int s = 128; s > 0; s >>= 1) {
        if (tid < s) { rk[tid] += rk[tid+s]; rv[tid] += rv[tid+s]; }
        __syncthreads();
    }
    if (tid == 0) { g_ksum[bc] = rk[0]; g_vsum[bc] = rv[0]; }
}

// ---------------- generic NT GEMM (fp32, small) ----------------
__global__ __launch_bounds__(256) void k_nt(const float* __restrict__ Ap, long strideA,
                                            const float* __restrict__ Bp, long strideB,
                                            const float* __restrict__ scale, long strideS,
                                            int L, float* __restrict__ out)
{
    __shared__ float As[32][65];
    __shared__ float Bs[32][65];
    const int b = blockIdx.z;
    const int i0 = blockIdx.y*64, j0 = blockIdx.x*64;
    const float* A = Ap + (size_t)b*strideA;
    const float* B = Bp + (size_t)b*strideB;
    const float* sc = scale ? scale + (size_t)b*strideS : (const float*)0;
    const int tid = threadIdx.x;
    const int ty = tid >> 4, tx = tid & 15;
    float acc[4][4];
    #pragma unroll
    for (int i = 0; i < 4; i++) {
        #pragma unroll
        for (int j = 0; j < 4; j++) acc[i][j] = 0.f;
    }

    for (int l0 = 0; l0 < L; l0 += 32) {
        #pragma unroll
        for (int r = 0; r < 8; r++) {
            int e = tid + r*256;
            int ii = e >> 5, ll = e & 31;
            float v = A[(size_t)(i0+ii)*L + l0 + ll];
            if (sc) v *= sc[l0 + ll];
            As[ll][ii] = v;
        }
        #pragma unroll
        for (int r = 0; r < 8; r++) {
            int e = tid + r*256;
            int jj = e >> 5, ll = e & 31;
            Bs[ll][jj] = B[(size_t)(j0+jj)*L + l0 + ll];
        }
        __syncthreads();
        #pragma unroll
        for (int ll = 0; ll < 32; ll++) {
            float ar[4], br[4];
            #pragma unroll
            for (int i = 0; i < 4; i++) ar[i] = As[ll][ty*4+i];
            #pragma unroll
            for (int j = 0; j < 4; j++) br[j] = Bs[ll][tx*4+j];
            #pragma unroll
            for (int i = 0; i < 4; i++) {
                #pragma unroll
                for (int j = 0; j < 4; j++)
                    acc[i][j] = fmaf(ar[i], br[j], acc[i][j]);
            }
        }
        __syncthreads();
    }
    float* ob = out + (size_t)b*CH*CH;
    #pragma unroll
    for (int i = 0; i < 4; i++) {
        #pragma unroll
        for (int j = 0; j < 4; j++)
            ob[(size_t)(i0+ty*4+i)*CH + j0 + tx*4 + j] = acc[i][j];
    }
}

// ---------------- rv[b,o] = rw @ vsum ----------------
__global__ __launch_bounds__(256) void k_rv(const float* __restrict__ rw)
{
    int b = blockIdx.x, o = threadIdx.x;
    __shared__ float vs[256];
    vs[o] = g_vsum[b*CH + o];
    __syncthreads();
    float s = 0.f;
    const float* rp = rw + (size_t)o*CH;
    #pragma unroll 8
    for (int c = 0; c < CH; c++) s = fmaf(rp[c], vs[c], s);
    g_rv[b*CH + o] = s;
}

// ---------------- denom ----------------
__global__ __launch_bounds__(256) void k_denom()
{
    int idx = blockIdx.x*256 + threadIdx.x;
    int b = idx >> 12, n = idx & 4095;
    __shared__ float ks[256];
    ks[threadIdx.x] = g_ksum[b*CH + threadIdx.x];
    __syncthreads();
    const float* Qp = g_Q + (size_t)b*CH*NPIX + n;
    float s = 0.f;
    #pragma unroll 8
    for (int c = 0; c < CH; c++) s = fmaf(Qp[(size_t)c*NPIX], ks[c], s);
    float agg = s * g_invQ[idx];
    g_denom[idx] = 1.0f / (4096.0f + agg + 1e-6f);
}

// ---------------- launcher ----------------
extern "C" void kernel_launch(void* const* d_in, const int* in_sizes, int n_in,
                              void* d_out, int out_size)
{
    (void)in_sizes; (void)n_in; (void)out_size;
    const float* x   = (const float*)d_in[0];
    const float* qw  = (const float*)d_in[1];
    const float* qb  = (const float*)d_in[2];
    const float* kw  = (const float*)d_in[3];
    const float* kb  = (const float*)d_in[4];
    const float* vw  = (const float*)d_in[5];
    const float* vb  = (const float*)d_in[6];
    const float* rw  = (const float*)d_in[7];
    const float* rb  = (const float*)d_in[8];
    const float* c1w = (const float*)d_in[9];
    const float* c1b = (const float*)d_in[10];
    const float* c2w = (const float*)d_in[11];
    const float* c2b = (const float*)d_in[12];
    float* out = (float*)d_out;

    float *pQ, *pK, *pV, *pkv, *pinvK, *pA;
    __nv_bfloat16 *pxbf, *pattnbf, *ph1bf, *pwq, *pwk, *pwv, *pwc1, *pwc2;
    cudaGetSymbolAddress((void**)&pQ,    g_Q);
    cudaGetSymbolAddress((void**)&pK,    g_K);
    cudaGetSymbolAddress((void**)&pV,    g_V);
    cudaGetSymbolAddress((void**)&pkv,   g_kv);
    cudaGetSymbolAddress((void**)&pA,    g_A);
    cudaGetSymbolAddress((void**)&pinvK, g_invK);
    cudaGetSymbolAddress((void**)&pxbf,   g_xbf);
    cudaGetSymbolAddress((void**)&pattnbf,g_attnbf);
    cudaGetSymbolAddress((void**)&ph1bf,  g_h1bf);
    cudaGetSymbolAddress((void**)&pwq,    g_wqb);
    cudaGetSymbolAddress((void**)&pwk,    g_wkb);
    cudaGetSymbolAddress((void**)&pwv,    g_wvb);
    cudaGetSymbolAddress((void**)&pwc1,   g_wc1b);
    cudaGetSymbolAddress((void**)&pwc2,   g_wc2b);

    dim3 gproj(32, 2, BSZ);
    dim3 gnt(4, 4, BSZ);
    dim3 gconv(32, 2, BSZ);

    // conversions
    k_cvt<<<(BSZ*CH*NPIX)/1024, 256>>>(x, pxbf);
    k_cvt<<<(CH*CH)/1024, 256>>>(qw, pwq);
    k_cvt<<<(CH*CH)/1024, 256>>>(kw, pwk);
    k_cvt<<<(CH*CH)/1024, 256>>>(vw, pwv);
    k_cvt_wc<<<(9*CH*CH)/256, 256>>>(c1w, pwc1);
    k_cvt_wc<<<(9*CH*CH)/256, 256>>>(c2w, pwc2);

    k_proj_tc<<<gproj, 256>>>(pwq, qb, pxbf, pQ);
    k_proj_tc<<<gproj, 256>>>(pwk, kb, pxbf, pK);
    k_proj_tc<<<gproj, 256>>>(pwv, vb, pxbf, pV);
    k_norms<<<(BSZ*NPIX)/256, 256>>>();
    k_colsums<<<BSZ*CH, 256>>>();
    k_nt<<<gnt, 256>>>(pK, (long)CH*NPIX, pV, (long)CH*NPIX, pinvK, (long)NPIX, NPIX, pkv);
    k_nt<<<gnt, 256>>>(rw, 0L, pkv, (long)CH*CH, (const float*)0, 0L, CH, pA);
    k_rv<<<BSZ, 256>>>(rw);
    k_denom<<<(BSZ*NPIX)/256, 256>>>();
    k_attn_tc<<<gproj, 256>>>(rb);
    k_conv_tc<<<gconv, 256>>>(pattnbf, pwc1, c1b, (const float*)0, (float*)0, ph1bf, 0);
    k_conv_tc<<<gconv, 256>>>(ph1bf, pwc2, c2b, x, out, (__nv_bfloat16*)0, 1);
}

// round 6
// speedup vs baseline: 5.2140x; 1.3372x over previous
#include <cuda_runtime.h>
#include <cuda_bf16.h>
#include <math.h>
#include <cstdint>

#define BSZ  8
#define CH   256
#define NPIX 4096
#define IMW  64
#define LDA  40   // bf16 elems per smem row (80B, conflict-free ldmatrix)
#define LDB3 264  // proj3 shared-B row width (528B rows, conflict-free)

// ---------------- scratch (device globals; alloc-free) ----------------
__device__ float g_Q[BSZ*CH*NPIX];
__device__ float g_K[BSZ*CH*NPIX];
__device__ float g_invQ[BSZ*NPIX];
__device__ float g_invK[BSZ*NPIX];
__device__ float g_ksum[BSZ*CH];
__device__ float g_vsum[BSZ*CH];
__device__ float g_kv[BSZ*CH*CH];
__device__ float g_kvp[BSZ*4*CH*CH];      // split-N partials
__device__ float g_A[BSZ*CH*CH];
__device__ float g_rv[BSZ*CH];
__device__ float g_denom[BSZ*NPIX];
// bf16 operands
__device__ __nv_bfloat16 g_xbf[BSZ*CH*NPIX];
__device__ __nv_bfloat16 g_Vbf[BSZ*CH*NPIX];
__device__ __nv_bfloat16 g_Knbf[BSZ*CH*NPIX];
__device__ __nv_bfloat16 g_attnbf[BSZ*CH*NPIX];
__device__ __nv_bfloat16 g_h1bf[BSZ*CH*NPIX];
__device__ __nv_bfloat16 g_wqkv[3*CH*CH];   // [which][o][c]
__device__ __nv_bfloat16 g_wc1b[9*CH*CH];   // [t][o][c]
__device__ __nv_bfloat16 g_wc2b[9*CH*CH];

// ================= warp-MMA helpers =================
__device__ __forceinline__ uint32_t smem_u32(const void* p) {
    uint32_t a;
    asm("{ .reg .u64 t; cvta.to.shared.u64 t, %1; cvt.u32.u64 %0, t; }" : "=r"(a) : "l"(p));
    return a;
}
__device__ __forceinline__ void ldsm_x4(uint32_t (&r)[4], uint32_t addr) {
    asm volatile("ldmatrix.sync.aligned.m8n8.x4.shared.b16 {%0,%1,%2,%3}, [%4];"
        : "=r"(r[0]), "=r"(r[1]), "=r"(r[2]), "=r"(r[3]) : "r"(addr));
}
__device__ __forceinline__ void mma16816(float (&d)[4], const uint32_t (&a)[4],
                                         uint32_t b0, uint32_t b1) {
    asm volatile("mma.sync.aligned.m16n8k16.row.col.f32.bf16.bf16.f32 "
        "{%0,%1,%2,%3}, {%4,%5,%6,%7}, {%8,%9}, {%0,%1,%2,%3};"
        : "+f"(d[0]), "+f"(d[1]), "+f"(d[2]), "+f"(d[3])
        : "r"(a[0]), "r"(a[1]), "r"(a[2]), "r"(a[3]), "r"(b0), "r"(b1));
}

// Generic MMA chunk: As rows=M, Bs rows=N, both [..][rowW], contraction cols at coff.
#define MMA_CHUNK_G(As, AW, Bs, BW, coff, acc, lane, wm, wn) do {                   \
    _Pragma("unroll")                                                               \
    for (int ks = 0; ks < 2; ks++) {                                                \
        uint32_t a_[2][4];                                                          \
        _Pragma("unroll")                                                           \
        for (int mi = 0; mi < 2; mi++)                                              \
            ldsm_x4(a_[mi], smem_u32(&(As)[((wm)*32 + mi*16 + ((lane)&15))*(AW)     \
                                          + ks*16 + ((lane)>>4)*8]));               \
        uint32_t b_[4][4];                                                          \
        _Pragma("unroll")                                                           \
        for (int ni = 0; ni < 4; ni++)                                              \
            ldsm_x4(b_[ni], smem_u32(&(Bs)[((wn)*64 + ni*16 + (((lane)>>4)&1)*8     \
                                            + ((lane)&7))*(BW)                      \
                                           + (coff) + ks*16 + (((lane)>>3)&1)*8])); \
        _Pragma("unroll")                                                           \
        for (int mi = 0; mi < 2; mi++) {                                            \
            _Pragma("unroll")                                                       \
            for (int ni = 0; ni < 4; ni++) {                                        \
                mma16816(acc[mi][ni*2],   a_[mi], b_[ni][0], b_[ni][1]);            \
                mma16816(acc[mi][ni*2+1], a_[mi], b_[ni][2], b_[ni][3]);            \
            }                                                                       \
        }                                                                           \
    }                                                                               \
} while (0)

#define ACC_ZERO(acc) do {                                                          \
    _Pragma("unroll")                                                               \
    for (int i_ = 0; i_ < 2; i_++) {                                                \
        _Pragma("unroll")                                                           \
        for (int j_ = 0; j_ < 8; j_++) {                                            \
            _Pragma("unroll")                                                       \
            for (int q_ = 0; q_ < 4; q_++) acc[i_][j_][q_] = 0.f;                   \
        }                                                                           \
    }                                                                               \
} while (0)

// ---------------- conversion kernels ----------------
__global__ __launch_bounds__(256) void k_cvt(const float* __restrict__ src,
                                             __nv_bfloat16* __restrict__ dst)
{
    int i = (blockIdx.x*256 + threadIdx.x) * 4;
    float4 v = *(const float4*)(src + i);
    dst[i+0] = __float2bfloat16(v.x);
    dst[i+1] = __float2bfloat16(v.y);
    dst[i+2] = __float2bfloat16(v.z);
    dst[i+3] = __float2bfloat16(v.w);
}
__global__ __launch_bounds__(256) void k_cvtw(const float* __restrict__ q,
                                              const float* __restrict__ k,
                                              const float* __restrict__ v,
                                              __nv_bfloat16* __restrict__ dst)
{
    int i = blockIdx.x*256 + threadIdx.x;       // 3*65536
    int which = i >> 16, r = i & 65535;
    const float* s = (which == 0) ? q : (which == 1) ? k : v;
    dst[i] = __float2bfloat16(s[r]);
}
__global__ __launch_bounds__(256) void k_cvt_wc(const float* __restrict__ w,
                                                __nv_bfloat16* __restrict__ dst)
{
    int i = blockIdx.x*256 + threadIdx.x;       // 589824 total
    int c = i & 255, o = (i >> 8) & 255, t = i >> 16;
    dst[i] = __float2bfloat16(w[o*2304 + c*9 + t]);
}

// ---------------- fused QKV projection: one shared B tile, 3 weight streams ----------
// dyn smem: Bs [128][LDB3] bf16 (67584B) then As [2][128][LDA] bf16 (20480B)
#define P3_BS_BYTES (128*LDB3*2)
#define P3_SMEM     (P3_BS_BYTES + 2*128*LDA*2)
__global__ __launch_bounds__(256) void k_proj3(const __nv_bfloat16* __restrict__ w3,
                                               const float* __restrict__ qb,
                                               const float* __restrict__ kb,
                                               const float* __restrict__ vb,
                                               float* __restrict__ outQ,
                                               float* __restrict__ outK,
                                               __nv_bfloat16* __restrict__ outV)
{
    extern __shared__ __align__(16) char dsm[];
    __nv_bfloat16* Bs = (__nv_bfloat16*)dsm;                 // [128][LDB3]
    __nv_bfloat16* As = (__nv_bfloat16*)(dsm + P3_BS_BYTES); // [2][128][LDA]
    const int b  = blockIdx.z;
    const int o0 = blockIdx.y * 128;
    const int n0 = blockIdx.x * 128;
    const __nv_bfloat16* inb = g_xbf + (size_t)b*CH*NPIX;
    const int tid = threadIdx.x;
    const int wid = tid >> 5, lane = tid & 31;
    const int wm = wid & 3, wn = wid >> 2;

    // fill shared B tile once: Bs[n][c] for all 256 c
    #pragma unroll
    for (int i = 0; i < 16; i++) {
        int e = tid + i*256;                 // 4096 vector slots
        int c = e >> 4, n8 = (e & 15) * 8;
        uint4 v = *(const uint4*)(inb + (size_t)c*NPIX + n0 + n8);
        const __nv_bfloat16* pv = (const __nv_bfloat16*)&v;
        #pragma unroll
        for (int j = 0; j < 8; j++) Bs[(n8+j)*LDB3 + c] = pv[j];
    }

    float acc[2][8][4];
    const int r0 = lane >> 2, c2 = (lane & 3)*2;

    #pragma unroll
    for (int which = 0; which < 3; which++) {
        const __nv_bfloat16* w = w3 + (size_t)which*CH*CH;
        ACC_ZERO(acc);
        // prefetch A chunk 0
        #pragma unroll
        for (int i = 0; i < 2; i++) {
            int e = tid + i*256;
            int o = e >> 2, cq = e & 3;
            *(uint4*)&As[(0*128 + o)*LDA + cq*8] = *(const uint4*)(w + (size_t)(o0+o)*CH + cq*8);
        }
        for (int kc = 0; kc < 8; kc++) {
            __syncthreads();
            int buf = kc & 1;
            if (kc + 1 < 8) {
                int cb = (kc + 1) * 32;
                #pragma unroll
                for (int i = 0; i < 2; i++) {
                    int e = tid + i*256;
                    int o = e >> 2, cq = e & 3;
                    *(uint4*)&As[((buf^1)*128 + o)*LDA + cq*8] =
                        *(const uint4*)(w + (size_t)(o0+o)*CH + cb + cq*8);
                }
            }
            MMA_CHUNK_G((As + buf*128*LDA), LDA, Bs, LDB3, kc*32, acc, lane, wm, wn);
        }
        // epilogue
        if (which < 2) {
            const float* bias = (which == 0) ? qb : kb;
            float* ob = ((which == 0) ? outQ : outK) + (size_t)b*CH*NPIX;
            #pragma unroll
            for (int mi = 0; mi < 2; mi++) {
                int o_lo = o0 + wm*32 + mi*16 + r0;
                int o_hi = o_lo + 8;
                float blo = bias[o_lo], bhi = bias[o_hi];
                #pragma unroll
                for (int nj = 0; nj < 8; nj++) {
                    int n = n0 + wn*64 + nj*8 + c2;
                    *(float2*)(ob + (size_t)o_lo*NPIX + n) =
                        make_float2(acc[mi][nj][0] + blo, acc[mi][nj][1] + blo);
                    *(float2*)(ob + (size_t)o_hi*NPIX + n) =
                        make_float2(acc[mi][nj][2] + bhi, acc[mi][nj][3] + bhi);
                }
            }
        } else {
            __nv_bfloat16* ob = outV + (size_t)b*CH*NPIX;
            #pragma unroll
            for (int mi = 0; mi < 2; mi++) {
                int o_lo = o0 + wm*32 + mi*16 + r0;
                int o_hi = o_lo + 8;
                float blo = vb[o_lo], bhi = vb[o_hi];
                #pragma unroll
                for (int nj = 0; nj < 8; nj++) {
                    int n = n0 + wn*64 + nj*8 + c2;
                    __nv_bfloat162 vlo, vhi;
                    vlo.x = __float2bfloat16(acc[mi][nj][0] + blo);
                    vlo.y = __float2bfloat16(acc[mi][nj][1] + blo);
                    vhi.x = __float2bfloat16(acc[mi][nj][2] + bhi);
                    vhi.y = __float2bfloat16(acc[mi][nj][3] + bhi);
                    *(__nv_bfloat162*)(ob + (size_t)o_lo*NPIX + n) = vlo;
                    *(__nv_bfloat162*)(ob + (size_t)o_hi*NPIX + n) = vhi;
                }
            }
        }
    }
}

// ---------------- bf16 MMA kv GEMM, split-N=4: kvp[b,sp][k,c] = sum_n Kn*V ----------
__global__ __launch_bounds__(256) void k_kv_tc()
{
    __shared__ __align__(16) __nv_bfloat16 As[2][128][LDA];
    __shared__ __align__(16) __nv_bfloat16 Bs[2][128][LDA];
    const int bsp = blockIdx.z;                  // b*4 + sp
    const int b = bsp >> 2, sp = bsp & 3;
    const int k0 = blockIdx.y * 128;
    const int c0 = blockIdx.x * 128;
    const int nb = sp * 1024;
    const __nv_bfloat16* Kn = g_Knbf + (size_t)b*CH*NPIX;
    const __nv_bfloat16* Vb = g_Vbf  + (size_t)b*CH*NPIX;
    const int tid = threadIdx.x;
    const int wid = tid >> 5, lane = tid & 31;
    const int wm = wid & 3, wn = wid >> 2;

    float acc[2][8][4];
    ACC_ZERO(acc);

    #pragma unroll
    for (int i = 0; i < 16; i++) {
        int e = tid + i*256;
        int r = e >> 5, n = e & 31;
        As[0][r][n] = Kn[(size_t)(k0+r)*NPIX + nb + n];
        Bs[0][r][n] = Vb[(size_t)(c0+r)*NPIX + nb + n];
    }

    for (int kc = 0; kc < 32; kc++) {
        __syncthreads();
        int buf = kc & 1;
        if (kc + 1 < 32) {
            int nn = nb + (kc + 1) * 32;
            #pragma unroll
            for (int i = 0; i < 16; i++) {
                int e = tid + i*256;
                int r = e >> 5, n = e & 31;
                As[buf^1][r][n] = Kn[(size_t)(k0+r)*NPIX + nn + n];
                Bs[buf^1][r][n] = Vb[(size_t)(c0+r)*NPIX + nn + n];
            }
        }
        MMA_CHUNK_G(&As[buf][0][0], LDA, &Bs[buf][0][0], LDA, 0, acc, lane, wm, wn);
    }

    float* ob = g_kvp + (size_t)bsp*CH*CH;
    const int r0 = lane >> 2, c2 = (lane & 3)*2;
    #pragma unroll
    for (int mi = 0; mi < 2; mi++) {
        int k_lo = k0 + wm*32 + mi*16 + r0;
        int k_hi = k_lo + 8;
        #pragma unroll
        for (int nj = 0; nj < 8; nj++) {
            int c = c0 + wn*64 + nj*8 + c2;
            *(float2*)(ob + (size_t)k_lo*CH + c) = make_float2(acc[mi][nj][0], acc[mi][nj][1]);
            *(float2*)(ob + (size_t)k_hi*CH + c) = make_float2(acc[mi][nj][2], acc[mi][nj][3]);
        }
    }
}

__global__ __launch_bounds__(256) void k_kvred()
{
    int i = blockIdx.x*256 + threadIdx.x;        // 8*65536
    int b = i >> 16, r = i & 65535;
    const float* p = g_kvp + (size_t)b*4*65536;
    g_kv[i] = (p[r] + p[65536 + r]) + (p[2*65536 + r] + p[3*65536 + r]);
}

// ---------------- bf16 MMA attn GEMM + epilogue (writes bf16) ----------------
__global__ __launch_bounds__(256) void k_attn_tc(const float* __restrict__ rb)
{
    __shared__ __align__(16) __nv_bfloat16 As[2][128][LDA];
    __shared__ __align__(16) __nv_bfloat16 Bs[2][128][LDA];
    const int b  = blockIdx.z;
    const int o0 = blockIdx.y * 128;
    const int n0 = blockIdx.x * 128;
    const float* Am = g_A + (size_t)b*CH*CH;
    const float* Qb = g_Q + (size_t)b*CH*NPIX;
    const int tid = threadIdx.x;
    const int wid = tid >> 5, lane = tid & 31;
    const int wm = wid & 3, wn = wid >> 2;

    float acc[2][8][4];
    ACC_ZERO(acc);

    #pragma unroll
    for (int i = 0; i < 16; i++) {
        int e = tid + i*256;
        int o = e >> 5, c = e & 31;
        As[0][o][c] = __float2bfloat16(Am[(size_t)(o0+o)*CH + c]);
    }
    #pragma unroll
    for (int i = 0; i < 16; i++) {
        int e = tid + i*256;
        int c = e >> 7, n = e & 127;
        Bs[0][n][c] = __float2bfloat16(Qb[(size_t)c*NPIX + n0 + n]);
    }

    for (int kc = 0; kc < 8; kc++) {
        __syncthreads();
        int buf = kc & 1;
        if (kc + 1 < 8) {
            int cb = (kc + 1) * 32;
            #pragma unroll
            for (int i = 0; i < 16; i++) {
                int e = tid + i*256;
                int o = e >> 5, c = e & 31;
                As[buf^1][o][c] = __float2bfloat16(Am[(size_t)(o0+o)*CH + cb + c]);
            }
            #pragma unroll
            for (int i = 0; i < 16; i++) {
                int e = tid + i*256;
                int c = e >> 7, n = e & 127;
                Bs[buf^1][n][c] = __float2bfloat16(Qb[(size_t)(cb+c)*NPIX + n0 + n]);
            }
        }
        MMA_CHUNK_G(&As[buf][0][0], LDA, &Bs[buf][0][0], LDA, 0, acc, lane, wm, wn);
    }

    __nv_bfloat16* ob = g_attnbf + (size_t)b*CH*NPIX;
    const int r0 = lane >> 2, c2 = (lane & 3)*2;
    #pragma unroll
    for (int mi = 0; mi < 2; mi++) {
        int o_lo = o0 + wm*32 + mi*16 + r0;
        int o_hi = o_lo + 8;
        float rvlo = g_rv[b*CH + o_lo], rvhi = g_rv[b*CH + o_hi];
        float rblo = rb[o_lo], rbhi = rb[o_hi];
        #pragma unroll
        for (int nj = 0; nj < 8; nj++) {
            int n = n0 + wn*64 + nj*8 + c2;
            float iq0 = g_invQ[b*NPIX + n],     dn0 = g_denom[b*NPIX + n];
            float iq1 = g_invQ[b*NPIX + n + 1], dn1 = g_denom[b*NPIX + n + 1];
            __nv_bfloat162 vlo, vhi;
            vlo.x = __float2bfloat16(fmaf(fmaf(iq0, acc[mi][nj][0], rvlo), dn0, rblo));
            vlo.y = __float2bfloat16(fmaf(fmaf(iq1, acc[mi][nj][1], rvlo), dn1, rblo));
            vhi.x = __float2bfloat16(fmaf(fmaf(iq0, acc[mi][nj][2], rvhi), dn0, rbhi));
            vhi.y = __float2bfloat16(fmaf(fmaf(iq1, acc[mi][nj][3], rvhi), dn1, rbhi));
            *(__nv_bfloat162*)(ob + (size_t)o_lo*NPIX + n) = vlo;
            *(__nv_bfloat162*)(ob + (size_t)o_hi*NPIX + n) = vhi;
        }
    }
}

// ---------------- bf16 MMA 3x3 conv: halo tile + direct-lds B fragments ----------------
__global__ __launch_bounds__(256) void k_conv_tc(const __nv_bfloat16* __restrict__ in,
                                                 const __nv_bfloat16* __restrict__ wt,   // [t][o][c]
                                                 const float* __restrict__ bias,
                                                 const float* __restrict__ xres,
                                                 float* __restrict__ out_f,
                                                 __nv_bfloat16* __restrict__ out_bf,
                                                 int fuse)
{
    __shared__ __align__(16) __nv_bfloat16 As[2][128][LDA];
    __shared__ __align__(16) uint32_t Bw[16*264];
    const int b   = blockIdx.z;
    const int o0  = blockIdx.y * 128;
    const int pr0 = blockIdx.x * 2;
    const __nv_bfloat16* inb = in + (size_t)b*CH*NPIX;
    const int tid = threadIdx.x;
    const int wid = tid >> 5, lane = tid & 31;
    const int wm = wid & 3, wn = wid >> 2;

    float acc[2][8][4];
    ACC_ZERO(acc);

    // A prefill for s=0 (t=0, cb=0)
    #pragma unroll
    for (int i = 0; i < 2; i++) {
        int e = tid + i*256;
        int o = e >> 2, cq = e & 3;
        *(uint4*)&As[0][o][cq*8] = *(const uint4*)(wt + ((size_t)o0 + o)*256 + cq*8);
    }

    int s = 0;
    for (int cb = 0; cb < 8; cb++) {
        const int cbase = cb * 32;
        for (int i = tid; i < 16*264; i += 256) {
            int kw = i / 264, p = i - kw*264;
            int row = p / 66, col = p - row*66;
            int gr = pr0 - 1 + row, gc = col - 1;
            uint32_t wv = 0;
            if ((unsigned)gr < IMW && (unsigned)gc < IMW) {
                const __nv_bfloat16* q = inb + (size_t)(cbase + kw*2)*NPIX + gr*IMW + gc;
                uint32_t lo = __bfloat16_as_ushort(q[0]);
                uint32_t hi = __bfloat16_as_ushort(q[NPIX]);
                wv = lo | (hi << 16);
            }
            Bw[i] = wv;
        }
        __syncthreads();
        for (int t = 0; t < 9; t++, s++) {
            const int pa = s & 1;
            if (s + 1 < 72) {
                int tn = (t + 1 == 9) ? 0 : t + 1;
                int cbn = (t + 1 == 9) ? (cb + 1) : cb;
                const __nv_bfloat16* wsrc = wt + ((size_t)tn*256 + o0)*256 + cbn*32;
                #pragma unroll
                for (int i = 0; i < 2; i++) {
                    int e = tid + i*256;
                    int o = e >> 2, cq = e & 3;
                    *(uint4*)&As[pa^1][o][cq*8] = *(const uint4*)(wsrc + (size_t)o*256 + cq*8);
                }
            }
            {
                const int dy = t / 3 - 1, dx = t % 3 - 1;
                const int rowoff = (1 + wn + dy) * 66 + 1 + dx;
                #pragma unroll
                for (int ks = 0; ks < 2; ks++) {
                    uint32_t a0[4], a1[4];
                    ldsm_x4(a0, smem_u32(&As[pa][wm*32 + (lane&15)][ks*16 + (lane>>4)*8]));
                    ldsm_x4(a1, smem_u32(&As[pa][wm*32 + 16 + (lane&15)][ks*16 + (lane>>4)*8]));
                    const uint32_t* bp = &Bw[(ks*8 + (lane&3))*264 + rowoff + (lane>>2)];
                    #pragma unroll
                    for (int f = 0; f < 8; f++) {
                        uint32_t b0 = bp[f*8];
                        uint32_t b1 = bp[f*8 + 4*264];
                        mma16816(acc[0][f], a0, b0, b1);
                        mma16816(acc[1][f], a1, b0, b1);
                    }
                }
            }
            __syncthreads();
        }
    }

    const int r0 = lane >> 2, c2 = (lane & 3)*2;
    const int pxbase = pr0*64;
    if (fuse) {
        const float* xb = xres + (size_t)b*CH*NPIX;
        float* ob = out_f + (size_t)b*CH*NPIX;
        #pragma unroll
        for (int mi = 0; mi < 2; mi++) {
            int o_lo = o0 + wm*32 + mi*16 + r0;
            int o_hi = o_lo + 8;
            float blo = bias[o_lo], bhi = bias[o_hi];
            #pragma unroll
            for (int f = 0; f < 8; f++) {
                int px = pxbase + wn*64 + f*8 + c2;
                float a0 = acc[mi][f][0] + blo, a1 = acc[mi][f][1] + blo;
                float a2 = acc[mi][f][2] + bhi, a3 = acc[mi][f][3] + bhi;
                float2 xlo = *(const float2*)(xb + (size_t)o_lo*NPIX + px);
                float2 xhi = *(const float2*)(xb + (size_t)o_hi*NPIX + px);
                a0 = fmaf(a0, xlo.x, xlo.x);
                a1 = fmaf(a1, xlo.y, xlo.y);
                a2 = fmaf(a2, xhi.x, xhi.x);
                a3 = fmaf(a3, xhi.y, xhi.y);
                *(float2*)(ob + (size_t)o_lo*NPIX + px) = make_float2(a0, a1);
                *(float2*)(ob + (size_t)o_hi*NPIX + px) = make_float2(a2, a3);
            }
        }
    } else {
        __nv_bfloat16* ob = out_bf + (size_t)b*CH*NPIX;
        #pragma unroll
        for (int mi = 0; mi < 2; mi++) {
            int o_lo = o0 + wm*32 + mi*16 + r0;
            int o_hi = o_lo + 8;
            float blo = bias[o_lo], bhi = bias[o_hi];
            #pragma unroll
            for (int f = 0; f < 8; f++) {
                int px = pxbase + wn*64 + f*8 + c2;
                __nv_bfloat162 vlo, vhi;
                vlo.x = __float2bfloat16(acc[mi][f][0] + blo);
                vlo.y = __float2bfloat16(acc[mi][f][1] + blo);
                vhi.x = __float2bfloat16(acc[mi][f][2] + bhi);
                vhi.y = __float2bfloat16(acc[mi][f][3] + bhi);
                *(__nv_bfloat162*)(ob + (size_t)o_lo*NPIX + px) = vlo;
                *(__nv_bfloat162*)(ob + (size_t)o_hi*NPIX + px) = vhi;
            }
        }
    }
}

// ---------------- per-token inverse norms of Q and K ----------------
__global__ __launch_bounds__(256) void k_norms()
{
    int idx = blockIdx.x*256 + threadIdx.x;
    int b = idx >> 12, n = idx & 4095;
    const float* Qp = g_Q + (size_t)b*CH*NPIX + n;
    const float* Kp = g_K + (size_t)b*CH*NPIX + n;
    float sq = 0.f, sk = 0.f;
    #pragma unroll 8
    for (int c = 0; c < CH; c++) {
        float q = Qp[(size_t)c*NPIX]; sq = fmaf(q, q, sq);
        float k = Kp[(size_t)c*NPIX]; sk = fmaf(k, k, sk);
    }
    g_invQ[idx] = 1.0f / sqrtf(sq);
    g_invK[idx] = 1.0f / sqrtf(sk);
}

// ---------------- ksum / vsum; also emits Kn in bf16 ----------------
__global__ __launch_bounds__(256) void k_colsums()
{
    int bc = blockIdx.x;
    int b = bc >> 8;
    const float* Kp = g_K + (size_t)bc*NPIX;
    const __nv_bfloat16* Vp = g_Vbf + (size_t)bc*NPIX;
    const float* ik = g_invK + (size_t)b*NPIX;
    __nv_bfloat16* knp = g_Knbf + (size_t)bc*NPIX;
    int tid = threadIdx.x;
    float sk = 0.f, sv = 0.f;
    for (int n = tid; n < NPIX; n += 256) {
        float kn = Kp[n] * ik[n];
        knp[n] = __float2bfloat16(kn);
        sk += kn;
        sv += __bfloat162float(Vp[n]);
    }
    __shared__ float rk[256], rv[256];
    rk[tid] = sk; rv[tid] = sv;
    __syncthreads();
    for (int s = 128; s > 0; s >>= 1) {
        if (tid < s) { rk[tid] += rk[tid+s]; rv[tid] += rv[tid+s]; }
        __syncthreads();
    }
    if (tid == 0) { g_ksum[bc] = rk[0]; g_vsum[bc] = rv[0]; }
}

// ---------------- A = rw @ kv^T (fp32, small) ----------------
__global__ __launch_bounds__(256) void k_nt(const float* __restrict__ Ap, long strideA,
                                            const float* __restrict__ Bp, long strideB,
                                            int L, float* __restrict__ out)
{
    __shared__ float As[32][65];
    __shared__ float Bs[32][65];
    const int b = blockIdx.z;
    const int i0 = blockIdx.y*64, j0 = blockIdx.x*64;
    const float* A = Ap + (size_t)b*strideA;
    const float* B = Bp + (size_t)b*strideB;
    const int tid = threadIdx.x;
    const int ty = tid >> 4, tx = tid & 15;
    float acc[4][4];
    #pragma unroll
    for (int i = 0; i < 4; i++) {
        #pragma unroll
        for (int j = 0; j < 4; j++) acc[i][j] = 0.f;
    }

    for (int l0 = 0; l0 < L; l0 += 32) {
        #pragma unroll
        for (int r = 0; r < 8; r++) {
            int e = tid + r*256;
            int ii = e >> 5, ll = e & 31;
            As[ll][ii] = A[(size_t)(i0+ii)*L + l0 + ll];
        }
        #pragma unroll
        for (int r = 0; r < 8; r++) {
            int e = tid + r*256;
            int jj = e >> 5, ll = e & 31;
            Bs[ll][jj] = B[(size_t)(j0+jj)*L + l0 + ll];
        }
        __syncthreads();
        #pragma unroll
        for (int ll = 0; ll < 32; ll++) {
            float ar[4], br[4];
            #pragma unroll
            for (int i = 0; i < 4; i++) ar[i] = As[ll][ty*4+i];
            #pragma unroll
            for (int j = 0; j < 4; j++) br[j] = Bs[ll][tx*4+j];
            #pragma unroll
            for (int i = 0; i < 4; i++) {
                #pragma unroll
                for (int j = 0; j < 4; j++)
                    acc[i][j] = fmaf(ar[i], br[j], acc[i][j]);
            }
        }
        __syncthreads();
    }
    float* ob = out + (size_t)b*CH*CH;
    #pragma unroll
    for (int i = 0; i < 4; i++) {
        #pragma unroll
        for (int j = 0; j < 4; j++)
            ob[(size_t)(i0+ty*4+i)*CH + j0 + tx*4 + j] = acc[i][j];
    }
}

// ---------------- rv[b,o] = rw @ vsum ----------------
__global__ __launch_bounds__(256) void k_rv(const float* __restrict__ rw)
{
    int b = blockIdx.x, o = threadIdx.x;
    __shared__ float vs[256];
    vs[o] = g_vsum[b*CH + o];
    __syncthreads();
    float s = 0.f;
    const float* rp = rw + (size_t)o*CH;
    #pragma unroll 8
    for (int c = 0; c < CH; c++) s = fmaf(rp[c], vs[c], s);
    g_rv[b*CH + o] = s;
}

// ---------------- denom ----------------
__global__ __launch_bounds__(256) void k_denom()
{
    int idx = blockIdx.x*256 + threadIdx.x;
    int b = idx >> 12, n = idx & 4095;
    __shared__ float ks[256];
    ks[threadIdx.x] = g_ksum[b*CH + threadIdx.x];
    __syncthreads();
    const float* Qp = g_Q + (size_t)b*CH*NPIX + n;
    float s = 0.f;
    #pragma unroll 8
    for (int c = 0; c < CH; c++) s = fmaf(Qp[(size_t)c*NPIX], ks[c], s);
    float agg = s * g_invQ[idx];
    g_denom[idx] = 1.0f / (4096.0f + agg + 1e-6f);
}

// ---------------- launcher ----------------
extern "C" void kernel_launch(void* const* d_in, const int* in_sizes, int n_in,
                              void* d_out, int out_size)
{
    (void)in_sizes; (void)n_in; (void)out_size;
    const float* x   = (const float*)d_in[0];
    const float* qw  = (const float*)d_in[1];
    const float* qb  = (const float*)d_in[2];
    const float* kw  = (const float*)d_in[3];
    const float* kb  = (const float*)d_in[4];
    const float* vw  = (const float*)d_in[5];
    const float* vb  = (const float*)d_in[6];
    const float* rw  = (const float*)d_in[7];
    const float* rb  = (const float*)d_in[8];
    const float* c1w = (const float*)d_in[9];
    const float* c1b = (const float*)d_in[10];
    const float* c2w = (const float*)d_in[11];
    const float* c2b = (const float*)d_in[12];
    float* out = (float*)d_out;

    float *pQ, *pK, *pkv;
    __nv_bfloat16 *pxbf, *pVbf, *pattnbf, *ph1bf, *pwqkv, *pwc1, *pwc2;
    cudaGetSymbolAddress((void**)&pQ,     g_Q);
    cudaGetSymbolAddress((void**)&pK,     g_K);
    cudaGetSymbolAddress((void**)&pkv,    g_kv);
    cudaGetSymbolAddress((void**)&pxbf,   g_xbf);
    cudaGetSymbolAddress((void**)&pVbf,   g_Vbf);
    cudaGetSymbolAddress((void**)&pattnbf,g_attnbf);
    cudaGetSymbolAddress((void**)&ph1bf,  g_h1bf);
    cudaGetSymbolAddress((void**)&pwqkv,  g_wqkv);
    cudaGetSymbolAddress((void**)&pwc1,   g_wc1b);
    cudaGetSymbolAddress((void**)&pwc2,   g_wc2b);

    static int attr_set = 0;
    if (!attr_set) {
        cudaFuncSetAttribute(k_proj3, cudaFuncAttributeMaxDynamicSharedMemorySize, P3_SMEM);
        attr_set = 1;
    }

    float* pA; cudaGetSymbolAddress((void**)&pA, g_A);

    dim3 gproj(32, 2, BSZ);
    dim3 gkv(2, 2, BSZ*4);
    dim3 gnt(4, 4, BSZ);
    dim3 gconv(32, 2, BSZ);

    // conversions
    k_cvt<<<(BSZ*CH*NPIX)/1024, 256>>>(x, pxbf);
    k_cvtw<<<(3*CH*CH)/256, 256>>>(qw, kw, vw, pwqkv);
    k_cvt_wc<<<(9*CH*CH)/256, 256>>>(c1w, pwc1);
    k_cvt_wc<<<(9*CH*CH)/256, 256>>>(c2w, pwc2);

    k_proj3<<<gproj, 256, P3_SMEM>>>(pwqkv, qb, kb, vb, pQ, pK, pVbf);
    k_norms<<<(BSZ*NPIX)/256, 256>>>();
    k_colsums<<<BSZ*CH, 256>>>();
    k_kv_tc<<<gkv, 256>>>();
    k_kvred<<<(BSZ*CH*CH)/256, 256>>>();
    k_nt<<<gnt, 256>>>(rw, 0L, pkv, (long)CH*CH, CH, pA);
    k_rv<<<BSZ, 256>>>(rw);
    k_denom<<<(BSZ*NPIX)/256, 256>>>();
    k_attn_tc<<<gproj, 256>>>(rb);
    k_conv_tc<<<gconv, 256>>>(pattnbf, pwc1, c1b, (const float*)0, (float*)0, ph1bf, 0);
    k_conv_tc<<<gconv, 256>>>(ph1bf, pwc2, c2b, x, out, (__nv_bfloat16*)0, 1);
}

// round 7
// speedup vs baseline: 5.7145x; 1.0960x over previous
#include <cuda_runtime.h>
#include <cuda_bf16.h>
#include <math.h>
#include <cstdint>

#define BSZ  8
#define CH   256
#define NPIX 4096
#define IMW  64
#define LDA  40   // bf16 elems per smem row (80B, conflict-free ldmatrix)
#define LDB3 264  // proj3 shared-B row width

// ---------------- scratch (device globals; alloc-free) ----------------
__device__ float g_invQ[BSZ*NPIX];
__device__ float g_invK[BSZ*NPIX];
__device__ float g_ksum[BSZ*CH];
__device__ float g_vsum[BSZ*CH];
__device__ float g_kv[BSZ*CH*CH];
__device__ float g_kvp[BSZ*4*CH*CH];
__device__ float g_rv[BSZ*CH];
__device__ float g_denom[BSZ*NPIX];
// bf16 operands
__device__ __nv_bfloat16 g_xbf[BSZ*CH*NPIX];
__device__ __nv_bfloat16 g_Qbf[BSZ*CH*NPIX];
__device__ __nv_bfloat16 g_Kbf[BSZ*CH*NPIX];
__device__ __nv_bfloat16 g_Vbf[BSZ*CH*NPIX];
__device__ __nv_bfloat16 g_Knbf[BSZ*CH*NPIX];
__device__ __nv_bfloat16 g_attnbf[BSZ*CH*NPIX];
__device__ __nv_bfloat16 g_h1bf[BSZ*CH*NPIX];
__device__ __nv_bfloat16 g_Abf[BSZ*CH*CH];
__device__ __nv_bfloat16 g_wqkv[3*CH*CH];   // [which][o][c]
__device__ __nv_bfloat16 g_wc1b[9*CH*CH];   // [t][o][c]
__device__ __nv_bfloat16 g_wc2b[9*CH*CH];

// ================= warp-MMA helpers =================
__device__ __forceinline__ uint32_t smem_u32(const void* p) {
    uint32_t a;
    asm("{ .reg .u64 t; cvta.to.shared.u64 t, %1; cvt.u32.u64 %0, t; }" : "=r"(a) : "l"(p));
    return a;
}
__device__ __forceinline__ void ldsm_x4(uint32_t (&r)[4], uint32_t addr) {
    asm volatile("ldmatrix.sync.aligned.m8n8.x4.shared.b16 {%0,%1,%2,%3}, [%4];"
        : "=r"(r[0]), "=r"(r[1]), "=r"(r[2]), "=r"(r[3]) : "r"(addr));
}
__device__ __forceinline__ void mma16816(float (&d)[4], const uint32_t (&a)[4],
                                         uint32_t b0, uint32_t b1) {
    asm volatile("mma.sync.aligned.m16n8k16.row.col.f32.bf16.bf16.f32 "
        "{%0,%1,%2,%3}, {%4,%5,%6,%7}, {%8,%9}, {%0,%1,%2,%3};"
        : "+f"(d[0]), "+f"(d[1]), "+f"(d[2]), "+f"(d[3])
        : "r"(a[0]), "r"(a[1]), "r"(a[2]), "r"(a[3]), "r"(b0), "r"(b1));
}

#define MMA_CHUNK_G(As, AW, Bs, BW, coff, acc, lane, wm, wn) do {                   \
    _Pragma("unroll")                                                               \
    for (int ks = 0; ks < 2; ks++) {                                                \
        uint32_t a_[2][4];                                                          \
        _Pragma("unroll")                                                           \
        for (int mi = 0; mi < 2; mi++)                                              \
            ldsm_x4(a_[mi], smem_u32(&(As)[((wm)*32 + mi*16 + ((lane)&15))*(AW)     \
                                          + ks*16 + ((lane)>>4)*8]));               \
        uint32_t b_[4][4];                                                          \
        _Pragma("unroll")                                                           \
        for (int ni = 0; ni < 4; ni++)                                              \
            ldsm_x4(b_[ni], smem_u32(&(Bs)[((wn)*64 + ni*16 + (((lane)>>4)&1)*8     \
                                            + ((lane)&7))*(BW)                      \
                                           + (coff) + ks*16 + (((lane)>>3)&1)*8])); \
        _Pragma("unroll")                                                           \
        for (int mi = 0; mi < 2; mi++) {                                            \
            _Pragma("unroll")                                                       \
            for (int ni = 0; ni < 4; ni++) {                                        \
                mma16816(acc[mi][ni*2],   a_[mi], b_[ni][0], b_[ni][1]);            \
                mma16816(acc[mi][ni*2+1], a_[mi], b_[ni][2], b_[ni][3]);            \
            }                                                                       \
        }                                                                           \
    }                                                                               \
} while (0)

#define ACC_ZERO(acc) do {                                                          \
    _Pragma("unroll")                                                               \
    for (int i_ = 0; i_ < 2; i_++) {                                                \
        _Pragma("unroll")                                                           \
        for (int j_ = 0; j_ < 8; j_++) {                                            \
            _Pragma("unroll")                                                       \
            for (int q_ = 0; q_ < 4; q_++) acc[i_][j_][q_] = 0.f;                   \
        }                                                                           \
    }                                                                               \
} while (0)

// ---------------- conversion kernels ----------------
__global__ __launch_bounds__(256) void k_cvt(const float* __restrict__ src,
                                             __nv_bfloat16* __restrict__ dst)
{
    int i = (blockIdx.x*256 + threadIdx.x) * 4;
    float4 v = *(const float4*)(src + i);
    dst[i+0] = __float2bfloat16(v.x);
    dst[i+1] = __float2bfloat16(v.y);
    dst[i+2] = __float2bfloat16(v.z);
    dst[i+3] = __float2bfloat16(v.w);
}
__global__ __launch_bounds__(256) void k_cvtw(const float* __restrict__ q,
                                              const float* __restrict__ k,
                                              const float* __restrict__ v,
                                              __nv_bfloat16* __restrict__ dst)
{
    int i = blockIdx.x*256 + threadIdx.x;
    int which = i >> 16, r = i & 65535;
    const float* s = (which == 0) ? q : (which == 1) ? k : v;
    dst[i] = __float2bfloat16(s[r]);
}
__global__ __launch_bounds__(256) void k_cvt_wc(const float* __restrict__ w,
                                                __nv_bfloat16* __restrict__ dst)
{
    int i = blockIdx.x*256 + threadIdx.x;
    int c = i & 255, o = (i >> 8) & 255, t = i >> 16;
    dst[i] = __float2bfloat16(w[o*2304 + c*9 + t]);
}

// ---------------- fused QKV projection (all-bf16 outputs) ----------------
#define P3_BS_BYTES (128*LDB3*2)
#define P3_SMEM     (P3_BS_BYTES + 2*128*LDA*2)
__global__ __launch_bounds__(256) void k_proj3(const __nv_bfloat16* __restrict__ w3,
                                               const float* __restrict__ qb,
                                               const float* __restrict__ kb,
                                               const float* __restrict__ vb,
                                               __nv_bfloat16* __restrict__ outQ,
                                               __nv_bfloat16* __restrict__ outK,
                                               __nv_bfloat16* __restrict__ outV)
{
    extern __shared__ __align__(16) char dsm[];
    __nv_bfloat16* Bs = (__nv_bfloat16*)dsm;                 // [128][LDB3]
    __nv_bfloat16* As = (__nv_bfloat16*)(dsm + P3_BS_BYTES); // [2][128][LDA]
    const int b  = blockIdx.z;
    const int o0 = blockIdx.y * 128;
    const int n0 = blockIdx.x * 128;
    const __nv_bfloat16* inb = g_xbf + (size_t)b*CH*NPIX;
    const int tid = threadIdx.x;
    const int wid = tid >> 5, lane = tid & 31;
    const int wm = wid & 3, wn = wid >> 2;

    #pragma unroll
    for (int i = 0; i < 16; i++) {
        int e = tid + i*256;
        int c = e >> 4, n8 = (e & 15) * 8;
        uint4 v = *(const uint4*)(inb + (size_t)c*NPIX + n0 + n8);
        const __nv_bfloat16* pv = (const __nv_bfloat16*)&v;
        #pragma unroll
        for (int j = 0; j < 8; j++) Bs[(n8+j)*LDB3 + c] = pv[j];
    }

    float acc[2][8][4];
    const int r0 = lane >> 2, c2 = (lane & 3)*2;

    #pragma unroll
    for (int which = 0; which < 3; which++) {
        const __nv_bfloat16* w = w3 + (size_t)which*CH*CH;
        ACC_ZERO(acc);
        #pragma unroll
        for (int i = 0; i < 2; i++) {
            int e = tid + i*256;
            int o = e >> 2, cq = e & 3;
            *(uint4*)&As[(0*128 + o)*LDA + cq*8] = *(const uint4*)(w + (size_t)(o0+o)*CH + cq*8);
        }
        for (int kc = 0; kc < 8; kc++) {
            __syncthreads();
            int buf = kc & 1;
            if (kc + 1 < 8) {
                int cb = (kc + 1) * 32;
                #pragma unroll
                for (int i = 0; i < 2; i++) {
                    int e = tid + i*256;
                    int o = e >> 2, cq = e & 3;
                    *(uint4*)&As[((buf^1)*128 + o)*LDA + cq*8] =
                        *(const uint4*)(w + (size_t)(o0+o)*CH + cb + cq*8);
                }
            }
            MMA_CHUNK_G((As + buf*128*LDA), LDA, Bs, LDB3, kc*32, acc, lane, wm, wn);
        }
        const float* bias = (which == 0) ? qb : (which == 1) ? kb : vb;
        __nv_bfloat16* ob = ((which == 0) ? outQ : (which == 1) ? outK : outV)
                            + (size_t)b*CH*NPIX;
        #pragma unroll
        for (int mi = 0; mi < 2; mi++) {
            int o_lo = o0 + wm*32 + mi*16 + r0;
            int o_hi = o_lo + 8;
            float blo = bias[o_lo], bhi = bias[o_hi];
            #pragma unroll
            for (int nj = 0; nj < 8; nj++) {
                int n = n0 + wn*64 + nj*8 + c2;
                __nv_bfloat162 vlo, vhi;
                vlo.x = __float2bfloat16(acc[mi][nj][0] + blo);
                vlo.y = __float2bfloat16(acc[mi][nj][1] + blo);
                vhi.x = __float2bfloat16(acc[mi][nj][2] + bhi);
                vhi.y = __float2bfloat16(acc[mi][nj][3] + bhi);
                *(__nv_bfloat162*)(ob + (size_t)o_lo*NPIX + n) = vlo;
                *(__nv_bfloat162*)(ob + (size_t)o_hi*NPIX + n) = vhi;
            }
        }
    }
}

// ---------------- bf16 MMA kv GEMM, split-N=4 ----------------
__global__ __launch_bounds__(256) void k_kv_tc()
{
    __shared__ __align__(16) __nv_bfloat16 As[2][128][LDA];
    __shared__ __align__(16) __nv_bfloat16 Bs[2][128][LDA];
    const int bsp = blockIdx.z;
    const int b = bsp >> 2, sp = bsp & 3;
    const int k0 = blockIdx.y * 128;
    const int c0 = blockIdx.x * 128;
    const int nb = sp * 1024;
    const __nv_bfloat16* Kn = g_Knbf + (size_t)b*CH*NPIX;
    const __nv_bfloat16* Vb = g_Vbf  + (size_t)b*CH*NPIX;
    const int tid = threadIdx.x;
    const int wid = tid >> 5, lane = tid & 31;
    const int wm = wid & 3, wn = wid >> 2;

    float acc[2][8][4];
    ACC_ZERO(acc);

    #pragma unroll
    for (int i = 0; i < 16; i++) {
        int e = tid + i*256;
        int r = e >> 5, n = e & 31;
        As[0][r][n] = Kn[(size_t)(k0+r)*NPIX + nb + n];
        Bs[0][r][n] = Vb[(size_t)(c0+r)*NPIX + nb + n];
    }

    for (int kc = 0; kc < 32; kc++) {
        __syncthreads();
        int buf = kc & 1;
        if (kc + 1 < 32) {
            int nn = nb + (kc + 1) * 32;
            #pragma unroll
            for (int i = 0; i < 16; i++) {
                int e = tid + i*256;
                int r = e >> 5, n = e & 31;
                As[buf^1][r][n] = Kn[(size_t)(k0+r)*NPIX + nn + n];
                Bs[buf^1][r][n] = Vb[(size_t)(c0+r)*NPIX + nn + n];
            }
        }
        MMA_CHUNK_G(&As[buf][0][0], LDA, &Bs[buf][0][0], LDA, 0, acc, lane, wm, wn);
    }

    float* ob = g_kvp + (size_t)bsp*CH*CH;
    const int r0 = lane >> 2, c2 = (lane & 3)*2;
    #pragma unroll
    for (int mi = 0; mi < 2; mi++) {
        int k_lo = k0 + wm*32 + mi*16 + r0;
        int k_hi = k_lo + 8;
        #pragma unroll
        for (int nj = 0; nj < 8; nj++) {
            int c = c0 + wn*64 + nj*8 + c2;
            *(float2*)(ob + (size_t)k_lo*CH + c) = make_float2(acc[mi][nj][0], acc[mi][nj][1]);
            *(float2*)(ob + (size_t)k_hi*CH + c) = make_float2(acc[mi][nj][2], acc[mi][nj][3]);
        }
    }
}

__global__ __launch_bounds__(256) void k_kvred()
{
    int i = blockIdx.x*256 + threadIdx.x;
    int b = i >> 16, r = i & 65535;
    const float* p = g_kvp + (size_t)b*4*65536;
    g_kv[i] = (p[r] + p[65536 + r]) + (p[2*65536 + r] + p[3*65536 + r]);
}

// ---------------- bf16 MMA attn GEMM + epilogue ----------------
__global__ __launch_bounds__(256) void k_attn_tc(const float* __restrict__ rb)
{
    __shared__ __align__(16) __nv_bfloat16 As[2][128][LDA];
    __shared__ __align__(16) __nv_bfloat16 Bs[2][128][LDA];
    const int b  = blockIdx.z;
    const int o0 = blockIdx.y * 128;
    const int n0 = blockIdx.x * 128;
    const __nv_bfloat16* Am = g_Abf + (size_t)b*CH*CH;
    const __nv_bfloat16* Qb = g_Qbf + (size_t)b*CH*NPIX;
    const int tid = threadIdx.x;
    const int wid = tid >> 5, lane = tid & 31;
    const int wm = wid & 3, wn = wid >> 2;

    float acc[2][8][4];
    ACC_ZERO(acc);

    #pragma unroll
    for (int i = 0; i < 2; i++) {
        int e = tid + i*256;
        int o = e >> 2, cq = e & 3;
        *(uint4*)&As[0][o][cq*8] = *(const uint4*)(Am + (size_t)(o0+o)*CH + cq*8);
    }
    #pragma unroll
    for (int i = 0; i < 2; i++) {
        int e = tid + i*256;
        int c = e >> 4, n8 = (e & 15) * 8;
        uint4 v = *(const uint4*)(Qb + (size_t)c*NPIX + n0 + n8);
        const __nv_bfloat16* pv = (const __nv_bfloat16*)&v;
        #pragma unroll
        for (int j = 0; j < 8; j++) Bs[0][n8+j][c] = pv[j];
    }

    for (int kc = 0; kc < 8; kc++) {
        __syncthreads();
        int buf = kc & 1;
        if (kc + 1 < 8) {
            int cb = (kc + 1) * 32;
            #pragma unroll
            for (int i = 0; i < 2; i++) {
                int e = tid + i*256;
                int o = e >> 2, cq = e & 3;
                *(uint4*)&As[buf^1][o][cq*8] = *(const uint4*)(Am + (size_t)(o0+o)*CH + cb + cq*8);
            }
            #pragma unroll
            for (int i = 0; i < 2; i++) {
                int e = tid + i*256;
                int c = e >> 4, n8 = (e & 15) * 8;
                uint4 v = *(const uint4*)(Qb + (size_t)(cb+c)*NPIX + n0 + n8);
                const __nv_bfloat16* pv = (const __nv_bfloat16*)&v;
                #pragma unroll
                for (int j = 0; j < 8; j++) Bs[buf^1][n8+j][c] = pv[j];
            }
        }
        MMA_CHUNK_G(&As[buf][0][0], LDA, &Bs[buf][0][0], LDA, 0, acc, lane, wm, wn);
    }

    __nv_bfloat16* ob = g_attnbf + (size_t)b*CH*NPIX;
    const int r0 = lane >> 2, c2 = (lane & 3)*2;
    #pragma unroll
    for (int mi = 0; mi < 2; mi++) {
        int o_lo = o0 + wm*32 + mi*16 + r0;
        int o_hi = o_lo + 8;
        float rvlo = g_rv[b*CH + o_lo], rvhi = g_rv[b*CH + o_hi];
        float rblo = rb[o_lo], rbhi = rb[o_hi];
        #pragma unroll
        for (int nj = 0; nj < 8; nj++) {
            int n = n0 + wn*64 + nj*8 + c2;
            float iq0 = g_invQ[b*NPIX + n],     dn0 = g_denom[b*NPIX + n];
            float iq1 = g_invQ[b*NPIX + n + 1], dn1 = g_denom[b*NPIX + n + 1];
            __nv_bfloat162 vlo, vhi;
            vlo.x = __float2bfloat16(fmaf(fmaf(iq0, acc[mi][nj][0], rvlo), dn0, rblo));
            vlo.y = __float2bfloat16(fmaf(fmaf(iq1, acc[mi][nj][1], rvlo), dn1, rblo));
            vhi.x = __float2bfloat16(fmaf(fmaf(iq0, acc[mi][nj][2], rvhi), dn0, rbhi));
            vhi.y = __float2bfloat16(fmaf(fmaf(iq1, acc[mi][nj][3], rvhi), dn1, rbhi));
            *(__nv_bfloat162*)(ob + (size_t)o_lo*NPIX + n) = vlo;
            *(__nv_bfloat162*)(ob + (size_t)o_hi*NPIX + n) = vhi;
        }
    }
}

// ---------------- bf16 MMA 3x3 conv: vectorized double-buffered halo fill ----------------
#define CONV_AS_BYTES (2*128*LDA*2)
#define CONV_SMEM     (CONV_AS_BYTES + 2*16*264*4)

__device__ __forceinline__ void conv_fillB(uint32_t* __restrict__ Bw,
                                           const __nv_bfloat16* __restrict__ inb,
                                           int cbase, int pr0, int tid)
{
    #pragma unroll
    for (int it = 0; it < 2; it++) {
        int e = tid + it*256;
        int kw = e >> 5;
        int row = (e >> 3) & 3;
        int seg = e & 7;
        int gr = pr0 - 1 + row;
        uint32_t* dst = Bw + kw*264 + row*66 + 1 + seg*8;
        if ((unsigned)gr < IMW) {
            const __nv_bfloat16* q = inb + (size_t)(cbase + kw*2)*NPIX + gr*IMW + seg*8;
            uint4 lo4 = *(const uint4*)q;
            uint4 hi4 = *(const uint4*)(q + NPIX);
            const unsigned short* ls = (const unsigned short*)&lo4;
            const unsigned short* hs = (const unsigned short*)&hi4;
            #pragma unroll
            for (int j = 0; j < 8; j++)
                dst[j] = (uint32_t)ls[j] | ((uint32_t)hs[j] << 16);
        } else {
            #pragma unroll
            for (int j = 0; j < 8; j++) dst[j] = 0u;
        }
    }
}

__global__ __launch_bounds__(256) void k_conv_tc(const __nv_bfloat16* __restrict__ in,
                                                 const __nv_bfloat16* __restrict__ wt,
                                                 const float* __restrict__ bias,
                                                 const float* __restrict__ xres,
                                                 float* __restrict__ out_f,
                                                 __nv_bfloat16* __restrict__ out_bf,
                                                 int fuse)
{
    extern __shared__ __align__(16) char dsm[];
    __nv_bfloat16* Asm = (__nv_bfloat16*)dsm;                 // [2][128][LDA]
    uint32_t* Bw0 = (uint32_t*)(dsm + CONV_AS_BYTES);
    uint32_t* Bw1 = Bw0 + 16*264;
    const int b   = blockIdx.z;
    const int o0  = blockIdx.y * 128;
    const int pr0 = blockIdx.x * 2;
    const __nv_bfloat16* inb = in + (size_t)b*CH*NPIX;
    const int tid = threadIdx.x;
    const int wid = tid >> 5, lane = tid & 31;
    const int wm = wid & 3, wn = wid >> 2;

    float acc[2][8][4];
    ACC_ZERO(acc);

    // halo columns are ALWAYS zero (tile spans full image width) — write once, both buffers
    if (tid < 128) {
        int kw = tid >> 3;
        int row = (tid >> 1) & 3;
        int side = tid & 1;
        int off = kw*264 + row*66 + side*65;
        Bw0[off] = 0u;
        Bw1[off] = 0u;
    }
    conv_fillB(Bw0, inb, 0, pr0, tid);
    // A prefill (t=0, cb=0)
    #pragma unroll
    for (int i = 0; i < 2; i++) {
        int e = tid + i*256;
        int o = e >> 2, cq = e & 3;
        *(uint4*)(Asm + (size_t)o*LDA + cq*8) = *(const uint4*)(wt + ((size_t)o0 + o)*256 + cq*8);
    }
    __syncthreads();

    int s = 0;
    for (int cb = 0; cb < 8; cb++) {
        uint32_t* Bcur = (cb & 1) ? Bw1 : Bw0;
        uint32_t* Bnxt = (cb & 1) ? Bw0 : Bw1;
        for (int t = 0; t < 9; t++, s++) {
            const int pa = s & 1;
            if (s + 1 < 72) {
                int tn = (t + 1 == 9) ? 0 : t + 1;
                int cbn = (t + 1 == 9) ? (cb + 1) : cb;
                const __nv_bfloat16* wsrc = wt + ((size_t)tn*256 + o0)*256 + cbn*32;
                #pragma unroll
                for (int i = 0; i < 2; i++) {
                    int e = tid + i*256;
                    int o = e >> 2, cq = e & 3;
                    *(uint4*)(Asm + ((size_t)(pa^1)*128 + o)*LDA + cq*8) =
                        *(const uint4*)(wsrc + (size_t)o*256 + cq*8);
                }
            }
            if (t == 0 && cb < 7)
                conv_fillB(Bnxt, inb, (cb + 1) * 32, pr0, tid);
            {
                const int dy = t / 3 - 1, dx = t % 3 - 1;
                const int rowoff = (1 + wn + dy) * 66 + 1 + dx;
                #pragma unroll
                for (int ks = 0; ks < 2; ks++) {
                    uint32_t a0[4], a1[4];
                    ldsm_x4(a0, smem_u32(Asm + ((size_t)pa*128 + wm*32 + (lane&15))*LDA
                                         + ks*16 + (lane>>4)*8));
                    ldsm_x4(a1, smem_u32(Asm + ((size_t)pa*128 + wm*32 + 16 + (lane&15))*LDA
                                         + ks*16 + (lane>>4)*8));
                    const uint32_t* bp = Bcur + (ks*8 + (lane&3))*264 + rowoff + (lane>>2);
                    #pragma unroll
                    for (int f = 0; f < 8; f++) {
                        uint32_t b0 = bp[f*8];
                        uint32_t b1 = bp[f*8 + 4*264];
                        mma16816(acc[0][f], a0, b0, b1);
                        mma16816(acc[1][f], a1, b0, b1);
                    }
                }
            }
            __syncthreads();
        }
    }

    const int r0 = lane >> 2, c2 = (lane & 3)*2;
    const int pxbase = pr0*64;
    if (fuse) {
        const float* xb = xres + (size_t)b*CH*NPIX;
        float* ob = out_f + (size_t)b*CH*NPIX;
        #pragma unroll
        for (int mi = 0; mi < 2; mi++) {
            int o_lo = o0 + wm*32 + mi*16 + r0;
            int o_hi = o_lo + 8;
            float blo = bias[o_lo], bhi = bias[o_hi];
            #pragma unroll
            for (int f = 0; f < 8; f++) {
                int px = pxbase + wn*64 + f*8 + c2;
                float a0 = acc[mi][f][0] + blo, a1 = acc[mi][f][1] + blo;
                float a2 = acc[mi][f][2] + bhi, a3 = acc[mi][f][3] + bhi;
                float2 xlo = *(const float2*)(xb + (size_t)o_lo*NPIX + px);
                float2 xhi = *(const float2*)(xb + (size_t)o_hi*NPIX + px);
                a0 = fmaf(a0, xlo.x, xlo.x);
                a1 = fmaf(a1, xlo.y, xlo.y);
                a2 = fmaf(a2, xhi.x, xhi.x);
                a3 = fmaf(a3, xhi.y, xhi.y);
                *(float2*)(ob + (size_t)o_lo*NPIX + px) = make_float2(a0, a1);
                *(float2*)(ob + (size_t)o_hi*NPIX + px) = make_float2(a2, a3);
            }
        }
    } else {
        __nv_bfloat16* ob = out_bf + (size_t)b*CH*NPIX;
        #pragma unroll
        for (int mi = 0; mi < 2; mi++) {
            int o_lo = o0 + wm*32 + mi*16 + r0;
            int o_hi = o_lo + 8;
            float blo = bias[o_lo], bhi = bias[o_hi];
            #pragma unroll
            for (int f = 0; f < 8; f++) {
                int px = pxbase + wn*64 + f*8 + c2;
                __nv_bfloat162 vlo, vhi;
                vlo.x = __float2bfloat16(acc[mi][f][0] + blo);
                vlo.y = __float2bfloat16(acc[mi][f][1] + blo);
                vhi.x = __float2bfloat16(acc[mi][f][2] + bhi);
                vhi.y = __float2bfloat16(acc[mi][f][3] + bhi);
                *(__nv_bfloat162*)(ob + (size_t)o_lo*NPIX + px) = vlo;
                *(__nv_bfloat162*)(ob + (size_t)o_hi*NPIX + px) = vhi;
            }
        }
    }
}

// ---------------- per-token inverse norms (bf16 inputs, 2 tokens/thread) ----------------
__global__ __launch_bounds__(256) void k_norms()
{
    int idx2 = blockIdx.x*256 + threadIdx.x;     // pair index, BSZ*NPIX/2 total
    int b = idx2 >> 11, n = (idx2 & 2047) * 2;
    const __nv_bfloat16* Qp = g_Qbf + (size_t)b*CH*NPIX + n;
    const __nv_bfloat16* Kp = g_Kbf + (size_t)b*CH*NPIX + n;
    float sq0 = 0.f, sq1 = 0.f, sk0 = 0.f, sk1 = 0.f;
    #pragma unroll 16
    for (int c = 0; c < CH; c++) {
        __nv_bfloat162 q = *(const __nv_bfloat162*)(Qp + (size_t)c*NPIX);
        __nv_bfloat162 k = *(const __nv_bfloat162*)(Kp + (size_t)c*NPIX);
        float qx = __bfloat162float(q.x), qy = __bfloat162float(q.y);
        float kx = __bfloat162float(k.x), ky = __bfloat162float(k.y);
        sq0 = fmaf(qx, qx, sq0); sq1 = fmaf(qy, qy, sq1);
        sk0 = fmaf(kx, kx, sk0); sk1 = fmaf(ky, ky, sk1);
    }
    int o = b*NPIX + n;
    g_invQ[o]   = 1.0f / sqrtf(sq0);
    g_invQ[o+1] = 1.0f / sqrtf(sq1);
    g_invK[o]   = 1.0f / sqrtf(sk0);
    g_invK[o+1] = 1.0f / sqrtf(sk1);
}

// ---------------- ksum / vsum; emits normalized Kn bf16 (vectorized) ----------------
__global__ __launch_bounds__(256) void k_colsums()
{
    int bc = blockIdx.x;
    int b = bc >> 8;
    const __nv_bfloat16* Kp = g_Kbf + (size_t)bc*NPIX;
    const __nv_bfloat16* Vp = g_Vbf + (size_t)bc*NPIX;
    const float* ik = g_invK + (size_t)b*NPIX;
    __nv_bfloat16* knp = g_Knbf + (size_t)bc*NPIX;
    int tid = threadIdx.x;
    float sk = 0.f, sv = 0.f;
    #pragma unroll
    for (int it = 0; it < 2; it++) {
        int base = (tid + it*256) * 8;
        uint4 kv4 = *(const uint4*)(Kp + base);
        uint4 vv4 = *(const uint4*)(Vp + base);
        float4 ika = *(const float4*)(ik + base);
        float4 ikb = *(const float4*)(ik + base + 4);
        const __nv_bfloat16* kk = (const __nv_bfloat16*)&kv4;
        const __nv_bfloat16* vv = (const __nv_bfloat16*)&vv4;
        float iks[8] = {ika.x, ika.y, ika.z, ika.w, ikb.x, ikb.y, ikb.z, ikb.w};
        unsigned short outw[8];
        #pragma unroll
        for (int j = 0; j < 8; j++) {
            float kn = __bfloat162float(kk[j]) * iks[j];
            __nv_bfloat16 knb = __float2bfloat16(kn);
            outw[j] = __bfloat16_as_ushort(knb);
            sk += kn;
            sv += __bfloat162float(vv[j]);
        }
        *(uint4*)(knp + base) = *(uint4*)outw;
    }
    __shared__ float rk[256], rv[256];
    rk[tid] = sk; rv[tid] = sv;
    __syncthreads();
    for (int s = 128; s > 0; s >>= 1) {
        if (tid < s) { rk[tid] += rk[tid+s]; rv[tid] += rv[tid+s]; }
        __syncthreads();
    }
    if (tid == 0) { g_ksum[bc] = rk[0]; g_vsum[bc] = rv[0]; }
}

// ---------------- A = rw @ kv^T (fp32 in, bf16 out) ----------------
__global__ __launch_bounds__(256) void k_nt(const float* __restrict__ Ap, long strideA,
                                            const float* __restrict__ Bp, long strideB,
                                            int L, __nv_bfloat16* __restrict__ out)
{
    __shared__ float As[32][65];
    __shared__ float Bs[32][65];
    const int b = blockIdx.z;
    const int i0 = blockIdx.y*64, j0 = blockIdx.x*64;
    const float* A = Ap + (size_t)b*strideA;
    const float* B = Bp + (size_t)b*strideB;
    const int tid = threadIdx.x;
    const int ty = tid >> 4, tx = tid & 15;
    float acc[4][4];
    #pragma unroll
    for (int i = 0; i < 4; i++) {
        #pragma unroll
        for (int j = 0; j < 4; j++) acc[i][j] = 0.f;
    }

    for (int l0 = 0; l0 < L; l0 += 32) {
        #pragma unroll
        for (int r = 0; r < 8; r++) {
            int e = tid + r*256;
            int ii = e >> 5, ll = e & 31;
            As[ll][ii] = A[(size_t)(i0+ii)*L + l0 + ll];
        }
        #pragma unroll
        for (int r = 0; r < 8; r++) {
            int e = tid + r*256;
            int jj = e >> 5, ll = e & 31;
            Bs[ll][jj] = B[(size_t)(j0+jj)*L + l0 + ll];
        }
        __syncthreads();
        #pragma unroll
        for (int ll = 0; ll < 32; ll++) {
            float ar[4], br[4];
            #pragma unroll
            for (int i = 0; i < 4; i++) ar[i] = As[ll][ty*4+i];
            #pragma unroll
            for (int j = 0; j < 4; j++) br[j] = Bs[ll][tx*4+j];
            #pragma unroll
            for (int i = 0; i < 4; i++) {
                #pragma unroll
                for (int j = 0; j < 4; j++)
                    acc[i][j] = fmaf(ar[i], br[j], acc[i][j]);
            }
        }
        __syncthreads();
    }
    __nv_bfloat16* ob = out + (size_t)b*CH*CH;
    #pragma unroll
    for (int i = 0; i < 4; i++) {
        #pragma unroll
        for (int j = 0; j < 4; j++)
            ob[(size_t)(i0+ty*4+i)*CH + j0 + tx*4 + j] = __float2bfloat16(acc[i][j]);
    }
}

// ---------------- rv[b,o] = rw @ vsum ----------------
__global__ __launch_bounds__(256) void k_rv(const float* __restrict__ rw)
{
    int b = blockIdx.x, o = threadIdx.x;
    __shared__ float vs[256];
    vs[o] = g_vsum[b*CH + o];
    __syncthreads();
    float s = 0.f;
    const float* rp = rw + (size_t)o*CH;
    #pragma unroll 8
    for (int c = 0; c < CH; c++) s = fmaf(rp[c], vs[c], s);
    g_rv[b*CH + o] = s;
}

// ---------------- denom (bf16 Q, 2 tokens/thread) ----------------
__global__ __launch_bounds__(256) void k_denom()
{
    int idx2 = blockIdx.x*256 + threadIdx.x;
    int b = idx2 >> 11, n = (idx2 & 2047) * 2;
    __shared__ float ks[256];
    ks[threadIdx.x] = g_ksum[b*CH + threadIdx.x];
    __syncthreads();
    const __nv_bfloat16* Qp = g_Qbf + (size_t)b*CH*NPIX + n;
    float s0 = 0.f, s1 = 0.f;
    #pragma unroll 16
    for (int c = 0; c < CH; c++) {
        __nv_bfloat162 q = *(const __nv_bfloat162*)(Qp + (size_t)c*NPIX);
        s0 = fmaf(__bfloat162float(q.x), ks[c], s0);
        s1 = fmaf(__bfloat162float(q.y), ks[c], s1);
    }
    int o = b*NPIX + n;
    g_denom[o]   = 1.0f / (4096.0f + s0 * g_invQ[o]   + 1e-6f);
    g_denom[o+1] = 1.0f / (4096.0f + s1 * g_invQ[o+1] + 1e-6f);
}

// ---------------- launcher ----------------
extern "C" void kernel_launch(void* const* d_in, const int* in_sizes, int n_in,
                              void* d_out, int out_size)
{
    (void)in_sizes; (void)n_in; (void)out_size;
    const float* x   = (const float*)d_in[0];
    const float* qw  = (const float*)d_in[1];
    const float* qb  = (const float*)d_in[2];
    const float* kw  = (const float*)d_in[3];
    const float* kb  = (const float*)d_in[4];
    const float* vw  = (const float*)d_in[5];
    const float* vb  = (const float*)d_in[6];
    const float* rw  = (const float*)d_in[7];
    const float* rb  = (const float*)d_in[8];
    const float* c1w = (const float*)d_in[9];
    const float* c1b = (const float*)d_in[10];
    const float* c2w = (const float*)d_in[11];
    const float* c2b = (const float*)d_in[12];
    float* out = (float*)d_out;

    float* pkv;
    __nv_bfloat16 *pxbf, *pQbf, *pKbf, *pVbf, *pattnbf, *ph1bf, *pAbf, *pwqkv, *pwc1, *pwc2;
    cudaGetSymbolAddress((void**)&pkv,    g_kv);
    cudaGetSymbolAddress((void**)&pxbf,   g_xbf);
    cudaGetSymbolAddress((void**)&pQbf,   g_Qbf);
    cudaGetSymbolAddress((void**)&pKbf,   g_Kbf);
    cudaGetSymbolAddress((void**)&pVbf,   g_Vbf);
    cudaGetSymbolAddress((void**)&pattnbf,g_attnbf);
    cudaGetSymbolAddress((void**)&ph1bf,  g_h1bf);
    cudaGetSymbolAddress((void**)&pAbf,   g_Abf);
    cudaGetSymbolAddress((void**)&pwqkv,  g_wqkv);
    cudaGetSymbolAddress((void**)&pwc1,   g_wc1b);
    cudaGetSymbolAddress((void**)&pwc2,   g_wc2b);

    static int attr_set = 0;
    if (!attr_set) {
        cudaFuncSetAttribute(k_proj3,   cudaFuncAttributeMaxDynamicSharedMemorySize, P3_SMEM);
        cudaFuncSetAttribute(k_conv_tc, cudaFuncAttributeMaxDynamicSharedMemorySize, CONV_SMEM);
        attr_set = 1;
    }

    dim3 gproj(32, 2, BSZ);
    dim3 gkv(2, 2, BSZ*4);
    dim3 gnt(4, 4, BSZ);
    dim3 gconv(32, 2, BSZ);

    k_cvt<<<(BSZ*CH*NPIX)/1024, 256>>>(x, pxbf);
    k_cvtw<<<(3*CH*CH)/256, 256>>>(qw, kw, vw, pwqkv);
    k_cvt_wc<<<(9*CH*CH)/256, 256>>>(c1w, pwc1);
    k_cvt_wc<<<(9*CH*CH)/256, 256>>>(c2w, pwc2);

    k_proj3<<<gproj, 256, P3_SMEM>>>(pwqkv, qb, kb, vb, pQbf, pKbf, pVbf);
    k_norms<<<(BSZ*NPIX/2)/256, 256>>>();
    k_colsums<<<BSZ*CH, 256>>>();
    k_kv_tc<<<gkv, 256>>>();
    k_kvred<<<(BSZ*CH*CH)/256, 256>>>();
    k_nt<<<gnt, 256>>>(rw, 0L, pkv, (long)CH*CH, CH, pAbf);
    k_rv<<<BSZ, 256>>>(rw);
    k_denom<<<(BSZ*NPIX/2)/256, 256>>>();
    k_attn_tc<<<gproj, 256>>>(rb);
    k_conv_tc<<<gconv, 256, CONV_SMEM>>>(pattnbf, pwc1, c1b, (const float*)0, (float*)0, ph1bf, 0);
    k_conv_tc<<<gconv, 256, CONV_SMEM>>>(ph1bf, pwc2, c2b, x, out, (__nv_bfloat16*)0, 1);
}

// round 8
// speedup vs baseline: 6.2576x; 1.0950x over previous
#include <cuda_runtime.h>
#include <cuda_bf16.h>
#include <math.h>
#include <cstdint>

#define BSZ  8
#define CH   256
#define NPIX 4096
#define IMW  64
#define LDA  40   // bf16 elems per smem row (80B, conflict-free ldmatrix)
#define LDB3 264  // proj3 shared-B row width
#define GST  536  // conv B group stride (words); banks (24g+2p)%32 conflict-free

// ---------------- scratch (device globals; alloc-free) ----------------
__device__ float g_invQ[BSZ*NPIX];
__device__ float g_invK[BSZ*NPIX];
__device__ float g_ksum[BSZ*CH];
__device__ float g_vsum[BSZ*CH];
__device__ float g_kv[BSZ*CH*CH];
__device__ float g_kvp[BSZ*4*CH*CH];
__device__ float g_rv[BSZ*CH];
__device__ float g_denom[BSZ*NPIX];
// bf16 operands
__device__ __nv_bfloat16 g_xt[BSZ*NPIX*CH];     // x transposed [b][n][c]
__device__ __nv_bfloat16 g_Qbf[BSZ*CH*NPIX];    // Q [b][c][n]
__device__ __nv_bfloat16 g_Qt[BSZ*NPIX*CH];     // Q transposed [b][n][c]
__device__ __nv_bfloat16 g_Kbf[BSZ*CH*NPIX];
__device__ __nv_bfloat16 g_Vbf[BSZ*CH*NPIX];
__device__ __nv_bfloat16 g_Knbf[BSZ*CH*NPIX];
__device__ __nv_bfloat16 g_attnbf[BSZ*CH*NPIX];
__device__ __nv_bfloat16 g_h1bf[BSZ*CH*NPIX];
__device__ __nv_bfloat16 g_Abf[BSZ*CH*CH];
__device__ __nv_bfloat16 g_wqkv[3*CH*CH];   // [which][o][c]
__device__ __nv_bfloat16 g_wc1b[9*CH*CH];   // [t][o][c]
__device__ __nv_bfloat16 g_wc2b[9*CH*CH];

// ================= warp-MMA helpers =================
__device__ __forceinline__ uint32_t smem_u32(const void* p) {
    uint32_t a;
    asm("{ .reg .u64 t; cvta.to.shared.u64 t, %1; cvt.u32.u64 %0, t; }" : "=r"(a) : "l"(p));
    return a;
}
__device__ __forceinline__ void ldsm_x4(uint32_t (&r)[4], uint32_t addr) {
    asm volatile("ldmatrix.sync.aligned.m8n8.x4.shared.b16 {%0,%1,%2,%3}, [%4];"
        : "=r"(r[0]), "=r"(r[1]), "=r"(r[2]), "=r"(r[3]) : "r"(addr));
}
__device__ __forceinline__ void mma16816(float (&d)[4], const uint32_t (&a)[4],
                                         uint32_t b0, uint32_t b1) {
    asm volatile("mma.sync.aligned.m16n8k16.row.col.f32.bf16.bf16.f32 "
        "{%0,%1,%2,%3}, {%4,%5,%6,%7}, {%8,%9}, {%0,%1,%2,%3};"
        : "+f"(d[0]), "+f"(d[1]), "+f"(d[2]), "+f"(d[3])
        : "r"(a[0]), "r"(a[1]), "r"(a[2]), "r"(a[3]), "r"(b0), "r"(b1));
}

#define MMA_CHUNK_G(As, AW, Bs, BW, coff, acc, lane, wm, wn) do {                   \
    _Pragma("unroll")                                                               \
    for (int ks = 0; ks < 2; ks++) {                                                \
        uint32_t a_[2][4];                                                          \
        _Pragma("unroll")                                                           \
        for (int mi = 0; mi < 2; mi++)                                              \
            ldsm_x4(a_[mi], smem_u32(&(As)[((wm)*32 + mi*16 + ((lane)&15))*(AW)     \
                                          + ks*16 + ((lane)>>4)*8]));               \
        uint32_t b_[4][4];                                                          \
        _Pragma("unroll")                                                           \
        for (int ni = 0; ni < 4; ni++)                                              \
            ldsm_x4(b_[ni], smem_u32(&(Bs)[((wn)*64 + ni*16 + (((lane)>>4)&1)*8     \
                                            + ((lane)&7))*(BW)                      \
                                           + (coff) + ks*16 + (((lane)>>3)&1)*8])); \
        _Pragma("unroll")                                                           \
        for (int mi = 0; mi < 2; mi++) {                                            \
            _Pragma("unroll")                                                       \
            for (int ni = 0; ni < 4; ni++) {                                        \
                mma16816(acc[mi][ni*2],   a_[mi], b_[ni][0], b_[ni][1]);            \
                mma16816(acc[mi][ni*2+1], a_[mi], b_[ni][2], b_[ni][3]);            \
            }                                                                       \
        }                                                                           \
    }                                                                               \
} while (0)

#define ACC_ZERO(acc) do {                                                          \
    _Pragma("unroll")                                                               \
    for (int i_ = 0; i_ < 2; i_++) {                                                \
        _Pragma("unroll")                                                           \
        for (int j_ = 0; j_ < 8; j_++) {                                            \
            _Pragma("unroll")                                                       \
            for (int q_ = 0; q_ < 4; q_++) acc[i_][j_][q_] = 0.f;                   \
        }                                                                           \
    }                                                                               \
} while (0)

// ---------------- conversion / transpose kernels ----------------
__global__ __launch_bounds__(256) void k_cvtw(const float* __restrict__ q,
                                              const float* __restrict__ k,
                                              const float* __restrict__ v,
                                              __nv_bfloat16* __restrict__ dst)
{
    int i = blockIdx.x*256 + threadIdx.x;
    int which = i >> 16, r = i & 65535;
    const float* s = (which == 0) ? q : (which == 1) ? k : v;
    dst[i] = __float2bfloat16(s[r]);
}
__global__ __launch_bounds__(256) void k_cvt_wc(const float* __restrict__ w,
                                                __nv_bfloat16* __restrict__ dst)
{
    int i = blockIdx.x*256 + threadIdx.x;
    int c = i & 255, o = (i >> 8) & 255, t = i >> 16;
    dst[i] = __float2bfloat16(w[o*2304 + c*9 + t]);
}
// x f32 [b][c][n] -> xt bf16 [b][n][c], 64c x 32n tiles
__global__ __launch_bounds__(256) void k_t_x(const float* __restrict__ x)
{
    __shared__ __nv_bfloat16 sm[32][80];
    const int b = blockIdx.z, c0 = blockIdx.y*64, n0 = blockIdx.x*32;
    const float* in = x + ((size_t)b*CH + c0)*NPIX + n0;
    const int tid = threadIdx.x;
    #pragma unroll
    for (int i = 0; i < 8; i++) {
        int e = tid + i*256;
        int c = e >> 5, n = e & 31;
        sm[n][c] = __float2bfloat16(in[(size_t)c*NPIX + n]);
    }
    __syncthreads();
    int n = tid >> 3, seg = tid & 7;
    *(uint4*)(g_xt + ((size_t)b*NPIX + n0+n)*256 + c0 + seg*8) = *(uint4*)&sm[n][seg*8];
}
// Q bf16 [b][c][n] -> Qt bf16 [b][n][c], 64c x 64n tiles
__global__ __launch_bounds__(256) void k_t_q()
{
    __shared__ __nv_bfloat16 sm[64][80];
    const int b = blockIdx.z, c0 = blockIdx.y*64, n0 = blockIdx.x*64;
    const __nv_bfloat16* in = g_Qbf + ((size_t)b*CH + c0)*NPIX + n0;
    const int tid = threadIdx.x;
    #pragma unroll
    for (int i = 0; i < 8; i++) {
        int e = tid + i*256;
        int c = e >> 5, np = e & 31;
        __nv_bfloat162 v = *(const __nv_bfloat162*)(in + (size_t)c*NPIX + np*2);
        sm[np*2][c] = v.x;
        sm[np*2+1][c] = v.y;
    }
    __syncthreads();
    #pragma unroll
    for (int i = 0; i < 2; i++) {
        int e = tid + i*256;
        int n = e >> 3, seg = e & 7;
        *(uint4*)(g_Qt + ((size_t)b*NPIX + n0+n)*256 + c0 + seg*8) = *(uint4*)&sm[n][seg*8];
    }
}

// ---------------- fused QKV projection ----------------
#define P3_BS_BYTES (128*LDB3*2)
#define P3_SMEM     (P3_BS_BYTES + 2*128*LDA*2)
__global__ __launch_bounds__(256) void k_proj3(const __nv_bfloat16* __restrict__ w3,
                                               const float* __restrict__ qb,
                                               const float* __restrict__ kb,
                                               const float* __restrict__ vb,
                                               __nv_bfloat16* __restrict__ outQ,
                                               __nv_bfloat16* __restrict__ outK,
                                               __nv_bfloat16* __restrict__ outV)
{
    extern __shared__ __align__(16) char dsm[];
    __nv_bfloat16* Bs = (__nv_bfloat16*)dsm;                 // [128][LDB3]
    __nv_bfloat16* As = (__nv_bfloat16*)(dsm + P3_BS_BYTES); // [2][128][LDA]
    const int b  = blockIdx.z;
    const int o0 = blockIdx.y * 128;
    const int n0 = blockIdx.x * 128;
    const __nv_bfloat16* xtb = g_xt + (size_t)b*NPIX*CH;
    const int tid = threadIdx.x;
    const int wid = tid >> 5, lane = tid & 31;
    const int wm = wid & 3, wn = wid >> 2;

    // B tile fill: straight uint4 row copies from xt
    #pragma unroll
    for (int i = 0; i < 16; i++) {
        int e = tid + i*256;
        int n = e >> 5, seg = e & 31;
        *(uint4*)&Bs[n*LDB3 + seg*8] = *(const uint4*)(xtb + (size_t)(n0+n)*256 + seg*8);
    }

    float acc[2][8][4];
    const int r0 = lane >> 2, c2 = (lane & 3)*2;

    #pragma unroll
    for (int which = 0; which < 3; which++) {
        const __nv_bfloat16* w = w3 + (size_t)which*CH*CH;
        ACC_ZERO(acc);
        #pragma unroll
        for (int i = 0; i < 2; i++) {
            int e = tid + i*256;
            int o = e >> 2, cq = e & 3;
            *(uint4*)&As[(0*128 + o)*LDA + cq*8] = *(const uint4*)(w + (size_t)(o0+o)*CH + cq*8);
        }
        for (int kc = 0; kc < 8; kc++) {
            __syncthreads();
            int buf = kc & 1;
            if (kc + 1 < 8) {
                int cb = (kc + 1) * 32;
                #pragma unroll
                for (int i = 0; i < 2; i++) {
                    int e = tid + i*256;
                    int o = e >> 2, cq = e & 3;
                    *(uint4*)&As[((buf^1)*128 + o)*LDA + cq*8] =
                        *(const uint4*)(w + (size_t)(o0+o)*CH + cb + cq*8);
                }
            }
            MMA_CHUNK_G((As + buf*128*LDA), LDA, Bs, LDB3, kc*32, acc, lane, wm, wn);
        }
        const float* bias = (which == 0) ? qb : (which == 1) ? kb : vb;
        __nv_bfloat16* ob = ((which == 0) ? outQ : (which == 1) ? outK : outV)
                            + (size_t)b*CH*NPIX;
        #pragma unroll
        for (int mi = 0; mi < 2; mi++) {
            int o_lo = o0 + wm*32 + mi*16 + r0;
            int o_hi = o_lo + 8;
            float blo = bias[o_lo], bhi = bias[o_hi];
            #pragma unroll
            for (int nj = 0; nj < 8; nj++) {
                int n = n0 + wn*64 + nj*8 + c2;
                __nv_bfloat162 vlo, vhi;
                vlo.x = __float2bfloat16(acc[mi][nj][0] + blo);
                vlo.y = __float2bfloat16(acc[mi][nj][1] + blo);
                vhi.x = __float2bfloat16(acc[mi][nj][2] + bhi);
                vhi.y = __float2bfloat16(acc[mi][nj][3] + bhi);
                *(__nv_bfloat162*)(ob + (size_t)o_lo*NPIX + n) = vlo;
                *(__nv_bfloat162*)(ob + (size_t)o_hi*NPIX + n) = vhi;
            }
        }
    }
}

// ---------------- bf16 MMA kv GEMM, split-N=4 ----------------
__global__ __launch_bounds__(256) void k_kv_tc()
{
    __shared__ __align__(16) __nv_bfloat16 As[2][128][LDA];
    __shared__ __align__(16) __nv_bfloat16 Bs[2][128][LDA];
    const int bsp = blockIdx.z;
    const int b = bsp >> 2, sp = bsp & 3;
    const int k0 = blockIdx.y * 128;
    const int c0 = blockIdx.x * 128;
    const int nb = sp * 1024;
    const __nv_bfloat16* Kn = g_Knbf + (size_t)b*CH*NPIX;
    const __nv_bfloat16* Vb = g_Vbf  + (size_t)b*CH*NPIX;
    const int tid = threadIdx.x;
    const int wid = tid >> 5, lane = tid & 31;
    const int wm = wid & 3, wn = wid >> 2;

    float acc[2][8][4];
    ACC_ZERO(acc);

    #pragma unroll
    for (int i = 0; i < 16; i++) {
        int e = tid + i*256;
        int r = e >> 5, n = e & 31;
        As[0][r][n] = Kn[(size_t)(k0+r)*NPIX + nb + n];
        Bs[0][r][n] = Vb[(size_t)(c0+r)*NPIX + nb + n];
    }

    for (int kc = 0; kc < 32; kc++) {
        __syncthreads();
        int buf = kc & 1;
        if (kc + 1 < 32) {
            int nn = nb + (kc + 1) * 32;
            #pragma unroll
            for (int i = 0; i < 16; i++) {
                int e = tid + i*256;
                int r = e >> 5, n = e & 31;
                As[buf^1][r][n] = Kn[(size_t)(k0+r)*NPIX + nn + n];
                Bs[buf^1][r][n] = Vb[(size_t)(c0+r)*NPIX + nn + n];
            }
        }
        MMA_CHUNK_G(&As[buf][0][0], LDA, &Bs[buf][0][0], LDA, 0, acc, lane, wm, wn);
    }

    float* ob = g_kvp + (size_t)bsp*CH*CH;
    const int r0 = lane >> 2, c2 = (lane & 3)*2;
    #pragma unroll
    for (int mi = 0; mi < 2; mi++) {
        int k_lo = k0 + wm*32 + mi*16 + r0;
        int k_hi = k_lo + 8;
        #pragma unroll
        for (int nj = 0; nj < 8; nj++) {
            int c = c0 + wn*64 + nj*8 + c2;
            *(float2*)(ob + (size_t)k_lo*CH + c) = make_float2(acc[mi][nj][0], acc[mi][nj][1]);
            *(float2*)(ob + (size_t)k_hi*CH + c) = make_float2(acc[mi][nj][2], acc[mi][nj][3]);
        }
    }
}

__global__ __launch_bounds__(256) void k_kvred()
{
    int i = blockIdx.x*256 + threadIdx.x;
    int b = i >> 16, r = i & 65535;
    const float* p = g_kvp + (size_t)b*4*65536;
    g_kv[i] = (p[r] + p[65536 + r]) + (p[2*65536 + r] + p[3*65536 + r]);
}

// ---------------- bf16 MMA attn GEMM + epilogue ----------------
__global__ __launch_bounds__(256) void k_attn_tc(const float* __restrict__ rb)
{
    __shared__ __align__(16) __nv_bfloat16 As[2][128][LDA];
    __shared__ __align__(16) __nv_bfloat16 Bs[2][128][LDA];
    const int b  = blockIdx.z;
    const int o0 = blockIdx.y * 128;
    const int n0 = blockIdx.x * 128;
    const __nv_bfloat16* Am = g_Abf + (size_t)b*CH*CH;
    const __nv_bfloat16* Qt = g_Qt + (size_t)b*NPIX*CH;
    const int tid = threadIdx.x;
    const int wid = tid >> 5, lane = tid & 31;
    const int wm = wid & 3, wn = wid >> 2;

    float acc[2][8][4];
    ACC_ZERO(acc);

    #pragma unroll
    for (int i = 0; i < 2; i++) {
        int e = tid + i*256;
        int o = e >> 2, cq = e & 3;
        *(uint4*)&As[0][o][cq*8] = *(const uint4*)(Am + (size_t)(o0+o)*CH + cq*8);
    }
    #pragma unroll
    for (int i = 0; i < 2; i++) {
        int e = tid + i*256;
        int n = e >> 2, cq = e & 3;
        *(uint4*)&Bs[0][n][cq*8] = *(const uint4*)(Qt + (size_t)(n0+n)*256 + cq*8);
    }

    for (int kc = 0; kc < 8; kc++) {
        __syncthreads();
        int buf = kc & 1;
        if (kc + 1 < 8) {
            int cb = (kc + 1) * 32;
            #pragma unroll
            for (int i = 0; i < 2; i++) {
                int e = tid + i*256;
                int o = e >> 2, cq = e & 3;
                *(uint4*)&As[buf^1][o][cq*8] = *(const uint4*)(Am + (size_t)(o0+o)*CH + cb + cq*8);
            }
            #pragma unroll
            for (int i = 0; i < 2; i++) {
                int e = tid + i*256;
                int n = e >> 2, cq = e & 3;
                *(uint4*)&Bs[buf^1][n][cq*8] = *(const uint4*)(Qt + (size_t)(n0+n)*256 + cb + cq*8);
            }
        }
        MMA_CHUNK_G(&As[buf][0][0], LDA, &Bs[buf][0][0], LDA, 0, acc, lane, wm, wn);
    }

    __nv_bfloat16* ob = g_attnbf + (size_t)b*CH*NPIX;
    const int r0 = lane >> 2, c2 = (lane & 3)*2;
    #pragma unroll
    for (int mi = 0; mi < 2; mi++) {
        int o_lo = o0 + wm*32 + mi*16 + r0;
        int o_hi = o_lo + 8;
        float rvlo = g_rv[b*CH + o_lo], rvhi = g_rv[b*CH + o_hi];
        float rblo = rb[o_lo], rbhi = rb[o_hi];
        #pragma unroll
        for (int nj = 0; nj < 8; nj++) {
            int n = n0 + wn*64 + nj*8 + c2;
            float iq0 = g_invQ[b*NPIX + n],     dn0 = g_denom[b*NPIX + n];
            float iq1 = g_invQ[b*NPIX + n + 1], dn1 = g_denom[b*NPIX + n + 1];
            __nv_bfloat162 vlo, vhi;
            vlo.x = __float2bfloat16(fmaf(fmaf(iq0, acc[mi][nj][0], rvlo), dn0, rblo));
            vlo.y = __float2bfloat16(fmaf(fmaf(iq1, acc[mi][nj][1], rvlo), dn1, rblo));
            vhi.x = __float2bfloat16(fmaf(fmaf(iq0, acc[mi][nj][2], rvhi), dn0, rbhi));
            vhi.y = __float2bfloat16(fmaf(fmaf(iq1, acc[mi][nj][3], rvhi), dn1, rbhi));
            *(__nv_bfloat162*)(ob + (size_t)o_lo*NPIX + n) = vlo;
            *(__nv_bfloat162*)(ob + (size_t)o_hi*NPIX + n) = vhi;
        }
    }
}

// ---------------- bf16 MMA 3x3 conv: paired-plane layout, LDS.64 B reads ----------------
// plane q (c-pair, 0..15): group g = (q&3)+((q>>3)<<2), slot s = (q>>2)&1
// word addr = g*GST + pos*2 + s  (pos = row*66 + col)
#define CONV_BW_WORDS (8*GST)
#define CONV_AS_BYTES (2*128*LDA*2)
#define CONV_SMEM     (CONV_AS_BYTES + 2*CONV_BW_WORDS*4)

__device__ __forceinline__ void conv_fillB(uint32_t* __restrict__ Bw,
                                           const __nv_bfloat16* __restrict__ inb,
                                           int cbase, int pr0, int tid)
{
    #pragma unroll
    for (int it = 0; it < 2; it++) {
        int e = tid + it*256;
        int kw = e >> 5;
        int row = (e >> 3) & 3;
        int seg = e & 7;
        int g = (kw & 3) + ((kw >> 3) << 2);
        int s = (kw >> 2) & 1;
        int gr = pr0 - 1 + row;
        uint32_t* dst = Bw + g*GST + (row*66 + 1 + seg*8)*2 + s;
        if ((unsigned)gr < IMW) {
            const __nv_bfloat16* q = inb + (size_t)(cbase + kw*2)*NPIX + gr*IMW + seg*8;
            uint4 lo4 = *(const uint4*)q;
            uint4 hi4 = *(const uint4*)(q + NPIX);
            const unsigned short* ls = (const unsigned short*)&lo4;
            const unsigned short* hs = (const unsigned short*)&hi4;
            #pragma unroll
            for (int j = 0; j < 8; j++)
                dst[j*2] = (uint32_t)ls[j] | ((uint32_t)hs[j] << 16);
        } else {
            #pragma unroll
            for (int j = 0; j < 8; j++) dst[j*2] = 0u;
        }
    }
}

__global__ __launch_bounds__(256) void k_conv_tc(const __nv_bfloat16* __restrict__ in,
                                                 const __nv_bfloat16* __restrict__ wt,
                                                 const float* __restrict__ bias,
                                                 const float* __restrict__ xres,
                                                 float* __restrict__ out_f,
                                                 __nv_bfloat16* __restrict__ out_bf,
                                                 int fuse)
{
    extern __shared__ __align__(16) char dsm[];
    __nv_bfloat16* Asm = (__nv_bfloat16*)dsm;                 // [2][128][LDA]
    uint32_t* Bw0 = (uint32_t*)(dsm + CONV_AS_BYTES);
    uint32_t* Bw1 = Bw0 + CONV_BW_WORDS;
    const int b   = blockIdx.z;
    const int o0  = blockIdx.y * 128;
    const int pr0 = blockIdx.x * 2;
    const __nv_bfloat16* inb = in + (size_t)b*CH*NPIX;
    const int tid = threadIdx.x;
    const int wid = tid >> 5, lane = tid & 31;
    const int wm = wid & 3, wn = wid >> 2;

    float acc[2][8][4];
    ACC_ZERO(acc);

    // halo columns always zero — write once, both buffers
    if (tid < 128) {
        int kw = tid >> 3;
        int row = (tid >> 1) & 3;
        int side = tid & 1;
        int g = (kw & 3) + ((kw >> 3) << 2);
        int s = (kw >> 2) & 1;
        int off = g*GST + (row*66 + side*65)*2 + s;
        Bw0[off] = 0u;
        Bw1[off] = 0u;
    }
    conv_fillB(Bw0, inb, 0, pr0, tid);
    #pragma unroll
    for (int i = 0; i < 2; i++) {
        int e = tid + i*256;
        int o = e >> 2, cq = e & 3;
        *(uint4*)(Asm + (size_t)o*LDA + cq*8) = *(const uint4*)(wt + ((size_t)o0 + o)*256 + cq*8);
    }
    __syncthreads();

    int s = 0;
    for (int cb = 0; cb < 8; cb++) {
        uint32_t* Bcur = (cb & 1) ? Bw1 : Bw0;
        uint32_t* Bnxt = (cb & 1) ? Bw0 : Bw1;
        for (int t = 0; t < 9; t++, s++) {
            const int pa = s & 1;
            if (s + 1 < 72) {
                int tn = (t + 1 == 9) ? 0 : t + 1;
                int cbn = (t + 1 == 9) ? (cb + 1) : cb;
                const __nv_bfloat16* wsrc = wt + ((size_t)tn*256 + o0)*256 + cbn*32;
                #pragma unroll
                for (int i = 0; i < 2; i++) {
                    int e = tid + i*256;
                    int o = e >> 2, cq = e & 3;
                    *(uint4*)(Asm + ((size_t)(pa^1)*128 + o)*LDA + cq*8) =
                        *(const uint4*)(wsrc + (size_t)o*256 + cq*8);
                }
            }
            if (t == 0 && cb < 7)
                conv_fillB(Bnxt, inb, (cb + 1) * 32, pr0, tid);
            {
                const int dy = t / 3 - 1, dx = t % 3 - 1;
                const int pos0 = (1 + wn + dy) * 66 + 1 + dx;
                #pragma unroll
                for (int ks = 0; ks < 2; ks++) {
                    uint32_t a0[4], a1[4];
                    ldsm_x4(a0, smem_u32(Asm + ((size_t)pa*128 + wm*32 + (lane&15))*LDA
                                         + ks*16 + (lane>>4)*8));
                    ldsm_x4(a1, smem_u32(Asm + ((size_t)pa*128 + wm*32 + 16 + (lane&15))*LDA
                                         + ks*16 + (lane>>4)*8));
                    const uint32_t* bp = Bcur + ((lane&3) + ks*4)*GST
                                       + (pos0 + (lane>>2))*2;
                    #pragma unroll
                    for (int f = 0; f < 8; f++) {
                        uint2 bb = *(const uint2*)(bp + f*16);
                        mma16816(acc[0][f], a0, bb.x, bb.y);
                        mma16816(acc[1][f], a1, bb.x, bb.y);
                    }
                }
            }
            __syncthreads();
        }
    }

    const int r0 = lane >> 2, c2 = (lane & 3)*2;
    const int pxbase = pr0*64;
    if (fuse) {
        const float* xb = xres + (size_t)b*CH*NPIX;
        float* ob = out_f + (size_t)b*CH*NPIX;
        #pragma unroll
        for (int mi = 0; mi < 2; mi++) {
            int o_lo = o0 + wm*32 + mi*16 + r0;
            int o_hi = o_lo + 8;
            float blo = bias[o_lo], bhi = bias[o_hi];
            #pragma unroll
            for (int f = 0; f < 8; f++) {
                int px = pxbase + wn*64 + f*8 + c2;
                float a0 = acc[mi][f][0] + blo, a1 = acc[mi][f][1] + blo;
                float a2 = acc[mi][f][2] + bhi, a3 = acc[mi][f][3] + bhi;
                float2 xlo = *(const float2*)(xb + (size_t)o_lo*NPIX + px);
                float2 xhi = *(const float2*)(xb + (size_t)o_hi*NPIX + px);
                a0 = fmaf(a0, xlo.x, xlo.x);
                a1 = fmaf(a1, xlo.y, xlo.y);
                a2 = fmaf(a2, xhi.x, xhi.x);
                a3 = fmaf(a3, xhi.y, xhi.y);
                *(float2*)(ob + (size_t)o_lo*NPIX + px) = make_float2(a0, a1);
                *(float2*)(ob + (size_t)o_hi*NPIX + px) = make_float2(a2, a3);
            }
        }
    } else {
        __nv_bfloat16* ob = out_bf + (size_t)b*CH*NPIX;
        #pragma unroll
        for (int mi = 0; mi < 2; mi++) {
            int o_lo = o0 + wm*32 + mi*16 + r0;
            int o_hi = o_lo + 8;
            float blo = bias[o_lo], bhi = bias[o_hi];
            #pragma unroll
            for (int f = 0; f < 8; f++) {
                int px = pxbase + wn*64 + f*8 + c2;
                __nv_bfloat162 vlo, vhi;
                vlo.x = __float2bfloat16(acc[mi][f][0] + blo);
                vlo.y = __float2bfloat16(acc[mi][f][1] + blo);
                vhi.x = __float2bfloat16(acc[mi][f][2] + bhi);
                vhi.y = __float2bfloat16(acc[mi][f][3] + bhi);
                *(__nv_bfloat162*)(ob + (size_t)o_lo*NPIX + px) = vlo;
                *(__nv_bfloat162*)(ob + (size_t)o_hi*NPIX + px) = vhi;
            }
        }
    }
}

// ---------------- invK (strided bf16, 2 tokens/thread) ----------------
__global__ __launch_bounds__(256) void k_normsK()
{
    int idx2 = blockIdx.x*256 + threadIdx.x;
    int b = idx2 >> 11, n = (idx2 & 2047) * 2;
    const __nv_bfloat16* Kp = g_Kbf + (size_t)b*CH*NPIX + n;
    float sk0 = 0.f, sk1 = 0.f;
    #pragma unroll 16
    for (int c = 0; c < CH; c++) {
        __nv_bfloat162 k = *(const __nv_bfloat162*)(Kp + (size_t)c*NPIX);
        float kx = __bfloat162float(k.x), ky = __bfloat162float(k.y);
        sk0 = fmaf(kx, kx, sk0);
        sk1 = fmaf(ky, ky, sk1);
    }
    int o = b*NPIX + n;
    g_invK[o]   = 1.0f / sqrtf(sk0);
    g_invK[o+1] = 1.0f / sqrtf(sk1);
}

// ---------------- ksum / vsum; emits normalized Kn bf16 ----------------
__global__ __launch_bounds__(256) void k_colsums()
{
    int bc = blockIdx.x;
    int b = bc >> 8;
    const __nv_bfloat16* Kp = g_Kbf + (size_t)bc*NPIX;
    const __nv_bfloat16* Vp = g_Vbf + (size_t)bc*NPIX;
    const float* ik = g_invK + (size_t)b*NPIX;
    __nv_bfloat16* knp = g_Knbf + (size_t)bc*NPIX;
    int tid = threadIdx.x;
    float sk = 0.f, sv = 0.f;
    #pragma unroll
    for (int it = 0; it < 2; it++) {
        int base = (tid + it*256) * 8;
        uint4 kv4 = *(const uint4*)(Kp + base);
        uint4 vv4 = *(const uint4*)(Vp + base);
        float4 ika = *(const float4*)(ik + base);
        float4 ikb = *(const float4*)(ik + base + 4);
        const __nv_bfloat16* kk = (const __nv_bfloat16*)&kv4;
        const __nv_bfloat16* vv = (const __nv_bfloat16*)&vv4;
        float iks[8] = {ika.x, ika.y, ika.z, ika.w, ikb.x, ikb.y, ikb.z, ikb.w};
        unsigned short outw[8];
        #pragma unroll
        for (int j = 0; j < 8; j++) {
            float kn = __bfloat162float(kk[j]) * iks[j];
            __nv_bfloat16 knb = __float2bfloat16(kn);
            outw[j] = __bfloat16_as_ushort(knb);
            sk += kn;
            sv += __bfloat162float(vv[j]);
        }
        *(uint4*)(knp + base) = *(uint4*)outw;
    }
    __shared__ float rk[256], rv[256];
    rk[tid] = sk; rv[tid] = sv;
    __syncthreads();
    for (int s = 128; s > 0; s >>= 1) {
        if (tid < s) { rk[tid] += rk[tid+s]; rv[tid] += rv[tid+s]; }
        __syncthreads();
    }
    if (tid == 0) { g_ksum[bc] = rk[0]; g_vsum[bc] = rv[0]; }
}

// ---------------- A = rw @ kv^T (fp32 in, bf16 out) ----------------
__global__ __launch_bounds__(256) void k_nt(const float* __restrict__ Ap, long strideA,
                                            const float* __restrict__ Bp, long strideB,
                                            int L, __nv_bfloat16* __restrict__ out)
{
    __shared__ float As[32][65];
    __shared__ float Bs[32][65];
    const int b = blockIdx.z;
    const int i0 = blockIdx.y*64, j0 = blockIdx.x*64;
    const float* A = Ap + (size_t)b*strideA;
    const float* B = Bp + (size_t)b*strideB;
    const int tid = threadIdx.x;
    const int ty = tid >> 4, tx = tid & 15;
    float acc[4][4];
    #pragma unroll
    for (int i = 0; i < 4; i++) {
        #pragma unroll
        for (int j = 0; j < 4; j++) acc[i][j] = 0.f;
    }

    for (int l0 = 0; l0 < L; l0 += 32) {
        #pragma unroll
        for (int r = 0; r < 8; r++) {
            int e = tid + r*256;
            int ii = e >> 5, ll = e & 31;
            As[ll][ii] = A[(size_t)(i0+ii)*L + l0 + ll];
        }
        #pragma unroll
        for (int r = 0; r < 8; r++) {
            int e = tid + r*256;
            int jj = e >> 5, ll = e & 31;
            Bs[ll][jj] = B[(size_t)(j0+jj)*L + l0 + ll];
        }
        __syncthreads();
        #pragma unroll
        for (int ll = 0; ll < 32; ll++) {
            float ar[4], br[4];
            #pragma unroll
            for (int i = 0; i < 4; i++) ar[i] = As[ll][ty*4+i];
            #pragma unroll
            for (int j = 0; j < 4; j++) br[j] = Bs[ll][tx*4+j];
            #pragma unroll
            for (int i = 0; i < 4; i++) {
                #pragma unroll
                for (int j = 0; j < 4; j++)
                    acc[i][j] = fmaf(ar[i], br[j], acc[i][j]);
            }
        }
        __syncthreads();
    }
    __nv_bfloat16* ob = out + (size_t)b*CH*CH;
    #pragma unroll
    for (int i = 0; i < 4; i++) {
        #pragma unroll
        for (int j = 0; j < 4; j++)
            ob[(size_t)(i0+ty*4+i)*CH + j0 + tx*4 + j] = __float2bfloat16(acc[i][j]);
    }
}

// ---------------- rv[b,o] = rw @ vsum ----------------
__global__ __launch_bounds__(256) void k_rv(const float* __restrict__ rw)
{
    int b = blockIdx.x, o = threadIdx.x;
    __shared__ float vs[256];
    vs[o] = g_vsum[b*CH + o];
    __syncthreads();
    float s = 0.f;
    const float* rp = rw + (size_t)o*CH;
    #pragma unroll 8
    for (int c = 0; c < CH; c++) s = fmaf(rp[c], vs[c], s);
    g_rv[b*CH + o] = s;
}

// ---------------- fused invQ + denom (warp per token, Qt rows) ----------------
__global__ __launch_bounds__(256) void k_qstats()
{
    __shared__ float ks[256];
    const int tid = threadIdx.x, lane = tid & 31, wid = tid >> 5;
    const int b = blockIdx.x >> 7;          // 128 blocks per batch
    ks[tid] = g_ksum[b*CH + tid];
    __syncthreads();
    const int t0 = blockIdx.x*32 + wid*4;   // global token index (includes b)
    #pragma unroll
    for (int j = 0; j < 4; j++) {
        int t = t0 + j;
        uint4 v = *(const uint4*)(g_Qt + (size_t)t*256 + lane*8);
        const __nv_bfloat16* qq = (const __nv_bfloat16*)&v;
        float sq = 0.f, dt = 0.f;
        #pragma unroll
        for (int k = 0; k < 8; k++) {
            float f = __bfloat162float(qq[k]);
            sq = fmaf(f, f, sq);
            dt = fmaf(f, ks[lane*8 + k], dt);
        }
        #pragma unroll
        for (int m = 16; m > 0; m >>= 1) {
            sq += __shfl_xor_sync(0xffffffffu, sq, m);
            dt += __shfl_xor_sync(0xffffffffu, dt, m);
        }
        if (lane == 0) {
            float iq = 1.0f / sqrtf(sq);
            g_invQ[t] = iq;
            g_denom[t] = 1.0f / (4096.0f + dt*iq + 1e-6f);
        }
    }
}

// ---------------- launcher ----------------
extern "C" void kernel_launch(void* const* d_in, const int* in_sizes, int n_in,
                              void* d_out, int out_size)
{
    (void)in_sizes; (void)n_in; (void)out_size;
    const float* x   = (const float*)d_in[0];
    const float* qw  = (const float*)d_in[1];
    const float* qb  = (const float*)d_in[2];
    const float* kw  = (const float*)d_in[3];
    const float* kb  = (const float*)d_in[4];
    const float* vw  = (const float*)d_in[5];
    const float* vb  = (const float*)d_in[6];
    const float* rw  = (const float*)d_in[7];
    const float* rb  = (const float*)d_in[8];
    const float* c1w = (const float*)d_in[9];
    const float* c1b = (const float*)d_in[10];
    const float* c2w = (const float*)d_in[11];
    const float* c2b = (const float*)d_in[12];
    float* out = (float*)d_out;

    float* pkv;
    __nv_bfloat16 *pQbf, *pKbf, *pVbf, *pattnbf, *ph1bf, *pAbf, *pwqkv, *pwc1, *pwc2;
    cudaGetSymbolAddress((void**)&pkv,    g_kv);
    cudaGetSymbolAddress((void**)&pQbf,   g_Qbf);
    cudaGetSymbolAddress((void**)&pKbf,   g_Kbf);
    cudaGetSymbolAddress((void**)&pVbf,   g_Vbf);
    cudaGetSymbolAddress((void**)&pattnbf,g_attnbf);
    cudaGetSymbolAddress((void**)&ph1bf,  g_h1bf);
    cudaGetSymbolAddress((void**)&pAbf,   g_Abf);
    cudaGetSymbolAddress((void**)&pwqkv,  g_wqkv);
    cudaGetSymbolAddress((void**)&pwc1,   g_wc1b);
    cudaGetSymbolAddress((void**)&pwc2,   g_wc2b);

    static int attr_set = 0;
    if (!attr_set) {
        cudaFuncSetAttribute(k_proj3,   cudaFuncAttributeMaxDynamicSharedMemorySize, P3_SMEM);
        cudaFuncSetAttribute(k_conv_tc, cudaFuncAttributeMaxDynamicSharedMemorySize, CONV_SMEM);
        attr_set = 1;
    }

    dim3 gproj(32, 2, BSZ);
    dim3 gkv(2, 2, BSZ*4);
    dim3 gnt(4, 4, BSZ);
    dim3 gconv(32, 2, BSZ);

    k_t_x<<<dim3(128, 4, BSZ), 256>>>(x);
    k_cvtw<<<(3*CH*CH)/256, 256>>>(qw, kw, vw, pwqkv);
    k_cvt_wc<<<(9*CH*CH)/256, 256>>>(c1w, pwc1);
    k_cvt_wc<<<(9*CH*CH)/256, 256>>>(c2w, pwc2);

    k_proj3<<<gproj, 256, P3_SMEM>>>(pwqkv, qb, kb, vb, pQbf, pKbf, pVbf);
    k_t_q<<<dim3(64, 4, BSZ), 256>>>();
    k_normsK<<<(BSZ*NPIX/2)/256, 256>>>();
    k_colsums<<<BSZ*CH, 256>>>();
    k_kv_tc<<<gkv, 256>>>();
    k_kvred<<<(BSZ*CH*CH)/256, 256>>>();
    k_nt<<<gnt, 256>>>(rw, 0L, pkv, (long)CH*CH, CH, pAbf);
    k_rv<<<BSZ, 256>>>(rw);
    k_qstats<<<(BSZ*NPIX)/32, 256>>>();
    k_attn_tc<<<gproj, 256>>>(rb);
    k_conv_tc<<<gconv, 256, CONV_SMEM>>>(pattnbf, pwc1, c1b, (const float*)0, (float*)0, ph1bf, 0);
    k_conv_tc<<<gconv, 256, CONV_SMEM>>>(ph1bf, pwc2, c2b, x, out, (__nv_bfloat16*)0, 1);
}

// round 9
// speedup vs baseline: 6.3635x; 1.0169x over previous
#include <cuda_runtime.h>
#include <cuda_bf16.h>
#include <math.h>
#include <cstdint>

#define BSZ  8
#define CH   256
#define NPIX 4096
#define IMW  64
#define LDA  40   // bf16 elems per smem row (80B, conflict-free ldmatrix)
#define LDB3 264  // proj3 shared-B row width
#define GST  536  // conv B group stride (words); banks (24g+2p)%32 conflict-free

// ---------------- scratch (device globals; alloc-free) ----------------
__device__ float g_invQ[BSZ*NPIX];
__device__ float g_invK[BSZ*NPIX];
__device__ float g_ksum[BSZ*CH];
__device__ float g_vsum[BSZ*CH];
__device__ float g_kv[BSZ*CH*CH];
__device__ float g_kvp[BSZ*4*CH*CH];
__device__ float g_rv[BSZ*CH];
__device__ float g_denom[BSZ*NPIX];
// bf16 operands
__device__ __nv_bfloat16 g_xt[BSZ*NPIX*CH];     // x transposed [b][n][c]
__device__ __nv_bfloat16 g_Qbf[BSZ*CH*NPIX];    // Q [b][c][n]
__device__ __nv_bfloat16 g_Qt[BSZ*NPIX*CH];     // Q transposed [b][n][c]
__device__ __nv_bfloat16 g_Kbf[BSZ*CH*NPIX];
__device__ __nv_bfloat16 g_Vbf[BSZ*CH*NPIX];
__device__ __nv_bfloat16 g_Knbf[BSZ*CH*NPIX];
__device__ __nv_bfloat16 g_attnbf[BSZ*CH*NPIX];
__device__ __nv_bfloat16 g_h1bf[BSZ*CH*NPIX];
__device__ __nv_bfloat16 g_Abf[BSZ*CH*CH];
__device__ __nv_bfloat16 g_wqkv[3*CH*CH];   // [which][o][c]
__device__ __nv_bfloat16 g_wc1b[9*CH*CH];   // [t][o][c]
__device__ __nv_bfloat16 g_wc2b[9*CH*CH];

// ================= warp-MMA helpers =================
__device__ __forceinline__ uint32_t smem_u32(const void* p) {
    uint32_t a;
    asm("{ .reg .u64 t; cvta.to.shared.u64 t, %1; cvt.u32.u64 %0, t; }" : "=r"(a) : "l"(p));
    return a;
}
__device__ __forceinline__ void ldsm_x4(uint32_t (&r)[4], uint32_t addr) {
    asm volatile("ldmatrix.sync.aligned.m8n8.x4.shared.b16 {%0,%1,%2,%3}, [%4];"
        : "=r"(r[0]), "=r"(r[1]), "=r"(r[2]), "=r"(r[3]) : "r"(addr));
}
__device__ __forceinline__ void mma16816(float (&d)[4], const uint32_t (&a)[4],
                                         uint32_t b0, uint32_t b1) {
    asm volatile("mma.sync.aligned.m16n8k16.row.col.f32.bf16.bf16.f32 "
        "{%0,%1,%2,%3}, {%4,%5,%6,%7}, {%8,%9}, {%0,%1,%2,%3};"
        : "+f"(d[0]), "+f"(d[1]), "+f"(d[2]), "+f"(d[3])
        : "r"(a[0]), "r"(a[1]), "r"(a[2]), "r"(a[3]), "r"(b0), "r"(b1));
}

#define MMA_CHUNK_G(As, AW, Bs, BW, coff, acc, lane, wm, wn) do {                   \
    _Pragma("unroll")                                                               \
    for (int ks = 0; ks < 2; ks++) {                                                \
        uint32_t a_[2][4];                                                          \
        _Pragma("unroll")                                                           \
        for (int mi = 0; mi < 2; mi++)                                              \
            ldsm_x4(a_[mi], smem_u32(&(As)[((wm)*32 + mi*16 + ((lane)&15))*(AW)     \
                                          + ks*16 + ((lane)>>4)*8]));               \
        uint32_t b_[4][4];                                                          \
        _Pragma("unroll")                                                           \
        for (int ni = 0; ni < 4; ni++)                                              \
            ldsm_x4(b_[ni], smem_u32(&(Bs)[((wn)*64 + ni*16 + (((lane)>>4)&1)*8     \
                                            + ((lane)&7))*(BW)                      \
                                           + (coff) + ks*16 + (((lane)>>3)&1)*8])); \
        _Pragma("unroll")                                                           \
        for (int mi = 0; mi < 2; mi++) {                                            \
            _Pragma("unroll")                                                       \
            for (int ni = 0; ni < 4; ni++) {                                        \
                mma16816(acc[mi][ni*2],   a_[mi], b_[ni][0], b_[ni][1]);            \
                mma16816(acc[mi][ni*2+1], a_[mi], b_[ni][2], b_[ni][3]);            \
            }                                                                       \
        }                                                                           \
    }                                                                               \
} while (0)

#define ACC_ZERO(acc) do {                                                          \
    _Pragma("unroll")                                                               \
    for (int i_ = 0; i_ < 2; i_++) {                                                \
        _Pragma("unroll")                                                           \
        for (int j_ = 0; j_ < 8; j_++) {                                            \
            _Pragma("unroll")                                                       \
            for (int q_ = 0; q_ < 4; q_++) acc[i_][j_][q_] = 0.f;                   \
        }                                                                           \
    }                                                                               \
} while (0)

// ---------------- conversion / transpose kernels ----------------
__global__ __launch_bounds__(256) void k_cvtw(const float* __restrict__ q,
                                              const float* __restrict__ k,
                                              const float* __restrict__ v,
                                              __nv_bfloat16* __restrict__ dst)
{
    int i = blockIdx.x*256 + threadIdx.x;
    int which = i >> 16, r = i & 65535;
    const float* s = (which == 0) ? q : (which == 1) ? k : v;
    dst[i] = __float2bfloat16(s[r]);
}
__global__ __launch_bounds__(256) void k_cvt_wc(const float* __restrict__ w,
                                                __nv_bfloat16* __restrict__ dst)
{
    int i = blockIdx.x*256 + threadIdx.x;
    int c = i & 255, o = (i >> 8) & 255, t = i >> 16;
    dst[i] = __float2bfloat16(w[o*2304 + c*9 + t]);
}
// x f32 [b][c][n] -> xt bf16 [b][n][c]
__global__ __launch_bounds__(256) void k_t_x(const float* __restrict__ x)
{
    __shared__ __nv_bfloat16 sm[32][80];
    const int b = blockIdx.z, c0 = blockIdx.y*64, n0 = blockIdx.x*32;
    const float* in = x + ((size_t)b*CH + c0)*NPIX + n0;
    const int tid = threadIdx.x;
    #pragma unroll
    for (int i = 0; i < 8; i++) {
        int e = tid + i*256;
        int c = e >> 5, n = e & 31;
        sm[n][c] = __float2bfloat16(in[(size_t)c*NPIX + n]);
    }
    __syncthreads();
    int n = tid >> 3, seg = tid & 7;
    *(uint4*)(g_xt + ((size_t)b*NPIX + n0+n)*256 + c0 + seg*8) = *(uint4*)&sm[n][seg*8];
}
// Q bf16 [b][c][n] -> Qt bf16 [b][n][c]
__global__ __launch_bounds__(256) void k_t_q()
{
    __shared__ __nv_bfloat16 sm[64][80];
    const int b = blockIdx.z, c0 = blockIdx.y*64, n0 = blockIdx.x*64;
    const __nv_bfloat16* in = g_Qbf + ((size_t)b*CH + c0)*NPIX + n0;
    const int tid = threadIdx.x;
    #pragma unroll
    for (int i = 0; i < 8; i++) {
        int e = tid + i*256;
        int c = e >> 5, np = e & 31;
        __nv_bfloat162 v = *(const __nv_bfloat162*)(in + (size_t)c*NPIX + np*2);
        sm[np*2][c] = v.x;
        sm[np*2+1][c] = v.y;
    }
    __syncthreads();
    #pragma unroll
    for (int i = 0; i < 2; i++) {
        int e = tid + i*256;
        int n = e >> 3, seg = e & 7;
        *(uint4*)(g_Qt + ((size_t)b*NPIX + n0+n)*256 + c0 + seg*8) = *(uint4*)&sm[n][seg*8];
    }
}

// ---------------- fused QKV projection ----------------
#define P3_BS_BYTES (128*LDB3*2)
#define P3_SMEM     (P3_BS_BYTES + 2*128*LDA*2)
__global__ __launch_bounds__(256) void k_proj3(const __nv_bfloat16* __restrict__ w3,
                                               const float* __restrict__ qb,
                                               const float* __restrict__ kb,
                                               const float* __restrict__ vb,
                                               __nv_bfloat16* __restrict__ outQ,
                                               __nv_bfloat16* __restrict__ outK,
                                               __nv_bfloat16* __restrict__ outV)
{
    extern __shared__ __align__(16) char dsm[];
    __nv_bfloat16* Bs = (__nv_bfloat16*)dsm;                 // [128][LDB3]
    __nv_bfloat16* As = (__nv_bfloat16*)(dsm + P3_BS_BYTES); // [2][128][LDA]
    const int b  = blockIdx.z;
    const int o0 = blockIdx.y * 128;
    const int n0 = blockIdx.x * 128;
    const __nv_bfloat16* xtb = g_xt + (size_t)b*NPIX*CH;
    const int tid = threadIdx.x;
    const int wid = tid >> 5, lane = tid & 31;
    const int wm = wid & 3, wn = wid >> 2;

    #pragma unroll
    for (int i = 0; i < 16; i++) {
        int e = tid + i*256;
        int n = e >> 5, seg = e & 31;
        *(uint4*)&Bs[n*LDB3 + seg*8] = *(const uint4*)(xtb + (size_t)(n0+n)*256 + seg*8);
    }

    float acc[2][8][4];
    const int r0 = lane >> 2, c2 = (lane & 3)*2;

    #pragma unroll
    for (int which = 0; which < 3; which++) {
        const __nv_bfloat16* w = w3 + (size_t)which*CH*CH;
        ACC_ZERO(acc);
        #pragma unroll
        for (int i = 0; i < 2; i++) {
            int e = tid + i*256;
            int o = e >> 2, cq = e & 3;
            *(uint4*)&As[(0*128 + o)*LDA + cq*8] = *(const uint4*)(w + (size_t)(o0+o)*CH + cq*8);
        }
        for (int kc = 0; kc < 8; kc++) {
            __syncthreads();
            int buf = kc & 1;
            if (kc + 1 < 8) {
                int cb = (kc + 1) * 32;
                #pragma unroll
                for (int i = 0; i < 2; i++) {
                    int e = tid + i*256;
                    int o = e >> 2, cq = e & 3;
                    *(uint4*)&As[((buf^1)*128 + o)*LDA + cq*8] =
                        *(const uint4*)(w + (size_t)(o0+o)*CH + cb + cq*8);
                }
            }
            MMA_CHUNK_G((As + buf*128*LDA), LDA, Bs, LDB3, kc*32, acc, lane, wm, wn);
        }
        const float* bias = (which == 0) ? qb : (which == 1) ? kb : vb;
        __nv_bfloat16* ob = ((which == 0) ? outQ : (which == 1) ? outK : outV)
                            + (size_t)b*CH*NPIX;
        #pragma unroll
        for (int mi = 0; mi < 2; mi++) {
            int o_lo = o0 + wm*32 + mi*16 + r0;
            int o_hi = o_lo + 8;
            float blo = bias[o_lo], bhi = bias[o_hi];
            #pragma unroll
            for (int nj = 0; nj < 8; nj++) {
                int n = n0 + wn*64 + nj*8 + c2;
                __nv_bfloat162 vlo, vhi;
                vlo.x = __float2bfloat16(acc[mi][nj][0] + blo);
                vlo.y = __float2bfloat16(acc[mi][nj][1] + blo);
                vhi.x = __float2bfloat16(acc[mi][nj][2] + bhi);
                vhi.y = __float2bfloat16(acc[mi][nj][3] + bhi);
                *(__nv_bfloat162*)(ob + (size_t)o_lo*NPIX + n) = vlo;
                *(__nv_bfloat162*)(ob + (size_t)o_hi*NPIX + n) = vhi;
            }
        }
    }
}

// ---------------- bf16 MMA kv GEMM, split-N=4 ----------------
__global__ __launch_bounds__(256) void k_kv_tc()
{
    __shared__ __align__(16) __nv_bfloat16 As[2][128][LDA];
    __shared__ __align__(16) __nv_bfloat16 Bs[2][128][LDA];
    const int bsp = blockIdx.z;
    const int b = bsp >> 2, sp = bsp & 3;
    const int k0 = blockIdx.y * 128;
    const int c0 = blockIdx.x * 128;
    const int nb = sp * 1024;
    const __nv_bfloat16* Kn = g_Knbf + (size_t)b*CH*NPIX;
    const __nv_bfloat16* Vb = g_Vbf  + (size_t)b*CH*NPIX;
    const int tid = threadIdx.x;
    const int wid = tid >> 5, lane = tid & 31;
    const int wm = wid & 3, wn = wid >> 2;

    float acc[2][8][4];
    ACC_ZERO(acc);

    #pragma unroll
    for (int i = 0; i < 16; i++) {
        int e = tid + i*256;
        int r = e >> 5, n = e & 31;
        As[0][r][n] = Kn[(size_t)(k0+r)*NPIX + nb + n];
        Bs[0][r][n] = Vb[(size_t)(c0+r)*NPIX + nb + n];
    }

    for (int kc = 0; kc < 32; kc++) {
        __syncthreads();
        int buf = kc & 1;
        if (kc + 1 < 32) {
            int nn = nb + (kc + 1) * 32;
            #pragma unroll
            for (int i = 0; i < 16; i++) {
                int e = tid + i*256;
                int r = e >> 5, n = e & 31;
                As[buf^1][r][n] = Kn[(size_t)(k0+r)*NPIX + nn + n];
                Bs[buf^1][r][n] = Vb[(size_t)(c0+r)*NPIX + nn + n];
            }
        }
        MMA_CHUNK_G(&As[buf][0][0], LDA, &Bs[buf][0][0], LDA, 0, acc, lane, wm, wn);
    }

    float* ob = g_kvp + (size_t)bsp*CH*CH;
    const int r0 = lane >> 2, c2 = (lane & 3)*2;
    #pragma unroll
    for (int mi = 0; mi < 2; mi++) {
        int k_lo = k0 + wm*32 + mi*16 + r0;
        int k_hi = k_lo + 8;
        #pragma unroll
        for (int nj = 0; nj < 8; nj++) {
            int c = c0 + wn*64 + nj*8 + c2;
            *(float2*)(ob + (size_t)k_lo*CH + c) = make_float2(acc[mi][nj][0], acc[mi][nj][1]);
            *(float2*)(ob + (size_t)k_hi*CH + c) = make_float2(acc[mi][nj][2], acc[mi][nj][3]);
        }
    }
}

__global__ __launch_bounds__(256) void k_kvred()
{
    int i = blockIdx.x*256 + threadIdx.x;
    int b = i >> 16, r = i & 65535;
    const float* p = g_kvp + (size_t)b*4*65536;
    g_kv[i] = (p[r] + p[65536 + r]) + (p[2*65536 + r] + p[3*65536 + r]);
}

// ---------------- bf16 MMA attn GEMM + epilogue ----------------
__global__ __launch_bounds__(256) void k_attn_tc(const float* __restrict__ rb)
{
    __shared__ __align__(16) __nv_bfloat16 As[2][128][LDA];
    __shared__ __align__(16) __nv_bfloat16 Bs[2][128][LDA];
    const int b  = blockIdx.z;
    const int o0 = blockIdx.y * 128;
    const int n0 = blockIdx.x * 128;
    const __nv_bfloat16* Am = g_Abf + (size_t)b*CH*CH;
    const __nv_bfloat16* Qt = g_Qt + (size_t)b*NPIX*CH;
    const int tid = threadIdx.x;
    const int wid = tid >> 5, lane = tid & 31;
    const int wm = wid & 3, wn = wid >> 2;

    float acc[2][8][4];
    ACC_ZERO(acc);

    #pragma unroll
    for (int i = 0; i < 2; i++) {
        int e = tid + i*256;
        int o = e >> 2, cq = e & 3;
        *(uint4*)&As[0][o][cq*8] = *(const uint4*)(Am + (size_t)(o0+o)*CH + cq*8);
    }
    #pragma unroll
    for (int i = 0; i < 2; i++) {
        int e = tid + i*256;
        int n = e >> 2, cq = e & 3;
        *(uint4*)&Bs[0][n][cq*8] = *(const uint4*)(Qt + (size_t)(n0+n)*256 + cq*8);
    }

    for (int kc = 0; kc < 8; kc++) {
        __syncthreads();
        int buf = kc & 1;
        if (kc + 1 < 8) {
            int cb = (kc + 1) * 32;
            #pragma unroll
            for (int i = 0; i < 2; i++) {
                int e = tid + i*256;
                int o = e >> 2, cq = e & 3;
                *(uint4*)&As[buf^1][o][cq*8] = *(const uint4*)(Am + (size_t)(o0+o)*CH + cb + cq*8);
            }
            #pragma unroll
            for (int i = 0; i < 2; i++) {
                int e = tid + i*256;
                int n = e >> 2, cq = e & 3;
                *(uint4*)&Bs[buf^1][n][cq*8] = *(const uint4*)(Qt + (size_t)(n0+n)*256 + cb + cq*8);
            }
        }
        MMA_CHUNK_G(&As[buf][0][0], LDA, &Bs[buf][0][0], LDA, 0, acc, lane, wm, wn);
    }

    __nv_bfloat16* ob = g_attnbf + (size_t)b*CH*NPIX;
    const int r0 = lane >> 2, c2 = (lane & 3)*2;
    #pragma unroll
    for (int mi = 0; mi < 2; mi++) {
        int o_lo = o0 + wm*32 + mi*16 + r0;
        int o_hi = o_lo + 8;
        float rvlo = g_rv[b*CH + o_lo], rvhi = g_rv[b*CH + o_hi];
        float rblo = rb[o_lo], rbhi = rb[o_hi];
        #pragma unroll
        for (int nj = 0; nj < 8; nj++) {
            int n = n0 + wn*64 + nj*8 + c2;
            float iq0 = g_invQ[b*NPIX + n],     dn0 = g_denom[b*NPIX + n];
            float iq1 = g_invQ[b*NPIX + n + 1], dn1 = g_denom[b*NPIX + n + 1];
            __nv_bfloat162 vlo, vhi;
            vlo.x = __float2bfloat16(fmaf(fmaf(iq0, acc[mi][nj][0], rvlo), dn0, rblo));
            vlo.y = __float2bfloat16(fmaf(fmaf(iq1, acc[mi][nj][1], rvlo), dn1, rblo));
            vhi.x = __float2bfloat16(fmaf(fmaf(iq0, acc[mi][nj][2], rvhi), dn0, rbhi));
            vhi.y = __float2bfloat16(fmaf(fmaf(iq1, acc[mi][nj][3], rvhi), dn1, rbhi));
            *(__nv_bfloat162*)(ob + (size_t)o_lo*NPIX + n) = vlo;
            *(__nv_bfloat162*)(ob + (size_t)o_hi*NPIX + n) = vhi;
        }
    }
}

// ---------------- bf16 MMA 3x3 conv: all-taps-resident A, 2 barriers per c-block ----
#define CONV_BW_WORDS (8*GST)
#define CONV_A_BYTES  (9*128*LDA*2)
#define CONV_SMEM     (CONV_A_BYTES + CONV_BW_WORDS*4)

__device__ __forceinline__ void conv_fillB(uint32_t* __restrict__ Bw,
                                           const __nv_bfloat16* __restrict__ inb,
                                           int cbase, int pr0, int tid)
{
    #pragma unroll
    for (int it = 0; it < 2; it++) {
        int e = tid + it*256;
        int kw = e >> 5;
        int row = (e >> 3) & 3;
        int seg = e & 7;
        int g = (kw & 3) + ((kw >> 3) << 2);
        int s = (kw >> 2) & 1;
        int gr = pr0 - 1 + row;
        uint32_t* dst = Bw + g*GST + (row*66 + 1 + seg*8)*2 + s;
        if ((unsigned)gr < IMW) {
            const __nv_bfloat16* q = inb + (size_t)(cbase + kw*2)*NPIX + gr*IMW + seg*8;
            uint4 lo4 = *(const uint4*)q;
            uint4 hi4 = *(const uint4*)(q + NPIX);
            const unsigned short* ls = (const unsigned short*)&lo4;
            const unsigned short* hs = (const unsigned short*)&hi4;
            #pragma unroll
            for (int j = 0; j < 8; j++)
                dst[j*2] = (uint32_t)ls[j] | ((uint32_t)hs[j] << 16);
        } else {
            #pragma unroll
            for (int j = 0; j < 8; j++) dst[j*2] = 0u;
        }
    }
}

__global__ __launch_bounds__(256) void k_conv_tc(const __nv_bfloat16* __restrict__ in,
                                                 const __nv_bfloat16* __restrict__ wt,
                                                 const float* __restrict__ bias,
                                                 const float* __restrict__ xres,
                                                 float* __restrict__ out_f,
                                                 __nv_bfloat16* __restrict__ out_bf,
                                                 int fuse)
{
    extern __shared__ __align__(16) char dsm[];
    __nv_bfloat16* Asm = (__nv_bfloat16*)dsm;                 // [9][128][LDA]
    uint32_t* Bw = (uint32_t*)(dsm + CONV_A_BYTES);
    const int b   = blockIdx.z;
    const int o0  = blockIdx.y * 128;
    const int pr0 = blockIdx.x * 2;
    const __nv_bfloat16* inb = in + (size_t)b*CH*NPIX;
    const int tid = threadIdx.x;
    const int wid = tid >> 5, lane = tid & 31;
    const int wm = wid & 3, wn = wid >> 2;

    float acc[2][8][4];
    ACC_ZERO(acc);

    // halo columns always zero (tile spans full image width) — written once
    if (tid < 128) {
        int kw = tid >> 3;
        int row = (tid >> 1) & 3;
        int side = tid & 1;
        int g = (kw & 3) + ((kw >> 3) << 2);
        int s = (kw >> 2) & 1;
        Bw[g*GST + (row*66 + side*65)*2 + s] = 0u;
    }

    for (int cb = 0; cb < 8; cb++) {
        __syncthreads();   // prior compute finished reading Asm/Bw
        // fill A: all 9 taps for this c-block
        #pragma unroll
        for (int i = 0; i < 18; i++) {
            int e = tid + i*256;               // 9*128*4 = 4608 uint4 slots
            int t = e >> 9;
            int rem = e & 511;
            int o = rem >> 2, cq = rem & 3;
            *(uint4*)(Asm + ((size_t)t*128 + o)*LDA + cq*8) =
                *(const uint4*)(wt + ((size_t)t*256 + o0 + o)*256 + cb*32 + cq*8);
        }
        conv_fillB(Bw, inb, cb*32, pr0, tid);
        __syncthreads();
        // compute: 9 taps, barrier-free (reads only)
        #pragma unroll
        for (int t = 0; t < 9; t++) {
            const int dy = t / 3 - 1, dx = t % 3 - 1;
            const int pos0 = (1 + wn + dy) * 66 + 1 + dx;
            #pragma unroll
            for (int ks = 0; ks < 2; ks++) {
                uint32_t a0[4], a1[4];
                ldsm_x4(a0, smem_u32(Asm + ((size_t)t*128 + wm*32 + (lane&15))*LDA
                                     + ks*16 + (lane>>4)*8));
                ldsm_x4(a1, smem_u32(Asm + ((size_t)t*128 + wm*32 + 16 + (lane&15))*LDA
                                     + ks*16 + (lane>>4)*8));
                const uint32_t* bp = Bw + ((lane&3) + ks*4)*GST
                                   + (pos0 + (lane>>2))*2;
                #pragma unroll
                for (int f = 0; f < 8; f++) {
                    uint2 bb = *(const uint2*)(bp + f*16);
                    mma16816(acc[0][f], a0, bb.x, bb.y);
                    mma16816(acc[1][f], a1, bb.x, bb.y);
                }
            }
        }
    }

    const int r0 = lane >> 2, c2 = (lane & 3)*2;
    const int pxbase = pr0*64;
    if (fuse) {
        const float* xb = xres + (size_t)b*CH*NPIX;
        float* ob = out_f + (size_t)b*CH*NPIX;
        #pragma unroll
        for (int mi = 0; mi < 2; mi++) {
            int o_lo = o0 + wm*32 + mi*16 + r0;
            int o_hi = o_lo + 8;
            float blo = bias[o_lo], bhi = bias[o_hi];
            #pragma unroll
            for (int f = 0; f < 8; f++) {
                int px = pxbase + wn*64 + f*8 + c2;
                float a0 = acc[mi][f][0] + blo, a1 = acc[mi][f][1] + blo;
                float a2 = acc[mi][f][2] + bhi, a3 = acc[mi][f][3] + bhi;
                float2 xlo = *(const float2*)(xb + (size_t)o_lo*NPIX + px);
                float2 xhi = *(const float2*)(xb + (size_t)o_hi*NPIX + px);
                a0 = fmaf(a0, xlo.x, xlo.x);
                a1 = fmaf(a1, xlo.y, xlo.y);
                a2 = fmaf(a2, xhi.x, xhi.x);
                a3 = fmaf(a3, xhi.y, xhi.y);
                *(float2*)(ob + (size_t)o_lo*NPIX + px) = make_float2(a0, a1);
                *(float2*)(ob + (size_t)o_hi*NPIX + px) = make_float2(a2, a3);
            }
        }
    } else {
        __nv_bfloat16* ob = out_bf + (size_t)b*CH*NPIX;
        #pragma unroll
        for (int mi = 0; mi < 2; mi++) {
            int o_lo = o0 + wm*32 + mi*16 + r0;
            int o_hi = o_lo + 8;
            float blo = bias[o_lo], bhi = bias[o_hi];
            #pragma unroll
            for (int f = 0; f < 8; f++) {
                int px = pxbase + wn*64 + f*8 + c2;
                __nv_bfloat162 vlo, vhi;
                vlo.x = __float2bfloat16(acc[mi][f][0] + blo);
                vlo.y = __float2bfloat16(acc[mi][f][1] + blo);
                vhi.x = __float2bfloat16(acc[mi][f][2] + bhi);
                vhi.y = __float2bfloat16(acc[mi][f][3] + bhi);
                *(__nv_bfloat162*)(ob + (size_t)o_lo*NPIX + px) = vlo;
                *(__nv_bfloat162*)(ob + (size_t)o_hi*NPIX + px) = vhi;
            }
        }
    }
}

// ---------------- invK ----------------
__global__ __launch_bounds__(256) void k_normsK()
{
    int idx2 = blockIdx.x*256 + threadIdx.x;
    int b = idx2 >> 11, n = (idx2 & 2047) * 2;
    const __nv_bfloat16* Kp = g_Kbf + (size_t)b*CH*NPIX + n;
    float sk0 = 0.f, sk1 = 0.f;
    #pragma unroll 16
    for (int c = 0; c < CH; c++) {
        __nv_bfloat162 k = *(const __nv_bfloat162*)(Kp + (size_t)c*NPIX);
        float kx = __bfloat162float(k.x), ky = __bfloat162float(k.y);
        sk0 = fmaf(kx, kx, sk0);
        sk1 = fmaf(ky, ky, sk1);
    }
    int o = b*NPIX + n;
    g_invK[o]   = 1.0f / sqrtf(sk0);
    g_invK[o+1] = 1.0f / sqrtf(sk1);
}

// ---------------- ksum / vsum; emits normalized Kn bf16 ----------------
__global__ __launch_bounds__(256) void k_colsums()
{
    int bc = blockIdx.x;
    int b = bc >> 8;
    const __nv_bfloat16* Kp = g_Kbf + (size_t)bc*NPIX;
    const __nv_bfloat16* Vp = g_Vbf + (size_t)bc*NPIX;
    const float* ik = g_invK + (size_t)b*NPIX;
    __nv_bfloat16* knp = g_Knbf + (size_t)bc*NPIX;
    int tid = threadIdx.x;
    float sk = 0.f, sv = 0.f;
    #pragma unroll
    for (int it = 0; it < 2; it++) {
        int base = (tid + it*256) * 8;
        uint4 kv4 = *(const uint4*)(Kp + base);
        uint4 vv4 = *(const uint4*)(Vp + base);
        float4 ika = *(const float4*)(ik + base);
        float4 ikb = *(const float4*)(ik + base + 4);
        const __nv_bfloat16* kk = (const __nv_bfloat16*)&kv4;
        const __nv_bfloat16* vv = (const __nv_bfloat16*)&vv4;
        float iks[8] = {ika.x, ika.y, ika.z, ika.w, ikb.x, ikb.y, ikb.z, ikb.w};
        unsigned short outw[8];
        #pragma unroll
        for (int j = 0; j < 8; j++) {
            float kn = __bfloat162float(kk[j]) * iks[j];
            __nv_bfloat16 knb = __float2bfloat16(kn);
            outw[j] = __bfloat16_as_ushort(knb);
            sk += kn;
            sv += __bfloat162float(vv[j]);
        }
        *(uint4*)(knp + base) = *(uint4*)outw;
    }
    __shared__ float rk[256], rv[256];
    rk[tid] = sk; rv[tid] = sv;
    __syncthreads();
    for (int s = 128; s > 0; s >>= 1) {
        if (tid < s) { rk[tid] += rk[tid+s]; rv[tid] += rv[tid+s]; }
        __syncthreads();
    }
    if (tid == 0) { g_ksum[bc] = rk[0]; g_vsum[bc] = rv[0]; }
}

// ---------------- A = rw @ kv^T (fp32 in, bf16 out) ----------------
__global__ __launch_bounds__(256) void k_nt(const float* __restrict__ Ap, long strideA,
                                            const float* __restrict__ Bp, long strideB,
                                            int L, __nv_bfloat16* __restrict__ out)
{
    __shared__ float As[32][65];
    __shared__ float Bs[32][65];
    const int b = blockIdx.z;
    const int i0 = blockIdx.y*64, j0 = blockIdx.x*64;
    const float* A = Ap + (size_t)b*strideA;
    const float* B = Bp + (size_t)b*strideB;
    const int tid = threadIdx.x;
    const int ty = tid >> 4, tx = tid & 15;
    float acc[4][4];
    #pragma unroll
    for (int i = 0; i < 4; i++) {
        #pragma unroll
        for (int j = 0; j < 4; j++) acc[i][j] = 0.f;
    }

    for (int l0 = 0; l0 < L; l0 += 32) {
        #pragma unroll
        for (int r = 0; r < 8; r++) {
            int e = tid + r*256;
            int ii = e >> 5, ll = e & 31;
            As[ll][ii] = A[(size_t)(i0+ii)*L + l0 + ll];
        }
        #pragma unroll
        for (int r = 0; r < 8; r++) {
            int e = tid + r*256;
            int jj = e >> 5, ll = e & 31;
            Bs[ll][jj] = B[(size_t)(j0+jj)*L + l0 + ll];
        }
        __syncthreads();
        #pragma unroll
        for (int ll = 0; ll < 32; ll++) {
            float ar[4], br[4];
            #pragma unroll
            for (int i = 0; i < 4; i++) ar[i] = As[ll][ty*4+i];
            #pragma unroll
            for (int j = 0; j < 4; j++) br[j] = Bs[ll][tx*4+j];
            #pragma unroll
            for (int i = 0; i < 4; i++) {
                #pragma unroll
                for (int j = 0; j < 4; j++)
                    acc[i][j] = fmaf(ar[i], br[j], acc[i][j]);
            }
        }
        __syncthreads();
    }
    __nv_bfloat16* ob = out + (size_t)b*CH*CH;
    #pragma unroll
    for (int i = 0; i < 4; i++) {
        #pragma unroll
        for (int j = 0; j < 4; j++)
            ob[(size_t)(i0+ty*4+i)*CH + j0 + tx*4 + j] = __float2bfloat16(acc[i][j]);
    }
}

// ---------------- rv[b,o] = rw @ vsum ----------------
__global__ __launch_bounds__(256) void k_rv(const float* __restrict__ rw)
{
    int b = blockIdx.x, o = threadIdx.x;
    __shared__ float vs[256];
    vs[o] = g_vsum[b*CH + o];
    __syncthreads();
    float s = 0.f;
    const float* rp = rw + (size_t)o*CH;
    #pragma unroll 8
    for (int c = 0; c < CH; c++) s = fmaf(rp[c], vs[c], s);
    g_rv[b*CH + o] = s;
}

// ---------------- fused invQ + denom (warp per token) ----------------
__global__ __launch_bounds__(256) void k_qstats()
{
    __shared__ float ks[256];
    const int tid = threadIdx.x, lane = tid & 31, wid = tid >> 5;
    const int b = blockIdx.x >> 7;
    ks[tid] = g_ksum[b*CH + tid];
    __syncthreads();
    const int t0 = blockIdx.x*32 + wid*4;
    #pragma unroll
    for (int j = 0; j < 4; j++) {
        int t = t0 + j;
        uint4 v = *(const uint4*)(g_Qt + (size_t)t*256 + lane*8);
        const __nv_bfloat16* qq = (const __nv_bfloat16*)&v;
        float sq = 0.f, dt = 0.f;
        #pragma unroll
        for (int k = 0; k < 8; k++) {
            float f = __bfloat162float(qq[k]);
            sq = fmaf(f, f, sq);
            dt = fmaf(f, ks[lane*8 + k], dt);
        }
        #pragma unroll
        for (int m = 16; m > 0; m >>= 1) {
            sq += __shfl_xor_sync(0xffffffffu, sq, m);
            dt += __shfl_xor_sync(0xffffffffu, dt, m);
        }
        if (lane == 0) {
            float iq = 1.0f / sqrtf(sq);
            g_invQ[t] = iq;
            g_denom[t] = 1.0f / (4096.0f + dt*iq + 1e-6f);
        }
    }
}

// ---------------- launcher ----------------
extern "C" void kernel_launch(void* const* d_in, const int* in_sizes, int n_in,
                              void* d_out, int out_size)
{
    (void)in_sizes; (void)n_in; (void)out_size;
    const float* x   = (const float*)d_in[0];
    const float* qw  = (const float*)d_in[1];
    const float* qb  = (const float*)d_in[2];
    const float* kw  = (const float*)d_in[3];
    const float* kb  = (const float*)d_in[4];
    const float* vw  = (const float*)d_in[5];
    const float* vb  = (const float*)d_in[6];
    const float* rw  = (const float*)d_in[7];
    const float* rb  = (const float*)d_in[8];
    const float* c1w = (const float*)d_in[9];
    const float* c1b = (const float*)d_in[10];
    const float* c2w = (const float*)d_in[11];
    const float* c2b = (const float*)d_in[12];
    float* out = (float*)d_out;

    float* pkv;
    __nv_bfloat16 *pQbf, *pKbf, *pVbf, *pattnbf, *ph1bf, *pAbf, *pwqkv, *pwc1, *pwc2;
    cudaGetSymbolAddress((void**)&pkv,    g_kv);
    cudaGetSymbolAddress((void**)&pQbf,   g_Qbf);
    cudaGetSymbolAddress((void**)&pKbf,   g_Kbf);
    cudaGetSymbolAddress((void**)&pVbf,   g_Vbf);
    cudaGetSymbolAddress((void**)&pattnbf,g_attnbf);
    cudaGetSymbolAddress((void**)&ph1bf,  g_h1bf);
    cudaGetSymbolAddress((void**)&pAbf,   g_Abf);
    cudaGetSymbolAddress((void**)&pwqkv,  g_wqkv);
    cudaGetSymbolAddress((void**)&pwc1,   g_wc1b);
    cudaGetSymbolAddress((void**)&pwc2,   g_wc2b);

    static int attr_set = 0;
    if (!attr_set) {
        cudaFuncSetAttribute(k_proj3,   cudaFuncAttributeMaxDynamicSharedMemorySize, P3_SMEM);
        cudaFuncSetAttribute(k_conv_tc, cudaFuncAttributeMaxDynamicSharedMemorySize, CONV_SMEM);
        attr_set = 1;
    }

    dim3 gproj(32, 2, BSZ);
    dim3 gkv(2, 2, BSZ*4);
    dim3 gnt(4, 4, BSZ);
    dim3 gconv(32, 2, BSZ);

    k_t_x<<<dim3(128, 4, BSZ), 256>>>(x);
    k_cvtw<<<(3*CH*CH)/256, 256>>>(qw, kw, vw, pwqkv);
    k_cvt_wc<<<(9*CH*CH)/256, 256>>>(c1w, pwc1);
    k_cvt_wc<<<(9*CH*CH)/256, 256>>>(c2w, pwc2);

    k_proj3<<<gproj, 256, P3_SMEM>>>(pwqkv, qb, kb, vb, pQbf, pKbf, pVbf);
    k_t_q<<<dim3(64, 4, BSZ), 256>>>();
    k_normsK<<<(BSZ*NPIX/2)/256, 256>>>();
    k_colsums<<<BSZ*CH, 256>>>();
    k_kv_tc<<<gkv, 256>>>();
    k_kvred<<<(BSZ*CH*CH)/256, 256>>>();
    k_nt<<<gnt, 256>>>(rw, 0L, pkv, (long)CH*CH, CH, pAbf);
    k_rv<<<BSZ, 256>>>(rw);
    k_qstats<<<(BSZ*NPIX)/32, 256>>>();
    k_attn_tc<<<gproj, 256>>>(rb);
    k_conv_tc<<<gconv, 256, CONV_SMEM>>>(pattnbf, pwc1, c1b, (const float*)0, (float*)0, ph1bf, 0);
    k_conv_tc<<<gconv, 256, CONV_SMEM>>>(ph1bf, pwc2, c2b, x, out, (__nv_bfloat16*)0, 1);
}

// round 10
// speedup vs baseline: 6.5507x; 1.0294x over previous
#include <cuda_runtime.h>
#include <cuda_bf16.h>
#include <math.h>
#include <cstdint>

#define BSZ  8
#define CH   256
#define NPIX 4096
#define IMW  64
#define LDA  40   // bf16 elems per smem row (80B, conflict-free ldmatrix)
#define LDB3 264  // proj3 shared-B row width
#define GST  536  // conv B group stride (words)

// ---------------- scratch (device globals; alloc-free) ----------------
__device__ float g_invQ[BSZ*NPIX];
__device__ float g_invK[BSZ*NPIX];
__device__ float g_ksum[BSZ*CH];
__device__ float g_vsum[BSZ*CH];
__device__ float g_kvp[BSZ*4*CH*CH];
__device__ float g_rv[BSZ*CH];
__device__ float g_denom[BSZ*NPIX];
// bf16 operands
__device__ __nv_bfloat16 g_xt[BSZ*NPIX*CH];
__device__ __nv_bfloat16 g_Qbf[BSZ*CH*NPIX];
__device__ __nv_bfloat16 g_Qt[BSZ*NPIX*CH];
__device__ __nv_bfloat16 g_Kbf[BSZ*CH*NPIX];
__device__ __nv_bfloat16 g_Vbf[BSZ*CH*NPIX];
__device__ __nv_bfloat16 g_Knbf[BSZ*CH*NPIX];
__device__ __nv_bfloat16 g_attnbf[BSZ*CH*NPIX];
__device__ __nv_bfloat16 g_h1bf[BSZ*CH*NPIX];
__device__ __nv_bfloat16 g_Abf[BSZ*CH*CH];
__device__ __nv_bfloat16 g_wqkv[3*CH*CH];
__device__ __nv_bfloat16 g_wc1b[9*CH*CH];
__device__ __nv_bfloat16 g_wc2b[9*CH*CH];

// ================= warp-MMA helpers =================
__device__ __forceinline__ uint32_t smem_u32(const void* p) {
    uint32_t a;
    asm("{ .reg .u64 t; cvta.to.shared.u64 t, %1; cvt.u32.u64 %0, t; }" : "=r"(a) : "l"(p));
    return a;
}
__device__ __forceinline__ void ldsm_x4(uint32_t (&r)[4], uint32_t addr) {
    asm volatile("ldmatrix.sync.aligned.m8n8.x4.shared.b16 {%0,%1,%2,%3}, [%4];"
        : "=r"(r[0]), "=r"(r[1]), "=r"(r[2]), "=r"(r[3]) : "r"(addr));
}
__device__ __forceinline__ void mma16816(float (&d)[4], const uint32_t (&a)[4],
                                         uint32_t b0, uint32_t b1) {
    asm volatile("mma.sync.aligned.m16n8k16.row.col.f32.bf16.bf16.f32 "
        "{%0,%1,%2,%3}, {%4,%5,%6,%7}, {%8,%9}, {%0,%1,%2,%3};"
        : "+f"(d[0]), "+f"(d[1]), "+f"(d[2]), "+f"(d[3])
        : "r"(a[0]), "r"(a[1]), "r"(a[2]), "r"(a[3]), "r"(b0), "r"(b1));
}

#define MMA_CHUNK_G(As, AW, Bs, BW, coff, acc, lane, wm, wn) do {                   \
    _Pragma("unroll")                                                               \
    for (int ks = 0; ks < 2; ks++) {                                                \
        uint32_t a_[2][4];                                                          \
        _Pragma("unroll")                                                           \
        for (int mi = 0; mi < 2; mi++)                                              \
            ldsm_x4(a_[mi], smem_u32(&(As)[((wm)*32 + mi*16 + ((lane)&15))*(AW)     \
                                          + ks*16 + ((lane)>>4)*8]));               \
        uint32_t b_[4][4];                                                          \
        _Pragma("unroll")                                                           \
        for (int ni = 0; ni < 4; ni++)                                              \
            ldsm_x4(b_[ni], smem_u32(&(Bs)[((wn)*64 + ni*16 + (((lane)>>4)&1)*8     \
                                            + ((lane)&7))*(BW)                      \
                                           + (coff) + ks*16 + (((lane)>>3)&1)*8])); \
        _Pragma("unroll")                                                           \
        for (int mi = 0; mi < 2; mi++) {                                            \
            _Pragma("unroll")                                                       \
            for (int ni = 0; ni < 4; ni++) {                                        \
                mma16816(acc[mi][ni*2],   a_[mi], b_[ni][0], b_[ni][1]);            \
                mma16816(acc[mi][ni*2+1], a_[mi], b_[ni][2], b_[ni][3]);            \
            }                                                                       \
        }                                                                           \
    }                                                                               \
} while (0)

#define ACC_ZERO(acc) do {                                                          \
    _Pragma("unroll")                                                               \
    for (int i_ = 0; i_ < 2; i_++) {                                                \
        _Pragma("unroll")                                                           \
        for (int j_ = 0; j_ < 8; j_++) {                                            \
            _Pragma("unroll")                                                       \
            for (int q_ = 0; q_ < 4; q_++) acc[i_][j_][q_] = 0.f;                   \
        }                                                                           \
    }                                                                               \
} while (0)

// ---------------- k_prep: t_x || cvtw || cvt_wc(c1) || cvt_wc(c2) ----------------
#define PREP_TX   4096
#define PREP_CVTW (PREP_TX + 768)
#define PREP_WC1  (PREP_CVTW + 2304)
#define PREP_TOT  (PREP_WC1 + 2304)
__global__ __launch_bounds__(256) void k_prep(const float* __restrict__ x,
                                              const float* __restrict__ qw,
                                              const float* __restrict__ kw,
                                              const float* __restrict__ vw,
                                              const float* __restrict__ c1w,
                                              const float* __restrict__ c2w)
{
    __shared__ __nv_bfloat16 sm[32][80];
    const int bx = blockIdx.x;
    const int tid = threadIdx.x;
    if (bx < PREP_TX) {                         // x transpose -> g_xt
        int nx = bx & 127, cy = (bx >> 7) & 3, b = bx >> 9;
        int c0 = cy*64, n0 = nx*32;
        const float* in = x + ((size_t)b*CH + c0)*NPIX + n0;
        #pragma unroll
        for (int i = 0; i < 8; i++) {
            int e = tid + i*256;
            int c = e >> 5, n = e & 31;
            sm[n][c] = __float2bfloat16(in[(size_t)c*NPIX + n]);
        }
        __syncthreads();
        int n = tid >> 3, seg = tid & 7;
        *(uint4*)(g_xt + ((size_t)b*NPIX + n0+n)*256 + c0 + seg*8) = *(uint4*)&sm[n][seg*8];
    } else if (bx < PREP_CVTW) {                // qkv weights cvt
        int i = (bx - PREP_TX)*256 + tid;
        int which = i >> 16, r = i & 65535;
        const float* s = (which == 0) ? qw : (which == 1) ? kw : vw;
        g_wqkv[i] = __float2bfloat16(s[r]);
    } else if (bx < PREP_WC1) {                 // conv1 weights cvt+transpose
        int i = (bx - PREP_CVTW)*256 + tid;
        int c = i & 255, o = (i >> 8) & 255, t = i >> 16;
        g_wc1b[i] = __float2bfloat16(c1w[o*2304 + c*9 + t]);
    } else {                                    // conv2 weights
        int i = (bx - PREP_WC1)*256 + tid;
        int c = i & 255, o = (i >> 8) & 255, t = i >> 16;
        g_wc2b[i] = __float2bfloat16(c2w[o*2304 + c*9 + t]);
    }
}

// ---------------- k_mid: t_q || normsK ----------------
#define MID_TQ  2048
#define MID_TOT (MID_TQ + 128)
__global__ __launch_bounds__(256) void k_mid()
{
    __shared__ __nv_bfloat16 sm[64][80];
    const int bx = blockIdx.x;
    const int tid = threadIdx.x;
    if (bx < MID_TQ) {                          // Q transpose -> g_Qt
        int n0 = (bx & 63)*64, c0 = ((bx >> 6) & 3)*64, b = bx >> 8;
        const __nv_bfloat16* in = g_Qbf + ((size_t)b*CH + c0)*NPIX + n0;
        #pragma unroll
        for (int i = 0; i < 8; i++) {
            int e = tid + i*256;
            int c = e >> 5, np = e & 31;
            __nv_bfloat162 v = *(const __nv_bfloat162*)(in + (size_t)c*NPIX + np*2);
            sm[np*2][c] = v.x;
            sm[np*2+1][c] = v.y;
        }
        __syncthreads();
        #pragma unroll
        for (int i = 0; i < 2; i++) {
            int e = tid + i*256;
            int n = e >> 3, seg = e & 7;
            *(uint4*)(g_Qt + ((size_t)b*NPIX + n0+n)*256 + c0 + seg*8) = *(uint4*)&sm[n][seg*8];
        }
    } else {                                    // invK
        int idx2 = (bx - MID_TQ)*256 + tid;
        int b = idx2 >> 11, n = (idx2 & 2047) * 2;
        const __nv_bfloat16* Kp = g_Kbf + (size_t)b*CH*NPIX + n;
        float sk0 = 0.f, sk1 = 0.f;
        #pragma unroll 16
        for (int c = 0; c < CH; c++) {
            __nv_bfloat162 k = *(const __nv_bfloat162*)(Kp + (size_t)c*NPIX);
            float kx = __bfloat162float(k.x), ky = __bfloat162float(k.y);
            sk0 = fmaf(kx, kx, sk0);
            sk1 = fmaf(ky, ky, sk1);
        }
        int o = b*NPIX + n;
        g_invK[o]   = 1.0f / sqrtf(sk0);
        g_invK[o+1] = 1.0f / sqrtf(sk1);
    }
}

// ---------------- fused QKV projection ----------------
#define P3_BS_BYTES (128*LDB3*2)
#define P3_SMEM     (P3_BS_BYTES + 2*128*LDA*2)
__global__ __launch_bounds__(256) void k_proj3(const __nv_bfloat16* __restrict__ w3,
                                               const float* __restrict__ qb,
                                               const float* __restrict__ kb,
                                               const float* __restrict__ vb,
                                               __nv_bfloat16* __restrict__ outQ,
                                               __nv_bfloat16* __restrict__ outK,
                                               __nv_bfloat16* __restrict__ outV)
{
    extern __shared__ __align__(16) char dsm[];
    __nv_bfloat16* Bs = (__nv_bfloat16*)dsm;
    __nv_bfloat16* As = (__nv_bfloat16*)(dsm + P3_BS_BYTES);
    const int b  = blockIdx.z;
    const int o0 = blockIdx.y * 128;
    const int n0 = blockIdx.x * 128;
    const __nv_bfloat16* xtb = g_xt + (size_t)b*NPIX*CH;
    const int tid = threadIdx.x;
    const int wid = tid >> 5, lane = tid & 31;
    const int wm = wid & 3, wn = wid >> 2;

    #pragma unroll
    for (int i = 0; i < 16; i++) {
        int e = tid + i*256;
        int n = e >> 5, seg = e & 31;
        *(uint4*)&Bs[n*LDB3 + seg*8] = *(const uint4*)(xtb + (size_t)(n0+n)*256 + seg*8);
    }

    float acc[2][8][4];
    const int r0 = lane >> 2, c2 = (lane & 3)*2;

    #pragma unroll
    for (int which = 0; which < 3; which++) {
        const __nv_bfloat16* w = w3 + (size_t)which*CH*CH;
        ACC_ZERO(acc);
        #pragma unroll
        for (int i = 0; i < 2; i++) {
            int e = tid + i*256;
            int o = e >> 2, cq = e & 3;
            *(uint4*)&As[(0*128 + o)*LDA + cq*8] = *(const uint4*)(w + (size_t)(o0+o)*CH + cq*8);
        }
        for (int kc = 0; kc < 8; kc++) {
            __syncthreads();
            int buf = kc & 1;
            if (kc + 1 < 8) {
                int cb = (kc + 1) * 32;
                #pragma unroll
                for (int i = 0; i < 2; i++) {
                    int e = tid + i*256;
                    int o = e >> 2, cq = e & 3;
                    *(uint4*)&As[((buf^1)*128 + o)*LDA + cq*8] =
                        *(const uint4*)(w + (size_t)(o0+o)*CH + cb + cq*8);
                }
            }
            MMA_CHUNK_G((As + buf*128*LDA), LDA, Bs, LDB3, kc*32, acc, lane, wm, wn);
        }
        const float* bias = (which == 0) ? qb : (which == 1) ? kb : vb;
        __nv_bfloat16* ob = ((which == 0) ? outQ : (which == 1) ? outK : outV)
                            + (size_t)b*CH*NPIX;
        #pragma unroll
        for (int mi = 0; mi < 2; mi++) {
            int o_lo = o0 + wm*32 + mi*16 + r0;
            int o_hi = o_lo + 8;
            float blo = bias[o_lo], bhi = bias[o_hi];
            #pragma unroll
            for (int nj = 0; nj < 8; nj++) {
                int n = n0 + wn*64 + nj*8 + c2;
                __nv_bfloat162 vlo, vhi;
                vlo.x = __float2bfloat16(acc[mi][nj][0] + blo);
                vlo.y = __float2bfloat16(acc[mi][nj][1] + blo);
                vhi.x = __float2bfloat16(acc[mi][nj][2] + bhi);
                vhi.y = __float2bfloat16(acc[mi][nj][3] + bhi);
                *(__nv_bfloat162*)(ob + (size_t)o_lo*NPIX + n) = vlo;
                *(__nv_bfloat162*)(ob + (size_t)o_hi*NPIX + n) = vhi;
            }
        }
    }
}

// ---------------- ksum / vsum; emits normalized Kn bf16 ----------------
__global__ __launch_bounds__(256) void k_colsums()
{
    int bc = blockIdx.x;
    int b = bc >> 8;
    const __nv_bfloat16* Kp = g_Kbf + (size_t)bc*NPIX;
    const __nv_bfloat16* Vp = g_Vbf + (size_t)bc*NPIX;
    const float* ik = g_invK + (size_t)b*NPIX;
    __nv_bfloat16* knp = g_Knbf + (size_t)bc*NPIX;
    int tid = threadIdx.x;
    float sk = 0.f, sv = 0.f;
    #pragma unroll
    for (int it = 0; it < 2; it++) {
        int base = (tid + it*256) * 8;
        uint4 kv4 = *(const uint4*)(Kp + base);
        uint4 vv4 = *(const uint4*)(Vp + base);
        float4 ika = *(const float4*)(ik + base);
        float4 ikb = *(const float4*)(ik + base + 4);
        const __nv_bfloat16* kk = (const __nv_bfloat16*)&kv4;
        const __nv_bfloat16* vv = (const __nv_bfloat16*)&vv4;
        float iks[8] = {ika.x, ika.y, ika.z, ika.w, ikb.x, ikb.y, ikb.z, ikb.w};
        unsigned short outw[8];
        #pragma unroll
        for (int j = 0; j < 8; j++) {
            float kn = __bfloat162float(kk[j]) * iks[j];
            __nv_bfloat16 knb = __float2bfloat16(kn);
            outw[j] = __bfloat16_as_ushort(knb);
            sk += kn;
            sv += __bfloat162float(vv[j]);
        }
        *(uint4*)(knp + base) = *(uint4*)outw;
    }
    __shared__ float rk[256], rv[256];
    rk[tid] = sk; rv[tid] = sv;
    __syncthreads();
    for (int s = 128; s > 0; s >>= 1) {
        if (tid < s) { rk[tid] += rk[tid+s]; rv[tid] += rv[tid+s]; }
        __syncthreads();
    }
    if (tid == 0) { g_ksum[bc] = rk[0]; g_vsum[bc] = rv[0]; }
}

// ---------------- k_post: kv GEMM || qstats || rv ----------------
#define POST_KV  128
#define POST_QS  (POST_KV + 1024)
#define POST_TOT (POST_QS + 8)
__global__ __launch_bounds__(256) void k_post(const float* __restrict__ rw)
{
    __shared__ __align__(16) __nv_bfloat16 As[2][128][LDA];
    __shared__ __align__(16) __nv_bfloat16 Bs[2][128][LDA];
    __shared__ float fs[256];
    const int bx = blockIdx.x;
    const int tid = threadIdx.x;
    if (bx < POST_KV) {
        // ---- kv GEMM, split-N=4 ----
        const int c0 = (bx & 1) * 128;
        const int k0 = ((bx >> 1) & 1) * 128;
        const int bsp = bx >> 2;
        const int b = bsp >> 2, sp = bsp & 3;
        const int nb = sp * 1024;
        const __nv_bfloat16* Kn = g_Knbf + (size_t)b*CH*NPIX;
        const __nv_bfloat16* Vb = g_Vbf  + (size_t)b*CH*NPIX;
        const int wid = tid >> 5, lane = tid & 31;
        const int wm = wid & 3, wn = wid >> 2;

        float acc[2][8][4];
        ACC_ZERO(acc);

        #pragma unroll
        for (int i = 0; i < 16; i++) {
            int e = tid + i*256;
            int r = e >> 5, n = e & 31;
            As[0][r][n] = Kn[(size_t)(k0+r)*NPIX + nb + n];
            Bs[0][r][n] = Vb[(size_t)(c0+r)*NPIX + nb + n];
        }
        for (int kc = 0; kc < 32; kc++) {
            __syncthreads();
            int buf = kc & 1;
            if (kc + 1 < 32) {
                int nn = nb + (kc + 1) * 32;
                #pragma unroll
                for (int i = 0; i < 16; i++) {
                    int e = tid + i*256;
                    int r = e >> 5, n = e & 31;
                    As[buf^1][r][n] = Kn[(size_t)(k0+r)*NPIX + nn + n];
                    Bs[buf^1][r][n] = Vb[(size_t)(c0+r)*NPIX + nn + n];
                }
            }
            MMA_CHUNK_G(&As[buf][0][0], LDA, &Bs[buf][0][0], LDA, 0, acc, lane, wm, wn);
        }
        float* ob = g_kvp + (size_t)bsp*CH*CH;
        const int r0 = lane >> 2, c2 = (lane & 3)*2;
        #pragma unroll
        for (int mi = 0; mi < 2; mi++) {
            int k_lo = k0 + wm*32 + mi*16 + r0;
            int k_hi = k_lo + 8;
            #pragma unroll
            for (int nj = 0; nj < 8; nj++) {
                int c = c0 + wn*64 + nj*8 + c2;
                *(float2*)(ob + (size_t)k_lo*CH + c) = make_float2(acc[mi][nj][0], acc[mi][nj][1]);
                *(float2*)(ob + (size_t)k_hi*CH + c) = make_float2(acc[mi][nj][2], acc[mi][nj][3]);
            }
        }
    } else if (bx < POST_QS) {
        // ---- qstats: fused invQ + denom (warp per token) ----
        const int bq = bx - POST_KV;
        const int lane = tid & 31, wid = tid >> 5;
        const int b = bq >> 7;
        fs[tid] = g_ksum[b*CH + tid];
        __syncthreads();
        const int t0 = bq*32 + wid*4;
        #pragma unroll
        for (int j = 0; j < 4; j++) {
            int t = t0 + j;
            uint4 v = *(const uint4*)(g_Qt + (size_t)t*256 + lane*8);
            const __nv_bfloat16* qq = (const __nv_bfloat16*)&v;
            float sq = 0.f, dt = 0.f;
            #pragma unroll
            for (int k = 0; k < 8; k++) {
                float f = __bfloat162float(qq[k]);
                sq = fmaf(f, f, sq);
                dt = fmaf(f, fs[lane*8 + k], dt);
            }
            #pragma unroll
            for (int m = 16; m > 0; m >>= 1) {
                sq += __shfl_xor_sync(0xffffffffu, sq, m);
                dt += __shfl_xor_sync(0xffffffffu, dt, m);
            }
            if (lane == 0) {
                float iq = 1.0f / sqrtf(sq);
                g_invQ[t] = iq;
                g_denom[t] = 1.0f / (4096.0f + dt*iq + 1e-6f);
            }
        }
    } else {
        // ---- rv = rw @ vsum ----
        const int b = bx - POST_QS;
        fs[tid] = g_vsum[b*CH + tid];
        __syncthreads();
        float s = 0.f;
        const float* rp = rw + (size_t)tid*CH;
        #pragma unroll 8
        for (int c = 0; c < CH; c++) s = fmaf(rp[c], fs[c], s);
        g_rv[b*CH + tid] = s;
    }
}

// ---------------- A = rw @ kv^T, kvred folded in (fp32 in, bf16 out) ----------------
__global__ __launch_bounds__(256) void k_nt(const float* __restrict__ rw,
                                            __nv_bfloat16* __restrict__ out)
{
    __shared__ float As[32][65];
    __shared__ float Bs[32][65];
    const int b = blockIdx.z;
    const int i0 = blockIdx.y*64, j0 = blockIdx.x*64;
    const float* P = g_kvp + (size_t)b*4*65536;
    const int tid = threadIdx.x;
    const int ty = tid >> 4, tx = tid & 15;
    float acc[4][4];
    #pragma unroll
    for (int i = 0; i < 4; i++) {
        #pragma unroll
        for (int j = 0; j < 4; j++) acc[i][j] = 0.f;
    }

    for (int l0 = 0; l0 < CH; l0 += 32) {
        #pragma unroll
        for (int r = 0; r < 8; r++) {
            int e = tid + r*256;
            int ii = e >> 5, ll = e & 31;
            As[ll][ii] = rw[(size_t)(i0+ii)*CH + l0 + ll];
        }
        #pragma unroll
        for (int r = 0; r < 8; r++) {
            int e = tid + r*256;
            int jj = e >> 5, ll = e & 31;
            size_t off = (size_t)(j0+jj)*CH + l0 + ll;
            Bs[ll][jj] = (P[off] + P[65536 + off]) + (P[2*65536 + off] + P[3*65536 + off]);
        }
        __syncthreads();
        #pragma unroll
        for (int ll = 0; ll < 32; ll++) {
            float ar[4], br[4];
            #pragma unroll
            for (int i = 0; i < 4; i++) ar[i] = As[ll][ty*4+i];
            #pragma unroll
            for (int j = 0; j < 4; j++) br[j] = Bs[ll][tx*4+j];
            #pragma unroll
            for (int i = 0; i < 4; i++) {
                #pragma unroll
                for (int j = 0; j < 4; j++)
                    acc[i][j] = fmaf(ar[i], br[j], acc[i][j]);
            }
        }
        __syncthreads();
    }
    __nv_bfloat16* ob = out + (size_t)b*CH*CH;
    #pragma unroll
    for (int i = 0; i < 4; i++) {
        #pragma unroll
        for (int j = 0; j < 4; j++)
            ob[(size_t)(i0+ty*4+i)*CH + j0 + tx*4 + j] = __float2bfloat16(acc[i][j]);
    }
}

// ---------------- bf16 MMA attn GEMM + epilogue ----------------
__global__ __launch_bounds__(256) void k_attn_tc(const float* __restrict__ rb)
{
    __shared__ __align__(16) __nv_bfloat16 As[2][128][LDA];
    __shared__ __align__(16) __nv_bfloat16 Bs[2][128][LDA];
    const int b  = blockIdx.z;
    const int o0 = blockIdx.y * 128;
    const int n0 = blockIdx.x * 128;
    const __nv_bfloat16* Am = g_Abf + (size_t)b*CH*CH;
    const __nv_bfloat16* Qt = g_Qt + (size_t)b*NPIX*CH;
    const int tid = threadIdx.x;
    const int wid = tid >> 5, lane = tid & 31;
    const int wm = wid & 3, wn = wid >> 2;

    float acc[2][8][4];
    ACC_ZERO(acc);

    #pragma unroll
    for (int i = 0; i < 2; i++) {
        int e = tid + i*256;
        int o = e >> 2, cq = e & 3;
        *(uint4*)&As[0][o][cq*8] = *(const uint4*)(Am + (size_t)(o0+o)*CH + cq*8);
    }
    #pragma unroll
    for (int i = 0; i < 2; i++) {
        int e = tid + i*256;
        int n = e >> 2, cq = e & 3;
        *(uint4*)&Bs[0][n][cq*8] = *(const uint4*)(Qt + (size_t)(n0+n)*256 + cq*8);
    }

    for (int kc = 0; kc < 8; kc++) {
        __syncthreads();
        int buf = kc & 1;
        if (kc + 1 < 8) {
            int cb = (kc + 1) * 32;
            #pragma unroll
            for (int i = 0; i < 2; i++) {
                int e = tid + i*256;
                int o = e >> 2, cq = e & 3;
                *(uint4*)&As[buf^1][o][cq*8] = *(const uint4*)(Am + (size_t)(o0+o)*CH + cb + cq*8);
            }
            #pragma unroll
            for (int i = 0; i < 2; i++) {
                int e = tid + i*256;
                int n = e >> 2, cq = e & 3;
                *(uint4*)&Bs[buf^1][n][cq*8] = *(const uint4*)(Qt + (size_t)(n0+n)*256 + cb + cq*8);
            }
        }
        MMA_CHUNK_G(&As[buf][0][0], LDA, &Bs[buf][0][0], LDA, 0, acc, lane, wm, wn);
    }

    __nv_bfloat16* ob = g_attnbf + (size_t)b*CH*NPIX;
    const int r0 = lane >> 2, c2 = (lane & 3)*2;
    #pragma unroll
    for (int mi = 0; mi < 2; mi++) {
        int o_lo = o0 + wm*32 + mi*16 + r0;
        int o_hi = o_lo + 8;
        float rvlo = g_rv[b*CH + o_lo], rvhi = g_rv[b*CH + o_hi];
        float rblo = rb[o_lo], rbhi = rb[o_hi];
        #pragma unroll
        for (int nj = 0; nj < 8; nj++) {
            int n = n0 + wn*64 + nj*8 + c2;
            float iq0 = g_invQ[b*NPIX + n],     dn0 = g_denom[b*NPIX + n];
            float iq1 = g_invQ[b*NPIX + n + 1], dn1 = g_denom[b*NPIX + n + 1];
            __nv_bfloat162 vlo, vhi;
            vlo.x = __float2bfloat16(fmaf(fmaf(iq0, acc[mi][nj][0], rvlo), dn0, rblo));
            vlo.y = __float2bfloat16(fmaf(fmaf(iq1, acc[mi][nj][1], rvlo), dn1, rblo));
            vhi.x = __float2bfloat16(fmaf(fmaf(iq0, acc[mi][nj][2], rvhi), dn0, rbhi));
            vhi.y = __float2bfloat16(fmaf(fmaf(iq1, acc[mi][nj][3], rvhi), dn1, rbhi));
            *(__nv_bfloat162*)(ob + (size_t)o_lo*NPIX + n) = vlo;
            *(__nv_bfloat162*)(ob + (size_t)o_hi*NPIX + n) = vhi;
        }
    }
}

// ---------------- bf16 MMA 3x3 conv (all-taps-resident A) ----------------
#define CONV_BW_WORDS (8*GST)
#define CONV_A_BYTES  (9*128*LDA*2)
#define CONV_SMEM     (CONV_A_BYTES + CONV_BW_WORDS*4)

__device__ __forceinline__ void conv_fillB(uint32_t* __restrict__ Bw,
                                           const __nv_bfloat16* __restrict__ inb,
                                           int cbase, int pr0, int tid)
{
    #pragma unroll
    for (int it = 0; it < 2; it++) {
        int e = tid + it*256;
        int kw = e >> 5;
        int row = (e >> 3) & 3;
        int seg = e & 7;
        int g = (kw & 3) + ((kw >> 3) << 2);
        int s = (kw >> 2) & 1;
        int gr = pr0 - 1 + row;
        uint32_t* dst = Bw + g*GST + (row*66 + 1 + seg*8)*2 + s;
        if ((unsigned)gr < IMW) {
            const __nv_bfloat16* q = inb + (size_t)(cbase + kw*2)*NPIX + gr*IMW + seg*8;
            uint4 lo4 = *(const uint4*)q;
            uint4 hi4 = *(const uint4*)(q + NPIX);
            const unsigned short* ls = (const unsigned short*)&lo4;
            const unsigned short* hs = (const unsigned short*)&hi4;
            #pragma unroll
            for (int j = 0; j < 8; j++)
                dst[j*2] = (uint32_t)ls[j] | ((uint32_t)hs[j] << 16);
        } else {
            #pragma unroll
            for (int j = 0; j < 8; j++) dst[j*2] = 0u;
        }
    }
}

__global__ __launch_bounds__(256) void k_conv_tc(const __nv_bfloat16* __restrict__ in,
                                                 const __nv_bfloat16* __restrict__ wt,
                                                 const float* __restrict__ bias,
                                                 const float* __restrict__ xres,
                                                 float* __restrict__ out_f,
                                                 __nv_bfloat16* __restrict__ out_bf,
                                                 int fuse)
{
    extern __shared__ __align__(16) char dsm[];
    __nv_bfloat16* Asm = (__nv_bfloat16*)dsm;
    uint32_t* Bw = (uint32_t*)(dsm + CONV_A_BYTES);
    const int b   = blockIdx.z;
    const int o0  = blockIdx.y * 128;
    const int pr0 = blockIdx.x * 2;
    const __nv_bfloat16* inb = in + (size_t)b*CH*NPIX;
    const int tid = threadIdx.x;
    const int wid = tid >> 5, lane = tid & 31;
    const int wm = wid & 3, wn = wid >> 2;

    float acc[2][8][4];
    ACC_ZERO(acc);

    if (tid < 128) {
        int kw = tid >> 3;
        int row = (tid >> 1) & 3;
        int side = tid & 1;
        int g = (kw & 3) + ((kw >> 3) << 2);
        int s = (kw >> 2) & 1;
        Bw[g*GST + (row*66 + side*65)*2 + s] = 0u;
    }

    for (int cb = 0; cb < 8; cb++) {
        __syncthreads();
        #pragma unroll
        for (int i = 0; i < 18; i++) {
            int e = tid + i*256;
            int t = e >> 9;
            int rem = e & 511;
            int o = rem >> 2, cq = rem & 3;
            *(uint4*)(Asm + ((size_t)t*128 + o)*LDA + cq*8) =
                *(const uint4*)(wt + ((size_t)t*256 + o0 + o)*256 + cb*32 + cq*8);
        }
        conv_fillB(Bw, inb, cb*32, pr0, tid);
        __syncthreads();
        #pragma unroll
        for (int t = 0; t < 9; t++) {
            const int dy = t / 3 - 1, dx = t % 3 - 1;
            const int pos0 = (1 + wn + dy) * 66 + 1 + dx;
            #pragma unroll
            for (int ks = 0; ks < 2; ks++) {
                uint32_t a0[4], a1[4];
                ldsm_x4(a0, smem_u32(Asm + ((size_t)t*128 + wm*32 + (lane&15))*LDA
                                     + ks*16 + (lane>>4)*8));
                ldsm_x4(a1, smem_u32(Asm + ((size_t)t*128 + wm*32 + 16 + (lane&15))*LDA
                                     + ks*16 + (lane>>4)*8));
                const uint32_t* bp = Bw + ((lane&3) + ks*4)*GST
                                   + (pos0 + (lane>>2))*2;
                #pragma unroll
                for (int f = 0; f < 8; f++) {
                    uint2 bb = *(const uint2*)(bp + f*16);
                    mma16816(acc[0][f], a0, bb.x, bb.y);
                    mma16816(acc[1][f], a1, bb.x, bb.y);
                }
            }
        }
    }

    const int r0 = lane >> 2, c2 = (lane & 3)*2;
    const int pxbase = pr0*64;
    if (fuse) {
        const float* xb = xres + (size_t)b*CH*NPIX;
        float* ob = out_f + (size_t)b*CH*NPIX;
        #pragma unroll
        for (int mi = 0; mi < 2; mi++) {
            int o_lo = o0 + wm*32 + mi*16 + r0;
            int o_hi = o_lo + 8;
            float blo = bias[o_lo], bhi = bias[o_hi];
            #pragma unroll
            for (int f = 0; f < 8; f++) {
                int px = pxbase + wn*64 + f*8 + c2;
                float a0 = acc[mi][f][0] + blo, a1 = acc[mi][f][1] + blo;
                float a2 = acc[mi][f][2] + bhi, a3 = acc[mi][f][3] + bhi;
                float2 xlo = *(const float2*)(xb + (size_t)o_lo*NPIX + px);
                float2 xhi = *(const float2*)(xb + (size_t)o_hi*NPIX + px);
                a0 = fmaf(a0, xlo.x, xlo.x);
                a1 = fmaf(a1, xlo.y, xlo.y);
                a2 = fmaf(a2, xhi.x, xhi.x);
                a3 = fmaf(a3, xhi.y, xhi.y);
                *(float2*)(ob + (size_t)o_lo*NPIX + px) = make_float2(a0, a1);
                *(float2*)(ob + (size_t)o_hi*NPIX + px) = make_float2(a2, a3);
            }
        }
    } else {
        __nv_bfloat16* ob = out_bf + (size_t)b*CH*NPIX;
        #pragma unroll
        for (int mi = 0; mi < 2; mi++) {
            int o_lo = o0 + wm*32 + mi*16 + r0;
            int o_hi = o_lo + 8;
            float blo = bias[o_lo], bhi = bias[o_hi];
            #pragma unroll
            for (int f = 0; f < 8; f++) {
                int px = pxbase + wn*64 + f*8 + c2;
                __nv_bfloat162 vlo, vhi;
                vlo.x = __float2bfloat16(acc[mi][f][0] + blo);
                vlo.y = __float2bfloat16(acc[mi][f][1] + blo);
                vhi.x = __float2bfloat16(acc[mi][f][2] + bhi);
                vhi.y = __float2bfloat16(acc[mi][f][3] + bhi);
                *(__nv_bfloat162*)(ob + (size_t)o_lo*NPIX + px) = vlo;
                *(__nv_bfloat162*)(ob + (size_t)o_hi*NPIX + px) = vhi;
            }
        }
    }
}

// ---------------- launcher ----------------
extern "C" void kernel_launch(void* const* d_in, const int* in_sizes, int n_in,
                              void* d_out, int out_size)
{
    (void)in_sizes; (void)n_in; (void)out_size;
    const float* x   = (const float*)d_in[0];
    const float* qw  = (const float*)d_in[1];
    const float* qb  = (const float*)d_in[2];
    const float* kw  = (const float*)d_in[3];
    const float* kb  = (const float*)d_in[4];
    const float* vw  = (const float*)d_in[5];
    const float* vb  = (const float*)d_in[6];
    const float* rw  = (const float*)d_in[7];
    const float* rb  = (const float*)d_in[8];
    const float* c1w = (const float*)d_in[9];
    const float* c1b = (const float*)d_in[10];
    const float* c2w = (const float*)d_in[11];
    const float* c2b = (const float*)d_in[12];
    float* out = (float*)d_out;

    __nv_bfloat16 *pQbf, *pKbf, *pVbf, *pattnbf, *ph1bf, *pAbf, *pwqkv, *pwc1, *pwc2;
    cudaGetSymbolAddress((void**)&pQbf,   g_Qbf);
    cudaGetSymbolAddress((void**)&pKbf,   g_Kbf);
    cudaGetSymbolAddress((void**)&pVbf,   g_Vbf);
    cudaGetSymbolAddress((void**)&pattnbf,g_attnbf);
    cudaGetSymbolAddress((void**)&ph1bf,  g_h1bf);
    cudaGetSymbolAddress((void**)&pAbf,   g_Abf);
    cudaGetSymbolAddress((void**)&pwqkv,  g_wqkv);
    cudaGetSymbolAddress((void**)&pwc1,   g_wc1b);
    cudaGetSymbolAddress((void**)&pwc2,   g_wc2b);

    static int attr_set = 0;
    if (!attr_set) {
        cudaFuncSetAttribute(k_proj3,   cudaFuncAttributeMaxDynamicSharedMemorySize, P3_SMEM);
        cudaFuncSetAttribute(k_conv_tc, cudaFuncAttributeMaxDynamicSharedMemorySize, CONV_SMEM);
        attr_set = 1;
    }

    dim3 gproj(32, 2, BSZ);
    dim3 gnt(4, 4, BSZ);
    dim3 gconv(32, 2, BSZ);

    k_prep<<<PREP_TOT, 256>>>(x, qw, kw, vw, c1w, c2w);
    k_proj3<<<gproj, 256, P3_SMEM>>>(pwqkv, qb, kb, vb, pQbf, pKbf, pVbf);
    k_mid<<<MID_TOT, 256>>>();
    k_colsums<<<BSZ*CH, 256>>>();
    k_post<<<POST_TOT, 256>>>(rw);
    k_nt<<<gnt, 256>>>(rw, pAbf);
    k_attn_tc<<<gproj, 256>>>(rb);
    k_conv_tc<<<gconv, 256, CONV_SMEM>>>(pattnbf, pwc1, c1b, (const float*)0, (float*)0, ph1bf, 0);
    k_conv_tc<<<gconv, 256, CONV_SMEM>>>(ph1bf, pwc2, c2b, x, out, (__nv_bfloat16*)0, 1);
}

// round 11
// speedup vs baseline: 7.3123x; 1.1163x over previous
#include <cuda_runtime.h>
#include <cuda_bf16.h>
#include <math.h>
#include <cstdint>

#define BSZ  8
#define CH   256
#define NPIX 4096
#define IMW  64
#define LDA  40   // bf16 elems per smem row (80B, conflict-free ldmatrix)
#define LDB3 264  // proj3 shared-B row width
#define GST  536  // conv B group stride (words)

// ---------------- scratch (device globals; alloc-free) ----------------
__device__ float g_invQ[BSZ*NPIX];
__device__ float g_invK[BSZ*NPIX];
__device__ float g_ksum[BSZ*CH];
__device__ float g_vsum[BSZ*CH];
__device__ float g_kvp[BSZ*4*CH*CH];
__device__ float g_rv[BSZ*CH];
__device__ float g_denom[BSZ*NPIX];
// bf16 operands
__device__ __nv_bfloat16 g_xt[BSZ*NPIX*CH];
__device__ __nv_bfloat16 g_Qbf[BSZ*CH*NPIX];
__device__ __nv_bfloat16 g_Qt[BSZ*NPIX*CH];
__device__ __nv_bfloat16 g_Kbf[BSZ*CH*NPIX];
__device__ __nv_bfloat16 g_Vbf[BSZ*CH*NPIX];
__device__ __nv_bfloat16 g_Knbf[BSZ*CH*NPIX];
__device__ __nv_bfloat16 g_attnbf[BSZ*CH*NPIX];
__device__ __nv_bfloat16 g_h1bf[BSZ*CH*NPIX];
__device__ __nv_bfloat16 g_Abf[BSZ*CH*CH];
__device__ __nv_bfloat16 g_wqkv[3*CH*CH];
__device__ __nv_bfloat16 g_wc1b[9*CH*CH];
__device__ __nv_bfloat16 g_wc2b[9*CH*CH];

// ================= warp-MMA helpers =================
__device__ __forceinline__ uint32_t smem_u32(const void* p) {
    uint32_t a;
    asm("{ .reg .u64 t; cvta.to.shared.u64 t, %1; cvt.u32.u64 %0, t; }" : "=r"(a) : "l"(p));
    return a;
}
__device__ __forceinline__ void ldsm_x4(uint32_t (&r)[4], uint32_t addr) {
    asm volatile("ldmatrix.sync.aligned.m8n8.x4.shared.b16 {%0,%1,%2,%3}, [%4];"
        : "=r"(r[0]), "=r"(r[1]), "=r"(r[2]), "=r"(r[3]) : "r"(addr));
}
__device__ __forceinline__ void mma16816(float (&d)[4], const uint32_t (&a)[4],
                                         uint32_t b0, uint32_t b1) {
    asm volatile("mma.sync.aligned.m16n8k16.row.col.f32.bf16.bf16.f32 "
        "{%0,%1,%2,%3}, {%4,%5,%6,%7}, {%8,%9}, {%0,%1,%2,%3};"
        : "+f"(d[0]), "+f"(d[1]), "+f"(d[2]), "+f"(d[3])
        : "r"(a[0]), "r"(a[1]), "r"(a[2]), "r"(a[3]), "r"(b0), "r"(b1));
}

#define MMA_CHUNK_G(As, AW, Bs, BW, coff, acc, lane, wm, wn) do {                   \
    _Pragma("unroll")                                                               \
    for (int ks = 0; ks < 2; ks++) {                                                \
        uint32_t a_[2][4];                                                          \
        _Pragma("unroll")                                                           \
        for (int mi = 0; mi < 2; mi++)                                              \
            ldsm_x4(a_[mi], smem_u32(&(As)[((wm)*32 + mi*16 + ((lane)&15))*(AW)     \
                                          + ks*16 + ((lane)>>4)*8]));               \
        uint32_t b_[4][4];                                                          \
        _Pragma("unroll")                                                           \
        for (int ni = 0; ni < 4; ni++)                                              \
            ldsm_x4(b_[ni], smem_u32(&(Bs)[((wn)*64 + ni*16 + (((lane)>>4)&1)*8     \
                                            + ((lane)&7))*(BW)                      \
                                           + (coff) + ks*16 + (((lane)>>3)&1)*8])); \
        _Pragma("unroll")                                                           \
        for (int mi = 0; mi < 2; mi++) {                                            \
            _Pragma("unroll")                                                       \
            for (int ni = 0; ni < 4; ni++) {                                        \
                mma16816(acc[mi][ni*2],   a_[mi], b_[ni][0], b_[ni][1]);            \
                mma16816(acc[mi][ni*2+1], a_[mi], b_[ni][2], b_[ni][3]);            \
            }                                                                       \
        }                                                                           \
    }                                                                               \
} while (0)

#define ACC_ZERO(acc) do {                                                          \
    _Pragma("unroll")                                                               \
    for (int i_ = 0; i_ < 2; i_++) {                                                \
        _Pragma("unroll")                                                           \
        for (int j_ = 0; j_ < 8; j_++) {                                            \
            _Pragma("unroll")                                                       \
            for (int q_ = 0; q_ < 4; q_++) acc[i_][j_][q_] = 0.f;                   \
        }                                                                           \
    }                                                                               \
} while (0)

// ---------------- k_prep: t_x || cvtw || cvt_wc(c1) || cvt_wc(c2) ----------------
#define PREP_TX   4096
#define PREP_CVTW (PREP_TX + 768)
#define PREP_WC1  (PREP_CVTW + 2304)
#define PREP_TOT  (PREP_WC1 + 2304)
__global__ __launch_bounds__(256) void k_prep(const float* __restrict__ x,
                                              const float* __restrict__ qw,
                                              const float* __restrict__ kw,
                                              const float* __restrict__ vw,
                                              const float* __restrict__ c1w,
                                              const float* __restrict__ c2w)
{
    __shared__ __nv_bfloat16 sm[32][80];
    const int bx = blockIdx.x;
    const int tid = threadIdx.x;
    if (bx < PREP_TX) {
        int nx = bx & 127, cy = (bx >> 7) & 3, b = bx >> 9;
        int c0 = cy*64, n0 = nx*32;
        const float* in = x + ((size_t)b*CH + c0)*NPIX + n0;
        #pragma unroll
        for (int i = 0; i < 8; i++) {
            int e = tid + i*256;
            int c = e >> 5, n = e & 31;
            sm[n][c] = __float2bfloat16(in[(size_t)c*NPIX + n]);
        }
        __syncthreads();
        int n = tid >> 3, seg = tid & 7;
        *(uint4*)(g_xt + ((size_t)b*NPIX + n0+n)*256 + c0 + seg*8) = *(uint4*)&sm[n][seg*8];
    } else if (bx < PREP_CVTW) {
        int i = (bx - PREP_TX)*256 + tid;
        int which = i >> 16, r = i & 65535;
        const float* s = (which == 0) ? qw : (which == 1) ? kw : vw;
        g_wqkv[i] = __float2bfloat16(s[r]);
    } else if (bx < PREP_WC1) {
        int i = (bx - PREP_CVTW)*256 + tid;
        int c = i & 255, o = (i >> 8) & 255, t = i >> 16;
        g_wc1b[i] = __float2bfloat16(c1w[o*2304 + c*9 + t]);
    } else {
        int i = (bx - PREP_WC1)*256 + tid;
        int c = i & 255, o = (i >> 8) & 255, t = i >> 16;
        g_wc2b[i] = __float2bfloat16(c2w[o*2304 + c*9 + t]);
    }
}

// ---------------- k_mid: t_q || normsK ----------------
#define MID_TQ  2048
#define MID_TOT (MID_TQ + 128)
__global__ __launch_bounds__(256) void k_mid()
{
    __shared__ __nv_bfloat16 sm[64][80];
    const int bx = blockIdx.x;
    const int tid = threadIdx.x;
    if (bx < MID_TQ) {
        int n0 = (bx & 63)*64, c0 = ((bx >> 6) & 3)*64, b = bx >> 8;
        const __nv_bfloat16* in = g_Qbf + ((size_t)b*CH + c0)*NPIX + n0;
        #pragma unroll
        for (int i = 0; i < 8; i++) {
            int e = tid + i*256;
            int c = e >> 5, np = e & 31;
            __nv_bfloat162 v = *(const __nv_bfloat162*)(in + (size_t)c*NPIX + np*2);
            sm[np*2][c] = v.x;
            sm[np*2+1][c] = v.y;
        }
        __syncthreads();
        #pragma unroll
        for (int i = 0; i < 2; i++) {
            int e = tid + i*256;
            int n = e >> 3, seg = e & 7;
            *(uint4*)(g_Qt + ((size_t)b*NPIX + n0+n)*256 + c0 + seg*8) = *(uint4*)&sm[n][seg*8];
        }
    } else {
        int idx2 = (bx - MID_TQ)*256 + tid;
        int b = idx2 >> 11, n = (idx2 & 2047) * 2;
        const __nv_bfloat16* Kp = g_Kbf + (size_t)b*CH*NPIX + n;
        float sk0 = 0.f, sk1 = 0.f;
        #pragma unroll 16
        for (int c = 0; c < CH; c++) {
            __nv_bfloat162 k = *(const __nv_bfloat162*)(Kp + (size_t)c*NPIX);
            float kx = __bfloat162float(k.x), ky = __bfloat162float(k.y);
            sk0 = fmaf(kx, kx, sk0);
            sk1 = fmaf(ky, ky, sk1);
        }
        int o = b*NPIX + n;
        g_invK[o]   = 1.0f / sqrtf(sk0);
        g_invK[o+1] = 1.0f / sqrtf(sk1);
    }
}

// ---------------- fused QKV projection ----------------
#define P3_BS_BYTES (128*LDB3*2)
#define P3_SMEM     (P3_BS_BYTES + 2*128*LDA*2)
__global__ __launch_bounds__(256) void k_proj3(const __nv_bfloat16* __restrict__ w3,
                                               const float* __restrict__ qb,
                                               const float* __restrict__ kb,
                                               const float* __restrict__ vb,
                                               __nv_bfloat16* __restrict__ outQ,
                                               __nv_bfloat16* __restrict__ outK,
                                               __nv_bfloat16* __restrict__ outV)
{
    extern __shared__ __align__(16) char dsm[];
    __nv_bfloat16* Bs = (__nv_bfloat16*)dsm;
    __nv_bfloat16* As = (__nv_bfloat16*)(dsm + P3_BS_BYTES);
    const int b  = blockIdx.z;
    const int o0 = blockIdx.y * 128;
    const int n0 = blockIdx.x * 128;
    const __nv_bfloat16* xtb = g_xt + (size_t)b*NPIX*CH;
    const int tid = threadIdx.x;
    const int wid = tid >> 5, lane = tid & 31;
    const int wm = wid & 3, wn = wid >> 2;

    #pragma unroll
    for (int i = 0; i < 16; i++) {
        int e = tid + i*256;
        int n = e >> 5, seg = e & 31;
        *(uint4*)&Bs[n*LDB3 + seg*8] = *(const uint4*)(xtb + (size_t)(n0+n)*256 + seg*8);
    }

    float acc[2][8][4];
    const int r0 = lane >> 2, c2 = (lane & 3)*2;

    #pragma unroll
    for (int which = 0; which < 3; which++) {
        const __nv_bfloat16* w = w3 + (size_t)which*CH*CH;
        ACC_ZERO(acc);
        #pragma unroll
        for (int i = 0; i < 2; i++) {
            int e = tid + i*256;
            int o = e >> 2, cq = e & 3;
            *(uint4*)&As[(0*128 + o)*LDA + cq*8] = *(const uint4*)(w + (size_t)(o0+o)*CH + cq*8);
        }
        for (int kc = 0; kc < 8; kc++) {
            __syncthreads();
            int buf = kc & 1;
            if (kc + 1 < 8) {
                int cb = (kc + 1) * 32;
                #pragma unroll
                for (int i = 0; i < 2; i++) {
                    int e = tid + i*256;
                    int o = e >> 2, cq = e & 3;
                    *(uint4*)&As[((buf^1)*128 + o)*LDA + cq*8] =
                        *(const uint4*)(w + (size_t)(o0+o)*CH + cb + cq*8);
                }
            }
            MMA_CHUNK_G((As + buf*128*LDA), LDA, Bs, LDB3, kc*32, acc, lane, wm, wn);
        }
        const float* bias = (which == 0) ? qb : (which == 1) ? kb : vb;
        __nv_bfloat16* ob = ((which == 0) ? outQ : (which == 1) ? outK : outV)
                            + (size_t)b*CH*NPIX;
        #pragma unroll
        for (int mi = 0; mi < 2; mi++) {
            int o_lo = o0 + wm*32 + mi*16 + r0;
            int o_hi = o_lo + 8;
            float blo = bias[o_lo], bhi = bias[o_hi];
            #pragma unroll
            for (int nj = 0; nj < 8; nj++) {
                int n = n0 + wn*64 + nj*8 + c2;
                __nv_bfloat162 vlo, vhi;
                vlo.x = __float2bfloat16(acc[mi][nj][0] + blo);
                vlo.y = __float2bfloat16(acc[mi][nj][1] + blo);
                vhi.x = __float2bfloat16(acc[mi][nj][2] + bhi);
                vhi.y = __float2bfloat16(acc[mi][nj][3] + bhi);
                *(__nv_bfloat162*)(ob + (size_t)o_lo*NPIX + n) = vlo;
                *(__nv_bfloat162*)(ob + (size_t)o_hi*NPIX + n) = vhi;
            }
        }
    }
}

// ---------------- ksum / vsum; emits normalized Kn bf16 ----------------
__global__ __launch_bounds__(256) void k_colsums()
{
    int bc = blockIdx.x;
    int b = bc >> 8;
    const __nv_bfloat16* Kp = g_Kbf + (size_t)bc*NPIX;
    const __nv_bfloat16* Vp = g_Vbf + (size_t)bc*NPIX;
    const float* ik = g_invK + (size_t)b*NPIX;
    __nv_bfloat16* knp = g_Knbf + (size_t)bc*NPIX;
    int tid = threadIdx.x;
    float sk = 0.f, sv = 0.f;
    #pragma unroll
    for (int it = 0; it < 2; it++) {
        int base = (tid + it*256) * 8;
        uint4 kv4 = *(const uint4*)(Kp + base);
        uint4 vv4 = *(const uint4*)(Vp + base);
        float4 ika = *(const float4*)(ik + base);
        float4 ikb = *(const float4*)(ik + base + 4);
        const __nv_bfloat16* kk = (const __nv_bfloat16*)&kv4;
        const __nv_bfloat16* vv = (const __nv_bfloat16*)&vv4;
        float iks[8] = {ika.x, ika.y, ika.z, ika.w, ikb.x, ikb.y, ikb.z, ikb.w};
        unsigned short outw[8];
        #pragma unroll
        for (int j = 0; j < 8; j++) {
            float kn = __bfloat162float(kk[j]) * iks[j];
            __nv_bfloat16 knb = __float2bfloat16(kn);
            outw[j] = __bfloat16_as_ushort(knb);
            sk += kn;
            sv += __bfloat162float(vv[j]);
        }
        *(uint4*)(knp + base) = *(uint4*)outw;
    }
    __shared__ float rk[256], rv[256];
    rk[tid] = sk; rv[tid] = sv;
    __syncthreads();
    for (int s = 128; s > 0; s >>= 1) {
        if (tid < s) { rk[tid] += rk[tid+s]; rv[tid] += rv[tid+s]; }
        __syncthreads();
    }
    if (tid == 0) { g_ksum[bc] = rk[0]; g_vsum[bc] = rv[0]; }
}

// ---------------- k_post: kv GEMM || qstats || rv ----------------
#define POST_KV  128
#define POST_QS  (POST_KV + 1024)
#define POST_TOT (POST_QS + 8)
__global__ __launch_bounds__(256) void k_post(const float* __restrict__ rw)
{
    __shared__ __align__(16) __nv_bfloat16 As[2][128][LDA];
    __shared__ __align__(16) __nv_bfloat16 Bs[2][128][LDA];
    __shared__ float fs[256];
    const int bx = blockIdx.x;
    const int tid = threadIdx.x;
    if (bx < POST_KV) {
        const int c0 = (bx & 1) * 128;
        const int k0 = ((bx >> 1) & 1) * 128;
        const int bsp = bx >> 2;
        const int b = bsp >> 2, sp = bsp & 3;
        const int nb = sp * 1024;
        const __nv_bfloat16* Kn = g_Knbf + (size_t)b*CH*NPIX;
        const __nv_bfloat16* Vb = g_Vbf  + (size_t)b*CH*NPIX;
        const int wid = tid >> 5, lane = tid & 31;
        const int wm = wid & 3, wn = wid >> 2;

        float acc[2][8][4];
        ACC_ZERO(acc);

        #pragma unroll
        for (int i = 0; i < 16; i++) {
            int e = tid + i*256;
            int r = e >> 5, n = e & 31;
            As[0][r][n] = Kn[(size_t)(k0+r)*NPIX + nb + n];
            Bs[0][r][n] = Vb[(size_t)(c0+r)*NPIX + nb + n];
        }
        for (int kc = 0; kc < 32; kc++) {
            __syncthreads();
            int buf = kc & 1;
            if (kc + 1 < 32) {
                int nn = nb + (kc + 1) * 32;
                #pragma unroll
                for (int i = 0; i < 16; i++) {
                    int e = tid + i*256;
                    int r = e >> 5, n = e & 31;
                    As[buf^1][r][n] = Kn[(size_t)(k0+r)*NPIX + nn + n];
                    Bs[buf^1][r][n] = Vb[(size_t)(c0+r)*NPIX + nn + n];
                }
            }
            MMA_CHUNK_G(&As[buf][0][0], LDA, &Bs[buf][0][0], LDA, 0, acc, lane, wm, wn);
        }
        float* ob = g_kvp + (size_t)bsp*CH*CH;
        const int r0 = lane >> 2, c2 = (lane & 3)*2;
        #pragma unroll
        for (int mi = 0; mi < 2; mi++) {
            int k_lo = k0 + wm*32 + mi*16 + r0;
            int k_hi = k_lo + 8;
            #pragma unroll
            for (int nj = 0; nj < 8; nj++) {
                int c = c0 + wn*64 + nj*8 + c2;
                *(float2*)(ob + (size_t)k_lo*CH + c) = make_float2(acc[mi][nj][0], acc[mi][nj][1]);
                *(float2*)(ob + (size_t)k_hi*CH + c) = make_float2(acc[mi][nj][2], acc[mi][nj][3]);
            }
        }
    } else if (bx < POST_QS) {
        const int bq = bx - POST_KV;
        const int lane = tid & 31, wid = tid >> 5;
        const int b = bq >> 7;
        fs[tid] = g_ksum[b*CH + tid];
        __syncthreads();
        const int t0 = bq*32 + wid*4;
        #pragma unroll
        for (int j = 0; j < 4; j++) {
            int t = t0 + j;
            uint4 v = *(const uint4*)(g_Qt + (size_t)t*256 + lane*8);
            const __nv_bfloat16* qq = (const __nv_bfloat16*)&v;
            float sq = 0.f, dt = 0.f;
            #pragma unroll
            for (int k = 0; k < 8; k++) {
                float f = __bfloat162float(qq[k]);
                sq = fmaf(f, f, sq);
                dt = fmaf(f, fs[lane*8 + k], dt);
            }
            #pragma unroll
            for (int m = 16; m > 0; m >>= 1) {
                sq += __shfl_xor_sync(0xffffffffu, sq, m);
                dt += __shfl_xor_sync(0xffffffffu, dt, m);
            }
            if (lane == 0) {
                float iq = 1.0f / sqrtf(sq);
                g_invQ[t] = iq;
                g_denom[t] = 1.0f / (4096.0f + dt*iq + 1e-6f);
            }
        }
    } else {
        const int b = bx - POST_QS;
        fs[tid] = g_vsum[b*CH + tid];
        __syncthreads();
        float s = 0.f;
        const float* rp = rw + (size_t)tid*CH;
        #pragma unroll 8
        for (int c = 0; c < CH; c++) s = fmaf(rp[c], fs[c], s);
        g_rv[b*CH + tid] = s;
    }
}

// ---------------- A = rw @ kv^T, kvred folded in ----------------
__global__ __launch_bounds__(256) void k_nt(const float* __restrict__ rw,
                                            __nv_bfloat16* __restrict__ out)
{
    __shared__ float As[32][65];
    __shared__ float Bs[32][65];
    const int b = blockIdx.z;
    const int i0 = blockIdx.y*64, j0 = blockIdx.x*64;
    const float* P = g_kvp + (size_t)b*4*65536;
    const int tid = threadIdx.x;
    const int ty = tid >> 4, tx = tid & 15;
    float acc[4][4];
    #pragma unroll
    for (int i = 0; i < 4; i++) {
        #pragma unroll
        for (int j = 0; j < 4; j++) acc[i][j] = 0.f;
    }

    for (int l0 = 0; l0 < CH; l0 += 32) {
        #pragma unroll
        for (int r = 0; r < 8; r++) {
            int e = tid + r*256;
            int ii = e >> 5, ll = e & 31;
            As[ll][ii] = rw[(size_t)(i0+ii)*CH + l0 + ll];
        }
        #pragma unroll
        for (int r = 0; r < 8; r++) {
            int e = tid + r*256;
            int jj = e >> 5, ll = e & 31;
            size_t off = (size_t)(j0+jj)*CH + l0 + ll;
            Bs[ll][jj] = (P[off] + P[65536 + off]) + (P[2*65536 + off] + P[3*65536 + off]);
        }
        __syncthreads();
        #pragma unroll
        for (int ll = 0; ll < 32; ll++) {
            float ar[4], br[4];
            #pragma unroll
            for (int i = 0; i < 4; i++) ar[i] = As[ll][ty*4+i];
            #pragma unroll
            for (int j = 0; j < 4; j++) br[j] = Bs[ll][tx*4+j];
            #pragma unroll
            for (int i = 0; i < 4; i++) {
                #pragma unroll
                for (int j = 0; j < 4; j++)
                    acc[i][j] = fmaf(ar[i], br[j], acc[i][j]);
            }
        }
        __syncthreads();
    }
    __nv_bfloat16* ob = out + (size_t)b*CH*CH;
    #pragma unroll
    for (int i = 0; i < 4; i++) {
        #pragma unroll
        for (int j = 0; j < 4; j++)
            ob[(size_t)(i0+ty*4+i)*CH + j0 + tx*4 + j] = __float2bfloat16(acc[i][j]);
    }
}

// ---------------- bf16 MMA attn GEMM + epilogue ----------------
__global__ __launch_bounds__(256) void k_attn_tc(const float* __restrict__ rb)
{
    __shared__ __align__(16) __nv_bfloat16 As[2][128][LDA];
    __shared__ __align__(16) __nv_bfloat16 Bs[2][128][LDA];
    const int b  = blockIdx.z;
    const int o0 = blockIdx.y * 128;
    const int n0 = blockIdx.x * 128;
    const __nv_bfloat16* Am = g_Abf + (size_t)b*CH*CH;
    const __nv_bfloat16* Qt = g_Qt + (size_t)b*NPIX*CH;
    const int tid = threadIdx.x;
    const int wid = tid >> 5, lane = tid & 31;
    const int wm = wid & 3, wn = wid >> 2;

    float acc[2][8][4];
    ACC_ZERO(acc);

    #pragma unroll
    for (int i = 0; i < 2; i++) {
        int e = tid + i*256;
        int o = e >> 2, cq = e & 3;
        *(uint4*)&As[0][o][cq*8] = *(const uint4*)(Am + (size_t)(o0+o)*CH + cq*8);
    }
    #pragma unroll
    for (int i = 0; i < 2; i++) {
        int e = tid + i*256;
        int n = e >> 2, cq = e & 3;
        *(uint4*)&Bs[0][n][cq*8] = *(const uint4*)(Qt + (size_t)(n0+n)*256 + cq*8);
    }

    for (int kc = 0; kc < 8; kc++) {
        __syncthreads();
        int buf = kc & 1;
        if (kc + 1 < 8) {
            int cb = (kc + 1) * 32;
            #pragma unroll
            for (int i = 0; i < 2; i++) {
                int e = tid + i*256;
                int o = e >> 2, cq = e & 3;
                *(uint4*)&As[buf^1][o][cq*8] = *(const uint4*)(Am + (size_t)(o0+o)*CH + cb + cq*8);
            }
            #pragma unroll
            for (int i = 0; i < 2; i++) {
                int e = tid + i*256;
                int n = e >> 2, cq = e & 3;
                *(uint4*)&Bs[buf^1][n][cq*8] = *(const uint4*)(Qt + (size_t)(n0+n)*256 + cb + cq*8);
            }
        }
        MMA_CHUNK_G(&As[buf][0][0], LDA, &Bs[buf][0][0], LDA, 0, acc, lane, wm, wn);
    }

    __nv_bfloat16* ob = g_attnbf + (size_t)b*CH*NPIX;
    const int r0 = lane >> 2, c2 = (lane & 3)*2;
    #pragma unroll
    for (int mi = 0; mi < 2; mi++) {
        int o_lo = o0 + wm*32 + mi*16 + r0;
        int o_hi = o_lo + 8;
        float rvlo = g_rv[b*CH + o_lo], rvhi = g_rv[b*CH + o_hi];
        float rblo = rb[o_lo], rbhi = rb[o_hi];
        #pragma unroll
        for (int nj = 0; nj < 8; nj++) {
            int n = n0 + wn*64 + nj*8 + c2;
            float iq0 = g_invQ[b*NPIX + n],     dn0 = g_denom[b*NPIX + n];
            float iq1 = g_invQ[b*NPIX + n + 1], dn1 = g_denom[b*NPIX + n + 1];
            __nv_bfloat162 vlo, vhi;
            vlo.x = __float2bfloat16(fmaf(fmaf(iq0, acc[mi][nj][0], rvlo), dn0, rblo));
            vlo.y = __float2bfloat16(fmaf(fmaf(iq1, acc[mi][nj][1], rvlo), dn1, rblo));
            vhi.x = __float2bfloat16(fmaf(fmaf(iq0, acc[mi][nj][2], rvhi), dn0, rbhi));
            vhi.y = __float2bfloat16(fmaf(fmaf(iq1, acc[mi][nj][3], rvhi), dn1, rbhi));
            *(__nv_bfloat162*)(ob + (size_t)o_lo*NPIX + n) = vlo;
            *(__nv_bfloat162*)(ob + (size_t)o_hi*NPIX + n) = vhi;
        }
    }
}

// ---------------- bf16 MMA 3x3 conv: 4 warps, 64x64 warp tiles (smem-BW optimized) ----
#define CONV_BW_WORDS (8*GST)
#define CONV_A_BYTES  (9*128*LDA*2)
#define CONV_SMEM     (CONV_A_BYTES + CONV_BW_WORDS*4)

__device__ __forceinline__ void conv_fillB4(uint32_t* __restrict__ Bw,
                                            const __nv_bfloat16* __restrict__ inb,
                                            int cbase, int pr0, int tid)
{
    #pragma unroll
    for (int it = 0; it < 4; it++) {
        int e = tid + it*128;
        int kw = e >> 5;
        int row = (e >> 3) & 3;
        int seg = e & 7;
        int g = (kw & 3) + ((kw >> 3) << 2);
        int s = (kw >> 2) & 1;
        int gr = pr0 - 1 + row;
        uint32_t* dst = Bw + g*GST + (row*66 + 1 + seg*8)*2 + s;
        if ((unsigned)gr < IMW) {
            const __nv_bfloat16* q = inb + (size_t)(cbase + kw*2)*NPIX + gr*IMW + seg*8;
            uint4 lo4 = *(const uint4*)q;
            uint4 hi4 = *(const uint4*)(q + NPIX);
            const unsigned short* ls = (const unsigned short*)&lo4;
            const unsigned short* hs = (const unsigned short*)&hi4;
            #pragma unroll
            for (int j = 0; j < 8; j++)
                dst[j*2] = (uint32_t)ls[j] | ((uint32_t)hs[j] << 16);
        } else {
            #pragma unroll
            for (int j = 0; j < 8; j++) dst[j*2] = 0u;
        }
    }
}

__global__ __launch_bounds__(128) void k_conv_tc(const __nv_bfloat16* __restrict__ in,
                                                 const __nv_bfloat16* __restrict__ wt,
                                                 const float* __restrict__ bias,
                                                 const float* __restrict__ xres,
                                                 float* __restrict__ out_f,
                                                 __nv_bfloat16* __restrict__ out_bf,
                                                 int fuse)
{
    extern __shared__ __align__(16) char dsm[];
    __nv_bfloat16* Asm = (__nv_bfloat16*)dsm;                 // [9][128][LDA]
    uint32_t* Bw = (uint32_t*)(dsm + CONV_A_BYTES);
    const int b   = blockIdx.z;
    const int o0  = blockIdx.y * 128;
    const int pr0 = blockIdx.x * 2;
    const __nv_bfloat16* inb = in + (size_t)b*CH*NPIX;
    const int tid = threadIdx.x;
    const int wid = tid >> 5, lane = tid & 31;
    const int wm = wid & 1;          // M half: 64 rows
    const int wn = wid >> 1;         // N half: 64 px (= image row wn)

    float acc[4][8][4];
    #pragma unroll
    for (int i = 0; i < 4; i++) {
        #pragma unroll
        for (int j = 0; j < 8; j++) {
            #pragma unroll
            for (int q = 0; q < 4; q++) acc[i][j][q] = 0.f;
        }
    }

    // halo zeros (128 entries, one per thread)
    {
        int kw = tid >> 3;
        int row = (tid >> 1) & 3;
        int side = tid & 1;
        int g = (kw & 3) + ((kw >> 3) << 2);
        int s = (kw >> 2) & 1;
        Bw[g*GST + (row*66 + side*65)*2 + s] = 0u;
    }

    for (int cb = 0; cb < 8; cb++) {
        __syncthreads();
        // fill A: all 9 taps (4608 uint4 / 128 threads = 36 each)
        #pragma unroll
        for (int i = 0; i < 36; i++) {
            int e = tid + i*128;
            int t = e >> 9;
            int rem = e & 511;
            int o = rem >> 2, cq = rem & 3;
            *(uint4*)(Asm + ((size_t)t*128 + o)*LDA + cq*8) =
                *(const uint4*)(wt + ((size_t)t*256 + o0 + o)*256 + cb*32 + cq*8);
        }
        conv_fillB4(Bw, inb, cb*32, pr0, tid);
        __syncthreads();
        #pragma unroll
        for (int t = 0; t < 9; t++) {
            const int dy = t / 3 - 1, dx = t % 3 - 1;
            const int pos0 = (1 + wn + dy) * 66 + 1 + dx;
            #pragma unroll
            for (int ks = 0; ks < 2; ks++) {
                uint32_t a_[4][4];
                #pragma unroll
                for (int mi = 0; mi < 4; mi++)
                    ldsm_x4(a_[mi], smem_u32(Asm + ((size_t)t*128 + wm*64 + mi*16 + (lane&15))*LDA
                                             + ks*16 + (lane>>4)*8));
                const uint32_t* bp = Bw + ((lane&3) + ks*4)*GST
                                   + (pos0 + (lane>>2))*2;
                #pragma unroll
                for (int f = 0; f < 8; f++) {
                    uint2 bb = *(const uint2*)(bp + f*16);
                    #pragma unroll
                    for (int mi = 0; mi < 4; mi++)
                        mma16816(acc[mi][f], a_[mi], bb.x, bb.y);
                }
            }
        }
    }

    const int r0 = lane >> 2, c2 = (lane & 3)*2;
    const int pxbase = pr0*64;
    if (fuse) {
        const float* xb = xres + (size_t)b*CH*NPIX;
        float* ob = out_f + (size_t)b*CH*NPIX;
        #pragma unroll
        for (int mi = 0; mi < 4; mi++) {
            int o_lo = o0 + wm*64 + mi*16 + r0;
            int o_hi = o_lo + 8;
            float blo = bias[o_lo], bhi = bias[o_hi];
            #pragma unroll
            for (int f = 0; f < 8; f++) {
                int px = pxbase + wn*64 + f*8 + c2;
                float a0 = acc[mi][f][0] + blo, a1 = acc[mi][f][1] + blo;
                float a2 = acc[mi][f][2] + bhi, a3 = acc[mi][f][3] + bhi;
                float2 xlo = *(const float2*)(xb + (size_t)o_lo*NPIX + px);
                float2 xhi = *(const float2*)(xb + (size_t)o_hi*NPIX + px);
                a0 = fmaf(a0, xlo.x, xlo.x);
                a1 = fmaf(a1, xlo.y, xlo.y);
                a2 = fmaf(a2, xhi.x, xhi.x);
                a3 = fmaf(a3, xhi.y, xhi.y);
                *(float2*)(ob + (size_t)o_lo*NPIX + px) = make_float2(a0, a1);
                *(float2*)(ob + (size_t)o_hi*NPIX + px) = make_float2(a2, a3);
            }
        }
    } else {
        __nv_bfloat16* ob = out_bf + (size_t)b*CH*NPIX;
        #pragma unroll
        for (int mi = 0; mi < 4; mi++) {
            int o_lo = o0 + wm*64 + mi*16 + r0;
            int o_hi = o_lo + 8;
            float blo = bias[o_lo], bhi = bias[o_hi];
            #pragma unroll
            for (int f = 0; f < 8; f++) {
                int px = pxbase + wn*64 + f*8 + c2;
                __nv_bfloat162 vlo, vhi;
                vlo.x = __float2bfloat16(acc[mi][f][0] + blo);
                vlo.y = __float2bfloat16(acc[mi][f][1] + blo);
                vhi.x = __float2bfloat16(acc[mi][f][2] + bhi);
                vhi.y = __float2bfloat16(acc[mi][f][3] + bhi);
                *(__nv_bfloat162*)(ob + (size_t)o_lo*NPIX + px) = vlo;
                *(__nv_bfloat162*)(ob + (size_t)o_hi*NPIX + px) = vhi;
            }
        }
    }
}

// ---------------- launcher ----------------
extern "C" void kernel_launch(void* const* d_in, const int* in_sizes, int n_in,
                              void* d_out, int out_size)
{
    (void)in_sizes; (void)n_in; (void)out_size;
    const float* x   = (const float*)d_in[0];
    const float* qw  = (const float*)d_in[1];
    const float* qb  = (const float*)d_in[2];
    const float* kw  = (const float*)d_in[3];
    const float* kb  = (const float*)d_in[4];
    const float* vw  = (const float*)d_in[5];
    const float* vb  = (const float*)d_in[6];
    const float* rw  = (const float*)d_in[7];
    const float* rb  = (const float*)d_in[8];
    const float* c1w = (const float*)d_in[9];
    const float* c1b = (const float*)d_in[10];
    const float* c2w = (const float*)d_in[11];
    const float* c2b = (const float*)d_in[12];
    float* out = (float*)d_out;

    __nv_bfloat16 *pQbf, *pKbf, *pVbf, *pattnbf, *ph1bf, *pAbf, *pwqkv, *pwc1, *pwc2;
    cudaGetSymbolAddress((void**)&pQbf,   g_Qbf);
    cudaGetSymbolAddress((void**)&pKbf,   g_Kbf);
    cudaGetSymbolAddress((void**)&pVbf,   g_Vbf);
    cudaGetSymbolAddress((void**)&pattnbf,g_attnbf);
    cudaGetSymbolAddress((void**)&ph1bf,  g_h1bf);
    cudaGetSymbolAddress((void**)&pAbf,   g_Abf);
    cudaGetSymbolAddress((void**)&pwqkv,  g_wqkv);
    cudaGetSymbolAddress((void**)&pwc1,   g_wc1b);
    cudaGetSymbolAddress((void**)&pwc2,   g_wc2b);

    static int attr_set = 0;
    if (!attr_set) {
        cudaFuncSetAttribute(k_proj3,   cudaFuncAttributeMaxDynamicSharedMemorySize, P3_SMEM);
        cudaFuncSetAttribute(k_conv_tc, cudaFuncAttributeMaxDynamicSharedMemorySize, CONV_SMEM);
        attr_set = 1;
    }

    dim3 gproj(32, 2, BSZ);
    dim3 gnt(4, 4, BSZ);
    dim3 gconv(32, 2, BSZ);

    k_prep<<<PREP_TOT, 256>>>(x, qw, kw, vw, c1w, c2w);
    k_proj3<<<gproj, 256, P3_SMEM>>>(pwqkv, qb, kb, vb, pQbf, pKbf, pVbf);
    k_mid<<<MID_TOT, 256>>>();
    k_colsums<<<BSZ*CH, 256>>>();
    k_post<<<POST_TOT, 256>>>(rw);
    k_nt<<<gnt, 256>>>(rw, pAbf);
    k_attn_tc<<<gproj, 256>>>(rb);
    k_conv_tc<<<gconv, 128, CONV_SMEM>>>(pattnbf, pwc1, c1b, (const float*)0, (float*)0, ph1bf, 0);
    k_conv_tc<<<gconv, 128, CONV_SMEM>>>(ph1bf, pwc2, c2b, x, out, (__nv_bfloat16*)0, 1);
}

// round 12
// speedup vs baseline: 7.3516x; 1.0054x over previous
#include <cuda_runtime.h>
#include <cuda_bf16.h>
#include <math.h>
#include <cstdint>

#define BSZ  8
#define CH   256
#define NPIX 4096
#define IMW  64
#define LDA  40   // bf16 elems per smem row (80B, conflict-free ldmatrix)
#define LDB3 264  // proj3 shared-B row width
#define GST  536  // conv B group stride (words)

// ---------------- scratch (device globals; alloc-free) ----------------
__device__ float g_invQ[BSZ*NPIX];
__device__ float g_invK[BSZ*NPIX];
__device__ float g_ksum[BSZ*CH];
__device__ float g_vsum[BSZ*CH];
__device__ float g_kvp[BSZ*4*CH*CH];
__device__ float g_rv[BSZ*CH];
__device__ float g_denom[BSZ*NPIX];
// bf16 operands
__device__ __nv_bfloat16 g_xt[BSZ*NPIX*CH];
__device__ __nv_bfloat16 g_Qbf[BSZ*CH*NPIX];
__device__ __nv_bfloat16 g_Qt[BSZ*NPIX*CH];
__device__ __nv_bfloat16 g_Kbf[BSZ*CH*NPIX];
__device__ __nv_bfloat16 g_Vbf[BSZ*CH*NPIX];
__device__ __nv_bfloat16 g_Knbf[BSZ*CH*NPIX];
__device__ __nv_bfloat16 g_attnbf[BSZ*CH*NPIX];
__device__ __nv_bfloat16 g_h1bf[BSZ*CH*NPIX];
__device__ __nv_bfloat16 g_Abf[BSZ*CH*CH];
__device__ __nv_bfloat16 g_wqkv[3*CH*CH];
__device__ __nv_bfloat16 g_wc1b[9*CH*CH];
__device__ __nv_bfloat16 g_wc2b[9*CH*CH];

// ================= warp-MMA helpers =================
__device__ __forceinline__ uint32_t smem_u32(const void* p) {
    uint32_t a;
    asm("{ .reg .u64 t; cvta.to.shared.u64 t, %1; cvt.u32.u64 %0, t; }" : "=r"(a) : "l"(p));
    return a;
}
__device__ __forceinline__ void ldsm_x4(uint32_t (&r)[4], uint32_t addr) {
    asm volatile("ldmatrix.sync.aligned.m8n8.x4.shared.b16 {%0,%1,%2,%3}, [%4];"
        : "=r"(r[0]), "=r"(r[1]), "=r"(r[2]), "=r"(r[3]) : "r"(addr));
}
__device__ __forceinline__ void mma16816(float (&d)[4], const uint32_t (&a)[4],
                                         uint32_t b0, uint32_t b1) {
    asm volatile("mma.sync.aligned.m16n8k16.row.col.f32.bf16.bf16.f32 "
        "{%0,%1,%2,%3}, {%4,%5,%6,%7}, {%8,%9}, {%0,%1,%2,%3};"
        : "+f"(d[0]), "+f"(d[1]), "+f"(d[2]), "+f"(d[3])
        : "r"(a[0]), "r"(a[1]), "r"(a[2]), "r"(a[3]), "r"(b0), "r"(b1));
}

// 8-warp (256 thr) chunk: warp = 32M x 64N (kv only)
#define MMA_CHUNK_G(As, AW, Bs, BW, coff, acc, lane, wm, wn) do {                   \
    _Pragma("unroll")                                                               \
    for (int ks = 0; ks < 2; ks++) {                                                \
        uint32_t a_[2][4];                                                          \
        _Pragma("unroll")                                                           \
        for (int mi = 0; mi < 2; mi++)                                              \
            ldsm_x4(a_[mi], smem_u32(&(As)[((wm)*32 + mi*16 + ((lane)&15))*(AW)     \
                                          + ks*16 + ((lane)>>4)*8]));               \
        uint32_t b_[4][4];                                                          \
        _Pragma("unroll")                                                           \
        for (int ni = 0; ni < 4; ni++)                                              \
            ldsm_x4(b_[ni], smem_u32(&(Bs)[((wn)*64 + ni*16 + (((lane)>>4)&1)*8     \
                                            + ((lane)&7))*(BW)                      \
                                           + (coff) + ks*16 + (((lane)>>3)&1)*8])); \
        _Pragma("unroll")                                                           \
        for (int mi = 0; mi < 2; mi++) {                                            \
            _Pragma("unroll")                                                       \
            for (int ni = 0; ni < 4; ni++) {                                        \
                mma16816(acc[mi][ni*2],   a_[mi], b_[ni][0], b_[ni][1]);            \
                mma16816(acc[mi][ni*2+1], a_[mi], b_[ni][2], b_[ni][3]);            \
            }                                                                       \
        }                                                                           \
    }                                                                               \
} while (0)

// 4-warp (128 thr) chunk: warp = 64M x 64N (proj3/attn)
#define MMA_CHUNK4(As, AW, Bs, BW, coff, acc, lane, wm, wn) do {                    \
    _Pragma("unroll")                                                               \
    for (int ks = 0; ks < 2; ks++) {                                                \
        uint32_t a_[4][4];                                                          \
        _Pragma("unroll")                                                           \
        for (int mi = 0; mi < 4; mi++)                                              \
            ldsm_x4(a_[mi], smem_u32(&(As)[((wm)*64 + mi*16 + ((lane)&15))*(AW)     \
                                          + ks*16 + ((lane)>>4)*8]));               \
        uint32_t b_[4][4];                                                          \
        _Pragma("unroll")                                                           \
        for (int ni = 0; ni < 4; ni++)                                              \
            ldsm_x4(b_[ni], smem_u32(&(Bs)[((wn)*64 + ni*16 + (((lane)>>4)&1)*8     \
                                            + ((lane)&7))*(BW)                      \
                                           + (coff) + ks*16 + (((lane)>>3)&1)*8])); \
        _Pragma("unroll")                                                           \
        for (int mi = 0; mi < 4; mi++) {                                            \
            _Pragma("unroll")                                                       \
            for (int ni = 0; ni < 4; ni++) {                                        \
                mma16816(acc[mi][ni*2],   a_[mi], b_[ni][0], b_[ni][1]);            \
                mma16816(acc[mi][ni*2+1], a_[mi], b_[ni][2], b_[ni][3]);            \
            }                                                                       \
        }                                                                           \
    }                                                                               \
} while (0)

#define ACC_ZERO2(acc) do {                                                         \
    _Pragma("unroll")                                                               \
    for (int i_ = 0; i_ < 2; i_++) {                                                \
        _Pragma("unroll")                                                           \
        for (int j_ = 0; j_ < 8; j_++) {                                            \
            _Pragma("unroll")                                                       \
            for (int q_ = 0; q_ < 4; q_++) acc[i_][j_][q_] = 0.f;                   \
        }                                                                           \
    }                                                                               \
} while (0)

#define ACC_ZERO4(acc) do {                                                         \
    _Pragma("unroll")                                                               \
    for (int i_ = 0; i_ < 4; i_++) {                                                \
        _Pragma("unroll")                                                           \
        for (int j_ = 0; j_ < 8; j_++) {                                            \
            _Pragma("unroll")                                                       \
            for (int q_ = 0; q_ < 4; q_++) acc[i_][j_][q_] = 0.f;                   \
        }                                                                           \
    }                                                                               \
} while (0)

// ---------------- k_prep: t_x || cvtw || cvt_wc(c1) || cvt_wc(c2) ----------------
#define PREP_TX   4096
#define PREP_CVTW (PREP_TX + 768)
#define PREP_WC1  (PREP_CVTW + 2304)
#define PREP_TOT  (PREP_WC1 + 2304)
__global__ __launch_bounds__(256) void k_prep(const float* __restrict__ x,
                                              const float* __restrict__ qw,
                                              const float* __restrict__ kw,
                                              const float* __restrict__ vw,
                                              const float* __restrict__ c1w,
                                              const float* __restrict__ c2w)
{
    __shared__ __nv_bfloat16 sm[32][80];
    const int bx = blockIdx.x;
    const int tid = threadIdx.x;
    if (bx < PREP_TX) {
        int nx = bx & 127, cy = (bx >> 7) & 3, b = bx >> 9;
        int c0 = cy*64, n0 = nx*32;
        const float* in = x + ((size_t)b*CH + c0)*NPIX + n0;
        #pragma unroll
        for (int i = 0; i < 8; i++) {
            int e = tid + i*256;
            int c = e >> 5, n = e & 31;
            sm[n][c] = __float2bfloat16(in[(size_t)c*NPIX + n]);
        }
        __syncthreads();
        int n = tid >> 3, seg = tid & 7;
        *(uint4*)(g_xt + ((size_t)b*NPIX + n0+n)*256 + c0 + seg*8) = *(uint4*)&sm[n][seg*8];
    } else if (bx < PREP_CVTW) {
        int i = (bx - PREP_TX)*256 + tid;
        int which = i >> 16, r = i & 65535;
        const float* s = (which == 0) ? qw : (which == 1) ? kw : vw;
        g_wqkv[i] = __float2bfloat16(s[r]);
    } else if (bx < PREP_WC1) {
        int i = (bx - PREP_CVTW)*256 + tid;
        int c = i & 255, o = (i >> 8) & 255, t = i >> 16;
        g_wc1b[i] = __float2bfloat16(c1w[o*2304 + c*9 + t]);
    } else {
        int i = (bx - PREP_WC1)*256 + tid;
        int c = i & 255, o = (i >> 8) & 255, t = i >> 16;
        g_wc2b[i] = __float2bfloat16(c2w[o*2304 + c*9 + t]);
    }
}

// ---------------- k_mid: t_q || normsK ----------------
#define MID_TQ  2048
#define MID_TOT (MID_TQ + 128)
__global__ __launch_bounds__(256) void k_mid()
{
    __shared__ __nv_bfloat16 sm[64][80];
    const int bx = blockIdx.x;
    const int tid = threadIdx.x;
    if (bx < MID_TQ) {
        int n0 = (bx & 63)*64, c0 = ((bx >> 6) & 3)*64, b = bx >> 8;
        const __nv_bfloat16* in = g_Qbf + ((size_t)b*CH + c0)*NPIX + n0;
        #pragma unroll
        for (int i = 0; i < 8; i++) {
            int e = tid + i*256;
            int c = e >> 5, np = e & 31;
            __nv_bfloat162 v = *(const __nv_bfloat162*)(in + (size_t)c*NPIX + np*2);
            sm[np*2][c] = v.x;
            sm[np*2+1][c] = v.y;
        }
        __syncthreads();
        #pragma unroll
        for (int i = 0; i < 2; i++) {
            int e = tid + i*256;
            int n = e >> 3, seg = e & 7;
            *(uint4*)(g_Qt + ((size_t)b*NPIX + n0+n)*256 + c0 + seg*8) = *(uint4*)&sm[n][seg*8];
        }
    } else {
        int idx2 = (bx - MID_TQ)*256 + tid;
        int b = idx2 >> 11, n = (idx2 & 2047) * 2;
        const __nv_bfloat16* Kp = g_Kbf + (size_t)b*CH*NPIX + n;
        float sk0 = 0.f, sk1 = 0.f;
        #pragma unroll 16
        for (int c = 0; c < CH; c++) {
            __nv_bfloat162 k = *(const __nv_bfloat162*)(Kp + (size_t)c*NPIX);
            float kx = __bfloat162float(k.x), ky = __bfloat162float(k.y);
            sk0 = fmaf(kx, kx, sk0);
            sk1 = fmaf(ky, ky, sk1);
        }
        int o = b*NPIX + n;
        g_invK[o]   = 1.0f / sqrtf(sk0);
        g_invK[o+1] = 1.0f / sqrtf(sk1);
    }
}

// ---------------- fused QKV projection: 128 threads, 64x64 warp tiles ----------------
#define P3_BS_BYTES (128*LDB3*2)
#define P3_SMEM     (P3_BS_BYTES + 2*128*LDA*2)
__global__ __launch_bounds__(128) void k_proj3(const __nv_bfloat16* __restrict__ w3,
                                               const float* __restrict__ qb,
                                               const float* __restrict__ kb,
                                               const float* __restrict__ vb,
                                               __nv_bfloat16* __restrict__ outQ,
                                               __nv_bfloat16* __restrict__ outK,
                                               __nv_bfloat16* __restrict__ outV)
{
    extern __shared__ __align__(16) char dsm[];
    __nv_bfloat16* Bs = (__nv_bfloat16*)dsm;                 // [128][LDB3]
    __nv_bfloat16* As = (__nv_bfloat16*)(dsm + P3_BS_BYTES); // [2][128][LDA]
    const int b  = blockIdx.z;
    const int o0 = blockIdx.y * 128;
    const int n0 = blockIdx.x * 128;
    const __nv_bfloat16* xtb = g_xt + (size_t)b*NPIX*CH;
    const int tid = threadIdx.x;
    const int wid = tid >> 5, lane = tid & 31;
    const int wm = wid & 1, wn = wid >> 1;

    #pragma unroll
    for (int i = 0; i < 32; i++) {
        int e = tid + i*128;
        int n = e >> 5, seg = e & 31;
        *(uint4*)&Bs[n*LDB3 + seg*8] = *(const uint4*)(xtb + (size_t)(n0+n)*256 + seg*8);
    }

    float acc[4][8][4];
    const int r0 = lane >> 2, c2 = (lane & 3)*2;

    #pragma unroll
    for (int which = 0; which < 3; which++) {
        const __nv_bfloat16* w = w3 + (size_t)which*CH*CH;
        ACC_ZERO4(acc);
        #pragma unroll
        for (int i = 0; i < 4; i++) {
            int e = tid + i*128;
            int o = e >> 2, cq = e & 3;
            *(uint4*)&As[(0*128 + o)*LDA + cq*8] = *(const uint4*)(w + (size_t)(o0+o)*CH + cq*8);
        }
        for (int kc = 0; kc < 8; kc++) {
            __syncthreads();
            int buf = kc & 1;
            if (kc + 1 < 8) {
                int cb = (kc + 1) * 32;
                #pragma unroll
                for (int i = 0; i < 4; i++) {
                    int e = tid + i*128;
                    int o = e >> 2, cq = e & 3;
                    *(uint4*)&As[((buf^1)*128 + o)*LDA + cq*8] =
                        *(const uint4*)(w + (size_t)(o0+o)*CH + cb + cq*8);
                }
            }
            MMA_CHUNK4((As + buf*128*LDA), LDA, Bs, LDB3, kc*32, acc, lane, wm, wn);
        }
        const float* bias = (which == 0) ? qb : (which == 1) ? kb : vb;
        __nv_bfloat16* ob = ((which == 0) ? outQ : (which == 1) ? outK : outV)
                            + (size_t)b*CH*NPIX;
        #pragma unroll
        for (int mi = 0; mi < 4; mi++) {
            int o_lo = o0 + wm*64 + mi*16 + r0;
            int o_hi = o_lo + 8;
            float blo = bias[o_lo], bhi = bias[o_hi];
            #pragma unroll
            for (int nj = 0; nj < 8; nj++) {
                int n = n0 + wn*64 + nj*8 + c2;
                __nv_bfloat162 vlo, vhi;
                vlo.x = __float2bfloat16(acc[mi][nj][0] + blo);
                vlo.y = __float2bfloat16(acc[mi][nj][1] + blo);
                vhi.x = __float2bfloat16(acc[mi][nj][2] + bhi);
                vhi.y = __float2bfloat16(acc[mi][nj][3] + bhi);
                *(__nv_bfloat162*)(ob + (size_t)o_lo*NPIX + n) = vlo;
                *(__nv_bfloat162*)(ob + (size_t)o_hi*NPIX + n) = vhi;
            }
        }
    }
}

// ---------------- ksum / vsum; emits normalized Kn bf16 ----------------
__global__ __launch_bounds__(256) void k_colsums()
{
    int bc = blockIdx.x;
    int b = bc >> 8;
    const __nv_bfloat16* Kp = g_Kbf + (size_t)bc*NPIX;
    const __nv_bfloat16* Vp = g_Vbf + (size_t)bc*NPIX;
    const float* ik = g_invK + (size_t)b*NPIX;
    __nv_bfloat16* knp = g_Knbf + (size_t)bc*NPIX;
    int tid = threadIdx.x;
    float sk = 0.f, sv = 0.f;
    #pragma unroll
    for (int it = 0; it < 2; it++) {
        int base = (tid + it*256) * 8;
        uint4 kv4 = *(const uint4*)(Kp + base);
        uint4 vv4 = *(const uint4*)(Vp + base);
        float4 ika = *(const float4*)(ik + base);
        float4 ikb = *(const float4*)(ik + base + 4);
        const __nv_bfloat16* kk = (const __nv_bfloat16*)&kv4;
        const __nv_bfloat16* vv = (const __nv_bfloat16*)&vv4;
        float iks[8] = {ika.x, ika.y, ika.z, ika.w, ikb.x, ikb.y, ikb.z, ikb.w};
        unsigned short outw[8];
        #pragma unroll
        for (int j = 0; j < 8; j++) {
            float kn = __bfloat162float(kk[j]) * iks[j];
            __nv_bfloat16 knb = __float2bfloat16(kn);
            outw[j] = __bfloat16_as_ushort(knb);
            sk += kn;
            sv += __bfloat162float(vv[j]);
        }
        *(uint4*)(knp + base) = *(uint4*)outw;
    }
    __shared__ float rk[256], rv[256];
    rk[tid] = sk; rv[tid] = sv;
    __syncthreads();
    for (int s = 128; s > 0; s >>= 1) {
        if (tid < s) { rk[tid] += rk[tid+s]; rv[tid] += rv[tid+s]; }
        __syncthreads();
    }
    if (tid == 0) { g_ksum[bc] = rk[0]; g_vsum[bc] = rv[0]; }
}

// ---------------- k_post: kv GEMM || qstats || rv ----------------
#define POST_KV  128
#define POST_QS  (POST_KV + 1024)
#define POST_TOT (POST_QS + 8)
__global__ __launch_bounds__(256) void k_post(const float* __restrict__ rw)
{
    __shared__ __align__(16) __nv_bfloat16 As[2][128][LDA];
    __shared__ __align__(16) __nv_bfloat16 Bs[2][128][LDA];
    __shared__ float fs[256];
    const int bx = blockIdx.x;
    const int tid = threadIdx.x;
    if (bx < POST_KV) {
        const int c0 = (bx & 1) * 128;
        const int k0 = ((bx >> 1) & 1) * 128;
        const int bsp = bx >> 2;
        const int b = bsp >> 2, sp = bsp & 3;
        const int nb = sp * 1024;
        const __nv_bfloat16* Kn = g_Knbf + (size_t)b*CH*NPIX;
        const __nv_bfloat16* Vb = g_Vbf  + (size_t)b*CH*NPIX;
        const int wid = tid >> 5, lane = tid & 31;
        const int wm = wid & 3, wn = wid >> 2;

        float acc[2][8][4];
        ACC_ZERO2(acc);

        #pragma unroll
        for (int i = 0; i < 16; i++) {
            int e = tid + i*256;
            int r = e >> 5, n = e & 31;
            As[0][r][n] = Kn[(size_t)(k0+r)*NPIX + nb + n];
            Bs[0][r][n] = Vb[(size_t)(c0+r)*NPIX + nb + n];
        }
        for (int kc = 0; kc < 32; kc++) {
            __syncthreads();
            int buf = kc & 1;
            if (kc + 1 < 32) {
                int nn = nb + (kc + 1) * 32;
                #pragma unroll
                for (int i = 0; i < 16; i++) {
                    int e = tid + i*256;
                    int r = e >> 5, n = e & 31;
                    As[buf^1][r][n] = Kn[(size_t)(k0+r)*NPIX + nn + n];
                    Bs[buf^1][r][n] = Vb[(size_t)(c0+r)*NPIX + nn + n];
                }
            }
            MMA_CHUNK_G(&As[buf][0][0], LDA, &Bs[buf][0][0], LDA, 0, acc, lane, wm, wn);
        }
        float* ob = g_kvp + (size_t)bsp*CH*CH;
        const int r0 = lane >> 2, c2 = (lane & 3)*2;
        #pragma unroll
        for (int mi = 0; mi < 2; mi++) {
            int k_lo = k0 + wm*32 + mi*16 + r0;
            int k_hi = k_lo + 8;
            #pragma unroll
            for (int nj = 0; nj < 8; nj++) {
                int c = c0 + wn*64 + nj*8 + c2;
                *(float2*)(ob + (size_t)k_lo*CH + c) = make_float2(acc[mi][nj][0], acc[mi][nj][1]);
                *(float2*)(ob + (size_t)k_hi*CH + c) = make_float2(acc[mi][nj][2], acc[mi][nj][3]);
            }
        }
    } else if (bx < POST_QS) {
        const int bq = bx - POST_KV;
        const int lane = tid & 31, wid = tid >> 5;
        const int b = bq >> 7;
        fs[tid] = g_ksum[b*CH + tid];
        __syncthreads();
        const int t0 = bq*32 + wid*4;
        #pragma unroll
        for (int j = 0; j < 4; j++) {
            int t = t0 + j;
            uint4 v = *(const uint4*)(g_Qt + (size_t)t*256 + lane*8);
            const __nv_bfloat16* qq = (const __nv_bfloat16*)&v;
            float sq = 0.f, dt = 0.f;
            #pragma unroll
            for (int k = 0; k < 8; k++) {
                float f = __bfloat162float(qq[k]);
                sq = fmaf(f, f, sq);
                dt = fmaf(f, fs[lane*8 + k], dt);
            }
            #pragma unroll
            for (int m = 16; m > 0; m >>= 1) {
                sq += __shfl_xor_sync(0xffffffffu, sq, m);
                dt += __shfl_xor_sync(0xffffffffu, dt, m);
            }
            if (lane == 0) {
                float iq = 1.0f / sqrtf(sq);
                g_invQ[t] = iq;
                g_denom[t] = 1.0f / (4096.0f + dt*iq + 1e-6f);
            }
        }
    } else {
        const int b = bx - POST_QS;
        fs[tid] = g_vsum[b*CH + tid];
        __syncthreads();
        float s = 0.f;
        const float* rp = rw + (size_t)tid*CH;
        #pragma unroll 8
        for (int c = 0; c < CH; c++) s = fmaf(rp[c], fs[c], s);
        g_rv[b*CH + tid] = s;
    }
}

// ---------------- A = rw @ kv^T, kvred folded in ----------------
__global__ __launch_bounds__(256) void k_nt(const float* __restrict__ rw,
                                            __nv_bfloat16* __restrict__ out)
{
    __shared__ float As[32][65];
    __shared__ float Bs[32][65];
    const int b = blockIdx.z;
    const int i0 = blockIdx.y*64, j0 = blockIdx.x*64;
    const float* P = g_kvp + (size_t)b*4*65536;
    const int tid = threadIdx.x;
    const int ty = tid >> 4, tx = tid & 15;
    float acc[4][4];
    #pragma unroll
    for (int i = 0; i < 4; i++) {
        #pragma unroll
        for (int j = 0; j < 4; j++) acc[i][j] = 0.f;
    }

    for (int l0 = 0; l0 < CH; l0 += 32) {
        #pragma unroll
        for (int r = 0; r < 8; r++) {
            int e = tid + r*256;
            int ii = e >> 5, ll = e & 31;
            As[ll][ii] = rw[(size_t)(i0+ii)*CH + l0 + ll];
        }
        #pragma unroll
        for (int r = 0; r < 8; r++) {
            int e = tid + r*256;
            int jj = e >> 5, ll = e & 31;
            size_t off = (size_t)(j0+jj)*CH + l0 + ll;
            Bs[ll][jj] = (P[off] + P[65536 + off]) + (P[2*65536 + off] + P[3*65536 + off]);
        }
        __syncthreads();
        #pragma unroll
        for (int ll = 0; ll < 32; ll++) {
            float ar[4], br[4];
            #pragma unroll
            for (int i = 0; i < 4; i++) ar[i] = As[ll][ty*4+i];
            #pragma unroll
            for (int j = 0; j < 4; j++) br[j] = Bs[ll][tx*4+j];
            #pragma unroll
            for (int i = 0; i < 4; i++) {
                #pragma unroll
                for (int j = 0; j < 4; j++)
                    acc[i][j] = fmaf(ar[i], br[j], acc[i][j]);
            }
        }
        __syncthreads();
    }
    __nv_bfloat16* ob = out + (size_t)b*CH*CH;
    #pragma unroll
    for (int i = 0; i < 4; i++) {
        #pragma unroll
        for (int j = 0; j < 4; j++)
            ob[(size_t)(i0+ty*4+i)*CH + j0 + tx*4 + j] = __float2bfloat16(acc[i][j]);
    }
}

// ---------------- bf16 MMA attn GEMM: 128 threads, 64x64 warp tiles ----------------
__global__ __launch_bounds__(128) void k_attn_tc(const float* __restrict__ rb)
{
    __shared__ __align__(16) __nv_bfloat16 As[2][128][LDA];
    __shared__ __align__(16) __nv_bfloat16 Bs[2][128][LDA];
    const int b  = blockIdx.z;
    const int o0 = blockIdx.y * 128;
    const int n0 = blockIdx.x * 128;
    const __nv_bfloat16* Am = g_Abf + (size_t)b*CH*CH;
    const __nv_bfloat16* Qt = g_Qt + (size_t)b*NPIX*CH;
    const int tid = threadIdx.x;
    const int wid = tid >> 5, lane = tid & 31;
    const int wm = wid & 1, wn = wid >> 1;

    float acc[4][8][4];
    ACC_ZERO4(acc);

    #pragma unroll
    for (int i = 0; i < 4; i++) {
        int e = tid + i*128;
        int o = e >> 2, cq = e & 3;
        *(uint4*)&As[0][o][cq*8] = *(const uint4*)(Am + (size_t)(o0+o)*CH + cq*8);
    }
    #pragma unroll
    for (int i = 0; i < 4; i++) {
        int e = tid + i*128;
        int n = e >> 2, cq = e & 3;
        *(uint4*)&Bs[0][n][cq*8] = *(const uint4*)(Qt + (size_t)(n0+n)*256 + cq*8);
    }

    for (int kc = 0; kc < 8; kc++) {
        __syncthreads();
        int buf = kc & 1;
        if (kc + 1 < 8) {
            int cb = (kc + 1) * 32;
            #pragma unroll
            for (int i = 0; i < 4; i++) {
                int e = tid + i*128;
                int o = e >> 2, cq = e & 3;
                *(uint4*)&As[buf^1][o][cq*8] = *(const uint4*)(Am + (size_t)(o0+o)*CH + cb + cq*8);
            }
            #pragma unroll
            for (int i = 0; i < 4; i++) {
                int e = tid + i*128;
                int n = e >> 2, cq = e & 3;
                *(uint4*)&Bs[buf^1][n][cq*8] = *(const uint4*)(Qt + (size_t)(n0+n)*256 + cb + cq*8);
            }
        }
        MMA_CHUNK4(&As[buf][0][0], LDA, &Bs[buf][0][0], LDA, 0, acc, lane, wm, wn);
    }

    __nv_bfloat16* ob = g_attnbf + (size_t)b*CH*NPIX;
    const int r0 = lane >> 2, c2 = (lane & 3)*2;
    #pragma unroll
    for (int mi = 0; mi < 4; mi++) {
        int o_lo = o0 + wm*64 + mi*16 + r0;
        int o_hi = o_lo + 8;
        float rvlo = g_rv[b*CH + o_lo], rvhi = g_rv[b*CH + o_hi];
        float rblo = rb[o_lo], rbhi = rb[o_hi];
        #pragma unroll
        for (int nj = 0; nj < 8; nj++) {
            int n = n0 + wn*64 + nj*8 + c2;
            float iq0 = g_invQ[b*NPIX + n],     dn0 = g_denom[b*NPIX + n];
            float iq1 = g_invQ[b*NPIX + n + 1], dn1 = g_denom[b*NPIX + n + 1];
            __nv_bfloat162 vlo, vhi;
            vlo.x = __float2bfloat16(fmaf(fmaf(iq0, acc[mi][nj][0], rvlo), dn0, rblo));
            vlo.y = __float2bfloat16(fmaf(fmaf(iq1, acc[mi][nj][1], rvlo), dn1, rblo));
            vhi.x = __float2bfloat16(fmaf(fmaf(iq0, acc[mi][nj][2], rvhi), dn0, rbhi));
            vhi.y = __float2bfloat16(fmaf(fmaf(iq1, acc[mi][nj][3], rvhi), dn1, rbhi));
            *(__nv_bfloat162*)(ob + (size_t)o_lo*NPIX + n) = vlo;
            *(__nv_bfloat162*)(ob + (size_t)o_hi*NPIX + n) = vhi;
        }
    }
}

// ---------------- bf16 MMA 3x3 conv: 4 warps, 64x64 warp tiles ----------------
#define CONV_BW_WORDS (8*GST)
#define CONV_A_BYTES  (9*128*LDA*2)
#define CONV_SMEM     (CONV_A_BYTES + CONV_BW_WORDS*4)

__device__ __forceinline__ void conv_fillB4(uint32_t* __restrict__ Bw,
                                            const __nv_bfloat16* __restrict__ inb,
                                            int cbase, int pr0, int tid)
{
    #pragma unroll
    for (int it = 0; it < 4; it++) {
        int e = tid + it*128;
        int kw = e >> 5;
        int row = (e >> 3) & 3;
        int seg = e & 7;
        int g = (kw & 3) + ((kw >> 3) << 2);
        int s = (kw >> 2) & 1;
        int gr = pr0 - 1 + row;
        uint32_t* dst = Bw + g*GST + (row*66 + 1 + seg*8)*2 + s;
        if ((unsigned)gr < IMW) {
            const __nv_bfloat16* q = inb + (size_t)(cbase + kw*2)*NPIX + gr*IMW + seg*8;
            uint4 lo4 = *(const uint4*)q;
            uint4 hi4 = *(const uint4*)(q + NPIX);
            const unsigned short* ls = (const unsigned short*)&lo4;
            const unsigned short* hs = (const unsigned short*)&hi4;
            #pragma unroll
            for (int j = 0; j < 8; j++)
                dst[j*2] = (uint32_t)ls[j] | ((uint32_t)hs[j] << 16);
        } else {
            #pragma unroll
            for (int j = 0; j < 8; j++) dst[j*2] = 0u;
        }
    }
}

__global__ __launch_bounds__(128) void k_conv_tc(const __nv_bfloat16* __restrict__ in,
                                                 const __nv_bfloat16* __restrict__ wt,
                                                 const float* __restrict__ bias,
                                                 const float* __restrict__ xres,
                                                 float* __restrict__ out_f,
                                                 __nv_bfloat16* __restrict__ out_bf,
                                                 int fuse)
{
    extern __shared__ __align__(16) char dsm[];
    __nv_bfloat16* Asm = (__nv_bfloat16*)dsm;
    uint32_t* Bw = (uint32_t*)(dsm + CONV_A_BYTES);
    const int b   = blockIdx.z;
    const int o0  = blockIdx.y * 128;
    const int pr0 = blockIdx.x * 2;
    const __nv_bfloat16* inb = in + (size_t)b*CH*NPIX;
    const int tid = threadIdx.x;
    const int wid = tid >> 5, lane = tid & 31;
    const int wm = wid & 1;
    const int wn = wid >> 1;

    float acc[4][8][4];
    ACC_ZERO4(acc);

    {
        int kw = tid >> 3;
        int row = (tid >> 1) & 3;
        int side = tid & 1;
        int g = (kw & 3) + ((kw >> 3) << 2);
        int s = (kw >> 2) & 1;
        Bw[g*GST + (row*66 + side*65)*2 + s] = 0u;
    }

    for (int cb = 0; cb < 8; cb++) {
        __syncthreads();
        #pragma unroll
        for (int i = 0; i < 36; i++) {
            int e = tid + i*128;
            int t = e >> 9;
            int rem = e & 511;
            int o = rem >> 2, cq = rem & 3;
            *(uint4*)(Asm + ((size_t)t*128 + o)*LDA + cq*8) =
                *(const uint4*)(wt + ((size_t)t*256 + o0 + o)*256 + cb*32 + cq*8);
        }
        conv_fillB4(Bw, inb, cb*32, pr0, tid);
        __syncthreads();
        #pragma unroll
        for (int t = 0; t < 9; t++) {
            const int dy = t / 3 - 1, dx = t % 3 - 1;
            const int pos0 = (1 + wn + dy) * 66 + 1 + dx;
            #pragma unroll
            for (int ks = 0; ks < 2; ks++) {
                uint32_t a_[4][4];
                #pragma unroll
                for (int mi = 0; mi < 4; mi++)
                    ldsm_x4(a_[mi], smem_u32(Asm + ((size_t)t*128 + wm*64 + mi*16 + (lane&15))*LDA
                                             + ks*16 + (lane>>4)*8));
                const uint32_t* bp = Bw + ((lane&3) + ks*4)*GST
                                   + (pos0 + (lane>>2))*2;
                #pragma unroll
                for (int f = 0; f < 8; f++) {
                    uint2 bb = *(const uint2*)(bp + f*16);
                    #pragma unroll
                    for (int mi = 0; mi < 4; mi++)
                        mma16816(acc[mi][f], a_[mi], bb.x, bb.y);
                }
            }
        }
    }

    const int r0 = lane >> 2, c2 = (lane & 3)*2;
    const int pxbase = pr0*64;
    if (fuse) {
        const float* xb = xres + (size_t)b*CH*NPIX;
        float* ob = out_f + (size_t)b*CH*NPIX;
        #pragma unroll
        for (int mi = 0; mi < 4; mi++) {
            int o_lo = o0 + wm*64 + mi*16 + r0;
            int o_hi = o_lo + 8;
            float blo = bias[o_lo], bhi = bias[o_hi];
            #pragma unroll
            for (int f = 0; f < 8; f++) {
                int px = pxbase + wn*64 + f*8 + c2;
                float a0 = acc[mi][f][0] + blo, a1 = acc[mi][f][1] + blo;
                float a2 = acc[mi][f][2] + bhi, a3 = acc[mi][f][3] + bhi;
                float2 xlo = *(const float2*)(xb + (size_t)o_lo*NPIX + px);
                float2 xhi = *(const float2*)(xb + (size_t)o_hi*NPIX + px);
                a0 = fmaf(a0, xlo.x, xlo.x);
                a1 = fmaf(a1, xlo.y, xlo.y);
                a2 = fmaf(a2, xhi.x, xhi.x);
                a3 = fmaf(a3, xhi.y, xhi.y);
                *(float2*)(ob + (size_t)o_lo*NPIX + px) = make_float2(a0, a1);
                *(float2*)(ob + (size_t)o_hi*NPIX + px) = make_float2(a2, a3);
            }
        }
    } else {
        __nv_bfloat16* ob = out_bf + (size_t)b*CH*NPIX;
        #pragma unroll
        for (int mi = 0; mi < 4; mi++) {
            int o_lo = o0 + wm*64 + mi*16 + r0;
            int o_hi = o_lo + 8;
            float blo = bias[o_lo], bhi = bias[o_hi];
            #pragma unroll
            for (int f = 0; f < 8; f++) {
                int px = pxbase + wn*64 + f*8 + c2;
                __nv_bfloat162 vlo, vhi;
                vlo.x = __float2bfloat16(acc[mi][f][0] + blo);
                vlo.y = __float2bfloat16(acc[mi][f][1] + blo);
                vhi.x = __float2bfloat16(acc[mi][f][2] + bhi);
                vhi.y = __float2bfloat16(acc[mi][f][3] + bhi);
                *(__nv_bfloat162*)(ob + (size_t)o_lo*NPIX + px) = vlo;
                *(__nv_bfloat162*)(ob + (size_t)o_hi*NPIX + px) = vhi;
            }
        }
    }
}

// ---------------- launcher ----------------
extern "C" void kernel_launch(void* const* d_in, const int* in_sizes, int n_in,
                              void* d_out, int out_size)
{
    (void)in_sizes; (void)n_in; (void)out_size;
    const float* x   = (const float*)d_in[0];
    const float* qw  = (const float*)d_in[1];
    const float* qb  = (const float*)d_in[2];
    const float* kw  = (const float*)d_in[3];
    const float* kb  = (const float*)d_in[4];
    const float* vw  = (const float*)d_in[5];
    const float* vb  = (const float*)d_in[6];
    const float* rw  = (const float*)d_in[7];
    const float* rb  = (const float*)d_in[8];
    const float* c1w = (const float*)d_in[9];
    const float* c1b = (const float*)d_in[10];
    const float* c2w = (const float*)d_in[11];
    const float* c2b = (const float*)d_in[12];
    float* out = (float*)d_out;

    __nv_bfloat16 *pQbf, *pKbf, *pVbf, *pattnbf, *ph1bf, *pAbf, *pwqkv, *pwc1, *pwc2;
    cudaGetSymbolAddress((void**)&pQbf,   g_Qbf);
    cudaGetSymbolAddress((void**)&pKbf,   g_Kbf);
    cudaGetSymbolAddress((void**)&pVbf,   g_Vbf);
    cudaGetSymbolAddress((void**)&pattnbf,g_attnbf);
    cudaGetSymbolAddress((void**)&ph1bf,  g_h1bf);
    cudaGetSymbolAddress((void**)&pAbf,   g_Abf);
    cudaGetSymbolAddress((void**)&pwqkv,  g_wqkv);
    cudaGetSymbolAddress((void**)&pwc1,   g_wc1b);
    cudaGetSymbolAddress((void**)&pwc2,   g_wc2b);

    static int attr_set = 0;
    if (!attr_set) {
        cudaFuncSetAttribute(k_proj3,   cudaFuncAttributeMaxDynamicSharedMemorySize, P3_SMEM);
        cudaFuncSetAttribute(k_conv_tc, cudaFuncAttributeMaxDynamicSharedMemorySize, CONV_SMEM);
        attr_set = 1;
    }

    dim3 gproj(32, 2, BSZ);
    dim3 gnt(4, 4, BSZ);
    dim3 gconv(32, 2, BSZ);

    k_prep<<<PREP_TOT, 256>>>(x, qw, kw, vw, c1w, c2w);
    k_proj3<<<gproj, 128, P3_SMEM>>>(pwqkv, qb, kb, vb, pQbf, pKbf, pVbf);
    k_mid<<<MID_TOT, 256>>>();
    k_colsums<<<BSZ*CH, 256>>>();
    k_post<<<POST_TOT, 256>>>(rw);
    k_nt<<<gnt, 256>>>(rw, pAbf);
    k_attn_tc<<<gproj, 128>>>(rb);
    k_conv_tc<<<gconv, 128, CONV_SMEM>>>(pattnbf, pwc1, c1b, (const float*)0, (float*)0, ph1bf, 0);
    k_conv_tc<<<gconv, 128, CONV_SMEM>>>(ph1bf, pwc2, c2b, x, out, (__nv_bfloat16*)0, 1);
}

// round 13
// speedup vs baseline: 7.5732x; 1.0302x over previous
#include <cuda_runtime.h>
#include <cuda_bf16.h>
#include <math.h>
#include <cstdint>

#define BSZ  8
#define CH   256
#define NPIX 4096
#define IMW  64
#define LDA  40   // bf16 elems per smem row (80B, conflict-free ldmatrix)
#define LDB3 264  // proj3 shared-B row width
#define GST  536  // conv B group stride (words)

// ---------------- scratch (device globals; alloc-free) ----------------
__device__ float g_invQ[BSZ*NPIX];
__device__ float g_invK[BSZ*NPIX];
__device__ float g_ksum[BSZ*CH];
__device__ float g_vsum[BSZ*CH];
__device__ float g_kvp[BSZ*4*CH*CH];
__device__ float g_rv[BSZ*CH];
__device__ float g_denom[BSZ*NPIX];
// bf16 operands
__device__ __nv_bfloat16 g_xt[BSZ*NPIX*CH];
__device__ __nv_bfloat16 g_Qt[BSZ*NPIX*CH];     // Q transposed [b][n][c] (written by proj3)
__device__ __nv_bfloat16 g_Kbf[BSZ*CH*NPIX];
__device__ __nv_bfloat16 g_Vbf[BSZ*CH*NPIX];
__device__ __nv_bfloat16 g_Knbf[BSZ*CH*NPIX];
__device__ __nv_bfloat16 g_attnbf[BSZ*CH*NPIX];
__device__ __nv_bfloat16 g_h1bf[BSZ*CH*NPIX];
__device__ __nv_bfloat16 g_Abf[BSZ*CH*CH];
__device__ __nv_bfloat16 g_wqkv[3*CH*CH];
__device__ __nv_bfloat16 g_wc1b[9*CH*CH];
__device__ __nv_bfloat16 g_wc2b[9*CH*CH];

// ================= warp-MMA helpers =================
__device__ __forceinline__ uint32_t smem_u32(const void* p) {
    uint32_t a;
    asm("{ .reg .u64 t; cvta.to.shared.u64 t, %1; cvt.u32.u64 %0, t; }" : "=r"(a) : "l"(p));
    return a;
}
__device__ __forceinline__ void ldsm_x4(uint32_t (&r)[4], uint32_t addr) {
    asm volatile("ldmatrix.sync.aligned.m8n8.x4.shared.b16 {%0,%1,%2,%3}, [%4];"
        : "=r"(r[0]), "=r"(r[1]), "=r"(r[2]), "=r"(r[3]) : "r"(addr));
}
__device__ __forceinline__ void mma16816(float (&d)[4], const uint32_t (&a)[4],
                                         uint32_t b0, uint32_t b1) {
    asm volatile("mma.sync.aligned.m16n8k16.row.col.f32.bf16.bf16.f32 "
        "{%0,%1,%2,%3}, {%4,%5,%6,%7}, {%8,%9}, {%0,%1,%2,%3};"
        : "+f"(d[0]), "+f"(d[1]), "+f"(d[2]), "+f"(d[3])
        : "r"(a[0]), "r"(a[1]), "r"(a[2]), "r"(a[3]), "r"(b0), "r"(b1));
}

// 8-warp (256 thr) chunk: warp = 32M x 64N (kv only)
#define MMA_CHUNK_G(As, AW, Bs, BW, coff, acc, lane, wm, wn) do {                   \
    _Pragma("unroll")                                                               \
    for (int ks = 0; ks < 2; ks++) {                                                \
        uint32_t a_[2][4];                                                          \
        _Pragma("unroll")                                                           \
        for (int mi = 0; mi < 2; mi++)                                              \
            ldsm_x4(a_[mi], smem_u32(&(As)[((wm)*32 + mi*16 + ((lane)&15))*(AW)     \
                                          + ks*16 + ((lane)>>4)*8]));               \
        uint32_t b_[4][4];                                                          \
        _Pragma("unroll")                                                           \
        for (int ni = 0; ni < 4; ni++)                                              \
            ldsm_x4(b_[ni], smem_u32(&(Bs)[((wn)*64 + ni*16 + (((lane)>>4)&1)*8     \
                                            + ((lane)&7))*(BW)                      \
                                           + (coff) + ks*16 + (((lane)>>3)&1)*8])); \
        _Pragma("unroll")                                                           \
        for (int mi = 0; mi < 2; mi++) {                                            \
            _Pragma("unroll")                                                       \
            for (int ni = 0; ni < 4; ni++) {                                        \
                mma16816(acc[mi][ni*2],   a_[mi], b_[ni][0], b_[ni][1]);            \
                mma16816(acc[mi][ni*2+1], a_[mi], b_[ni][2], b_[ni][3]);            \
            }                                                                       \
        }                                                                           \
    }                                                                               \
} while (0)

// 4-warp (128 thr) chunk: warp = 64M x 64N (proj3/attn)
#define MMA_CHUNK4(As, AW, Bs, BW, coff, acc, lane, wm, wn) do {                    \
    _Pragma("unroll")                                                               \
    for (int ks = 0; ks < 2; ks++) {                                                \
        uint32_t a_[4][4];                                                          \
        _Pragma("unroll")                                                           \
        for (int mi = 0; mi < 4; mi++)                                              \
            ldsm_x4(a_[mi], smem_u32(&(As)[((wm)*64 + mi*16 + ((lane)&15))*(AW)     \
                                          + ks*16 + ((lane)>>4)*8]));               \
        uint32_t b_[4][4];                                                          \
        _Pragma("unroll")                                                           \
        for (int ni = 0; ni < 4; ni++)                                              \
            ldsm_x4(b_[ni], smem_u32(&(Bs)[((wn)*64 + ni*16 + (((lane)>>4)&1)*8     \
                                            + ((lane)&7))*(BW)                      \
                                           + (coff) + ks*16 + (((lane)>>3)&1)*8])); \
        _Pragma("unroll")                                                           \
        for (int mi = 0; mi < 4; mi++) {                                            \
            _Pragma("unroll")                                                       \
            for (int ni = 0; ni < 4; ni++) {                                        \
                mma16816(acc[mi][ni*2],   a_[mi], b_[ni][0], b_[ni][1]);            \
                mma16816(acc[mi][ni*2+1], a_[mi], b_[ni][2], b_[ni][3]);            \
            }                                                                       \
        }                                                                           \
    }                                                                               \
} while (0)

#define ACC_ZERO2(acc) do {                                                         \
    _Pragma("unroll")                                                               \
    for (int i_ = 0; i_ < 2; i_++) {                                                \
        _Pragma("unroll")                                                           \
        for (int j_ = 0; j_ < 8; j_++) {                                            \
            _Pragma("unroll")                                                       \
            for (int q_ = 0; q_ < 4; q_++) acc[i_][j_][q_] = 0.f;                   \
        }                                                                           \
    }                                                                               \
} while (0)

#define ACC_ZERO4(acc) do {                                                         \
    _Pragma("unroll")                                                               \
    for (int i_ = 0; i_ < 4; i_++) {                                                \
        _Pragma("unroll")                                                           \
        for (int j_ = 0; j_ < 8; j_++) {                                            \
            _Pragma("unroll")                                                       \
            for (int q_ = 0; q_ < 4; q_++) acc[i_][j_][q_] = 0.f;                   \
        }                                                                           \
    }                                                                               \
} while (0)

// ---------------- k_prep: t_x || cvtw || cvt_wc(c1) || cvt_wc(c2) ----------------
#define PREP_TX   4096
#define PREP_CVTW (PREP_TX + 768)
#define PREP_WC1  (PREP_CVTW + 2304)
#define PREP_TOT  (PREP_WC1 + 2304)
__global__ __launch_bounds__(256) void k_prep(const float* __restrict__ x,
                                              const float* __restrict__ qw,
                                              const float* __restrict__ kw,
                                              const float* __restrict__ vw,
                                              const float* __restrict__ c1w,
                                              const float* __restrict__ c2w)
{
    __shared__ __nv_bfloat16 sm[32][80];
    const int bx = blockIdx.x;
    const int tid = threadIdx.x;
    if (bx < PREP_TX) {
        int nx = bx & 127, cy = (bx >> 7) & 3, b = bx >> 9;
        int c0 = cy*64, n0 = nx*32;
        const float* in = x + ((size_t)b*CH + c0)*NPIX + n0;
        #pragma unroll
        for (int i = 0; i < 8; i++) {
            int e = tid + i*256;
            int c = e >> 5, n = e & 31;
            sm[n][c] = __float2bfloat16(in[(size_t)c*NPIX + n]);
        }
        __syncthreads();
        int n = tid >> 3, seg = tid & 7;
        *(uint4*)(g_xt + ((size_t)b*NPIX + n0+n)*256 + c0 + seg*8) = *(uint4*)&sm[n][seg*8];
    } else if (bx < PREP_CVTW) {
        int i = (bx - PREP_TX)*256 + tid;
        int which = i >> 16, r = i & 65535;
        const float* s = (which == 0) ? qw : (which == 1) ? kw : vw;
        g_wqkv[i] = __float2bfloat16(s[r]);
    } else if (bx < PREP_WC1) {
        int i = (bx - PREP_CVTW)*256 + tid;
        int c = i & 255, o = (i >> 8) & 255, t = i >> 16;
        g_wc1b[i] = __float2bfloat16(c1w[o*2304 + c*9 + t]);
    } else {
        int i = (bx - PREP_WC1)*256 + tid;
        int c = i & 255, o = (i >> 8) & 255, t = i >> 16;
        g_wc2b[i] = __float2bfloat16(c2w[o*2304 + c*9 + t]);
    }
}

// ---------------- k_mid: invK only (t_q eliminated) ----------------
__global__ __launch_bounds__(256) void k_mid()
{
    int idx2 = blockIdx.x*256 + threadIdx.x;
    int b = idx2 >> 11, n = (idx2 & 2047) * 2;
    const __nv_bfloat16* Kp = g_Kbf + (size_t)b*CH*NPIX + n;
    float sk0 = 0.f, sk1 = 0.f;
    #pragma unroll 16
    for (int c = 0; c < CH; c++) {
        __nv_bfloat162 k = *(const __nv_bfloat162*)(Kp + (size_t)c*NPIX);
        float kx = __bfloat162float(k.x), ky = __bfloat162float(k.y);
        sk0 = fmaf(kx, kx, sk0);
        sk1 = fmaf(ky, ky, sk1);
    }
    int o = b*NPIX + n;
    g_invK[o]   = 1.0f / sqrtf(sk0);
    g_invK[o+1] = 1.0f / sqrtf(sk1);
}

// ---------------- fused QKV projection (K, V, then Q -> writes Qt directly) --------
#define P3_BS_BYTES (128*LDB3*2)
#define P3_SMEM     (P3_BS_BYTES + 2*128*LDA*2)
__global__ __launch_bounds__(128) void k_proj3(const __nv_bfloat16* __restrict__ w3,
                                               const float* __restrict__ qb,
                                               const float* __restrict__ kb,
                                               const float* __restrict__ vb,
                                               __nv_bfloat16* __restrict__ outK,
                                               __nv_bfloat16* __restrict__ outV)
{
    extern __shared__ __align__(16) char dsm[];
    __nv_bfloat16* Bs = (__nv_bfloat16*)dsm;                 // [128][LDB3]
    __nv_bfloat16* As = (__nv_bfloat16*)(dsm + P3_BS_BYTES); // [2][128][LDA]
    const int b  = blockIdx.z;
    const int o0 = blockIdx.y * 128;
    const int n0 = blockIdx.x * 128;
    const __nv_bfloat16* xtb = g_xt + (size_t)b*NPIX*CH;
    const int tid = threadIdx.x;
    const int wid = tid >> 5, lane = tid & 31;
    const int wm = wid & 1, wn = wid >> 1;

    #pragma unroll
    for (int i = 0; i < 32; i++) {
        int e = tid + i*128;
        int n = e >> 5, seg = e & 31;
        *(uint4*)&Bs[n*LDB3 + seg*8] = *(const uint4*)(xtb + (size_t)(n0+n)*256 + seg*8);
    }

    float acc[4][8][4];
    const int r0 = lane >> 2, c2 = (lane & 3)*2;

    // stream order: 0=K (w3+1), 1=V (w3+2), 2=Q (w3+0, written transposed)
    #pragma unroll
    for (int pass = 0; pass < 3; pass++) {
        const int which = (pass == 0) ? 1 : (pass == 1) ? 2 : 0;
        const __nv_bfloat16* w = w3 + (size_t)which*CH*CH;
        ACC_ZERO4(acc);
        #pragma unroll
        for (int i = 0; i < 4; i++) {
            int e = tid + i*128;
            int o = e >> 2, cq = e & 3;
            *(uint4*)&As[(0*128 + o)*LDA + cq*8] = *(const uint4*)(w + (size_t)(o0+o)*CH + cq*8);
        }
        for (int kc = 0; kc < 8; kc++) {
            __syncthreads();
            int buf = kc & 1;
            if (kc + 1 < 8) {
                int cb = (kc + 1) * 32;
                #pragma unroll
                for (int i = 0; i < 4; i++) {
                    int e = tid + i*128;
                    int o = e >> 2, cq = e & 3;
                    *(uint4*)&As[((buf^1)*128 + o)*LDA + cq*8] =
                        *(const uint4*)(w + (size_t)(o0+o)*CH + cb + cq*8);
                }
            }
            MMA_CHUNK4((As + buf*128*LDA), LDA, Bs, LDB3, kc*32, acc, lane, wm, wn);
        }
        if (pass < 2) {
            const float* bias = (pass == 0) ? kb : vb;
            __nv_bfloat16* ob = ((pass == 0) ? outK : outV) + (size_t)b*CH*NPIX;
            #pragma unroll
            for (int mi = 0; mi < 4; mi++) {
                int o_lo = o0 + wm*64 + mi*16 + r0;
                int o_hi = o_lo + 8;
                float blo = bias[o_lo], bhi = bias[o_hi];
                #pragma unroll
                for (int nj = 0; nj < 8; nj++) {
                    int n = n0 + wn*64 + nj*8 + c2;
                    __nv_bfloat162 vlo, vhi;
                    vlo.x = __float2bfloat16(acc[mi][nj][0] + blo);
                    vlo.y = __float2bfloat16(acc[mi][nj][1] + blo);
                    vhi.x = __float2bfloat16(acc[mi][nj][2] + bhi);
                    vhi.y = __float2bfloat16(acc[mi][nj][3] + bhi);
                    *(__nv_bfloat162*)(ob + (size_t)o_lo*NPIX + n) = vlo;
                    *(__nv_bfloat162*)(ob + (size_t)o_hi*NPIX + n) = vhi;
                }
            }
        } else {
            // Q pass: stage [n][o] into Bs (done with x tile), then write Qt coalesced
            __syncthreads();        // everyone done reading Bs (last chunk MMAs)
            #pragma unroll
            for (int mi = 0; mi < 4; mi++) {
                int o_lo = wm*64 + mi*16 + r0;
                int o_hi = o_lo + 8;
                float blo = qb[o0 + o_lo], bhi = qb[o0 + o_hi];
                #pragma unroll
                for (int nj = 0; nj < 8; nj++) {
                    int n = wn*64 + nj*8 + c2;
                    Bs[(size_t)n*LDB3 + o_lo]     = __float2bfloat16(acc[mi][nj][0] + blo);
                    Bs[(size_t)(n+1)*LDB3 + o_lo] = __float2bfloat16(acc[mi][nj][1] + blo);
                    Bs[(size_t)n*LDB3 + o_hi]     = __float2bfloat16(acc[mi][nj][2] + bhi);
                    Bs[(size_t)(n+1)*LDB3 + o_hi] = __float2bfloat16(acc[mi][nj][3] + bhi);
                }
            }
            __syncthreads();
            __nv_bfloat16* qt = g_Qt + (size_t)b*NPIX*CH;
            #pragma unroll
            for (int i = 0; i < 16; i++) {
                int e = tid + i*128;
                int n = e >> 4, seg = e & 15;
                *(uint4*)(qt + (size_t)(n0+n)*256 + o0 + seg*8) = *(uint4*)&Bs[(size_t)n*LDB3 + seg*8];
            }
        }
    }
}

// ---------------- ksum / vsum; emits normalized Kn bf16 ----------------
__global__ __launch_bounds__(256) void k_colsums()
{
    int bc = blockIdx.x;
    int b = bc >> 8;
    const __nv_bfloat16* Kp = g_Kbf + (size_t)bc*NPIX;
    const __nv_bfloat16* Vp = g_Vbf + (size_t)bc*NPIX;
    const float* ik = g_invK + (size_t)b*NPIX;
    __nv_bfloat16* knp = g_Knbf + (size_t)bc*NPIX;
    int tid = threadIdx.x;
    float sk = 0.f, sv = 0.f;
    #pragma unroll
    for (int it = 0; it < 2; it++) {
        int base = (tid + it*256) * 8;
        uint4 kv4 = *(const uint4*)(Kp + base);
        uint4 vv4 = *(const uint4*)(Vp + base);
        float4 ika = *(const float4*)(ik + base);
        float4 ikb = *(const float4*)(ik + base + 4);
        const __nv_bfloat16* kk = (const __nv_bfloat16*)&kv4;
        const __nv_bfloat16* vv = (const __nv_bfloat16*)&vv4;
        float iks[8] = {ika.x, ika.y, ika.z, ika.w, ikb.x, ikb.y, ikb.z, ikb.w};
        unsigned short outw[8];
        #pragma unroll
        for (int j = 0; j < 8; j++) {
            float kn = __bfloat162float(kk[j]) * iks[j];
            __nv_bfloat16 knb = __float2bfloat16(kn);
            outw[j] = __bfloat16_as_ushort(knb);
            sk += kn;
            sv += __bfloat162float(vv[j]);
        }
        *(uint4*)(knp + base) = *(uint4*)outw;
    }
    __shared__ float rk[256], rv[256];
    rk[tid] = sk; rv[tid] = sv;
    __syncthreads();
    for (int s = 128; s > 0; s >>= 1) {
        if (tid < s) { rk[tid] += rk[tid+s]; rv[tid] += rv[tid+s]; }
        __syncthreads();
    }
    if (tid == 0) { g_ksum[bc] = rk[0]; g_vsum[bc] = rv[0]; }
}

// ---------------- k_post: kv GEMM || qstats || rv ----------------
#define POST_KV  128
#define POST_QS  (POST_KV + 1024)
#define POST_TOT (POST_QS + 8)
__global__ __launch_bounds__(256) void k_post(const float* __restrict__ rw)
{
    __shared__ __align__(16) __nv_bfloat16 As[2][128][LDA];
    __shared__ __align__(16) __nv_bfloat16 Bs[2][128][LDA];
    __shared__ float fs[256];
    const int bx = blockIdx.x;
    const int tid = threadIdx.x;
    if (bx < POST_KV) {
        const int c0 = (bx & 1) * 128;
        const int k0 = ((bx >> 1) & 1) * 128;
        const int bsp = bx >> 2;
        const int b = bsp >> 2, sp = bsp & 3;
        const int nb = sp * 1024;
        const __nv_bfloat16* Kn = g_Knbf + (size_t)b*CH*NPIX;
        const __nv_bfloat16* Vb = g_Vbf  + (size_t)b*CH*NPIX;
        const int wid = tid >> 5, lane = tid & 31;
        const int wm = wid & 3, wn = wid >> 2;

        float acc[2][8][4];
        ACC_ZERO2(acc);

        #pragma unroll
        for (int i = 0; i < 16; i++) {
            int e = tid + i*256;
            int r = e >> 5, n = e & 31;
            As[0][r][n] = Kn[(size_t)(k0+r)*NPIX + nb + n];
            Bs[0][r][n] = Vb[(size_t)(c0+r)*NPIX + nb + n];
        }
        for (int kc = 0; kc < 32; kc++) {
            __syncthreads();
            int buf = kc & 1;
            if (kc + 1 < 32) {
                int nn = nb + (kc + 1) * 32;
                #pragma unroll
                for (int i = 0; i < 16; i++) {
                    int e = tid + i*256;
                    int r = e >> 5, n = e & 31;
                    As[buf^1][r][n] = Kn[(size_t)(k0+r)*NPIX + nn + n];
                    Bs[buf^1][r][n] = Vb[(size_t)(c0+r)*NPIX + nn + n];
                }
            }
            MMA_CHUNK_G(&As[buf][0][0], LDA, &Bs[buf][0][0], LDA, 0, acc, lane, wm, wn);
        }
        float* ob = g_kvp + (size_t)bsp*CH*CH;
        const int r0 = lane >> 2, c2 = (lane & 3)*2;
        #pragma unroll
        for (int mi = 0; mi < 2; mi++) {
            int k_lo = k0 + wm*32 + mi*16 + r0;
            int k_hi = k_lo + 8;
            #pragma unroll
            for (int nj = 0; nj < 8; nj++) {
                int c = c0 + wn*64 + nj*8 + c2;
                *(float2*)(ob + (size_t)k_lo*CH + c) = make_float2(acc[mi][nj][0], acc[mi][nj][1]);
                *(float2*)(ob + (size_t)k_hi*CH + c) = make_float2(acc[mi][nj][2], acc[mi][nj][3]);
            }
        }
    } else if (bx < POST_QS) {
        const int bq = bx - POST_KV;
        const int lane = tid & 31, wid = tid >> 5;
        const int b = bq >> 7;
        fs[tid] = g_ksum[b*CH + tid];
        __syncthreads();
        const int t0 = bq*32 + wid*4;
        #pragma unroll
        for (int j = 0; j < 4; j++) {
            int t = t0 + j;
            uint4 v = *(const uint4*)(g_Qt + (size_t)t*256 + lane*8);
            const __nv_bfloat16* qq = (const __nv_bfloat16*)&v;
            float sq = 0.f, dt = 0.f;
            #pragma unroll
            for (int k = 0; k < 8; k++) {
                float f = __bfloat162float(qq[k]);
                sq = fmaf(f, f, sq);
                dt = fmaf(f, fs[lane*8 + k], dt);
            }
            #pragma unroll
            for (int m = 16; m > 0; m >>= 1) {
                sq += __shfl_xor_sync(0xffffffffu, sq, m);
                dt += __shfl_xor_sync(0xffffffffu, dt, m);
            }
            if (lane == 0) {
                float iq = 1.0f / sqrtf(sq);
                g_invQ[t] = iq;
                g_denom[t] = 1.0f / (4096.0f + dt*iq + 1e-6f);
            }
        }
    } else {
        const int b = bx - POST_QS;
        fs[tid] = g_vsum[b*CH + tid];
        __syncthreads();
        float s = 0.f;
        const float* rp = rw + (size_t)tid*CH;
        #pragma unroll 8
        for (int c = 0; c < CH; c++) s = fmaf(rp[c], fs[c], s);
        g_rv[b*CH + tid] = s;
    }
}

// ---------------- A = rw @ kv^T, kvred folded in ----------------
__global__ __launch_bounds__(256) void k_nt(const float* __restrict__ rw,
                                            __nv_bfloat16* __restrict__ out)
{
    __shared__ float As[32][65];
    __shared__ float Bs[32][65];
    const int b = blockIdx.z;
    const int i0 = blockIdx.y*64, j0 = blockIdx.x*64;
    const float* P = g_kvp + (size_t)b*4*65536;
    const int tid = threadIdx.x;
    const int ty = tid >> 4, tx = tid & 15;
    float acc[4][4];
    #pragma unroll
    for (int i = 0; i < 4; i++) {
        #pragma unroll
        for (int j = 0; j < 4; j++) acc[i][j] = 0.f;
    }

    for (int l0 = 0; l0 < CH; l0 += 32) {
        #pragma unroll
        for (int r = 0; r < 8; r++) {
            int e = tid + r*256;
            int ii = e >> 5, ll = e & 31;
            As[ll][ii] = rw[(size_t)(i0+ii)*CH + l0 + ll];
        }
        #pragma unroll
        for (int r = 0; r < 8; r++) {
            int e = tid + r*256;
            int jj = e >> 5, ll = e & 31;
            size_t off = (size_t)(j0+jj)*CH + l0 + ll;
            Bs[ll][jj] = (P[off] + P[65536 + off]) + (P[2*65536 + off] + P[3*65536 + off]);
        }
        __syncthreads();
        #pragma unroll
        for (int ll = 0; ll < 32; ll++) {
            float ar[4], br[4];
            #pragma unroll
            for (int i = 0; i < 4; i++) ar[i] = As[ll][ty*4+i];
            #pragma unroll
            for (int j = 0; j < 4; j++) br[j] = Bs[ll][tx*4+j];
            #pragma unroll
            for (int i = 0; i < 4; i++) {
                #pragma unroll
                for (int j = 0; j < 4; j++)
                    acc[i][j] = fmaf(ar[i], br[j], acc[i][j]);
            }
        }
        __syncthreads();
    }
    __nv_bfloat16* ob = out + (size_t)b*CH*CH;
    #pragma unroll
    for (int i = 0; i < 4; i++) {
        #pragma unroll
        for (int j = 0; j < 4; j++)
            ob[(size_t)(i0+ty*4+i)*CH + j0 + tx*4 + j] = __float2bfloat16(acc[i][j]);
    }
}

// ---------------- bf16 MMA attn GEMM: 128 threads, 64x64 warp tiles ----------------
__global__ __launch_bounds__(128) void k_attn_tc(const float* __restrict__ rb)
{
    __shared__ __align__(16) __nv_bfloat16 As[2][128][LDA];
    __shared__ __align__(16) __nv_bfloat16 Bs[2][128][LDA];
    const int b  = blockIdx.z;
    const int o0 = blockIdx.y * 128;
    const int n0 = blockIdx.x * 128;
    const __nv_bfloat16* Am = g_Abf + (size_t)b*CH*CH;
    const __nv_bfloat16* Qt = g_Qt + (size_t)b*NPIX*CH;
    const int tid = threadIdx.x;
    const int wid = tid >> 5, lane = tid & 31;
    const int wm = wid & 1, wn = wid >> 1;

    float acc[4][8][4];
    ACC_ZERO4(acc);

    #pragma unroll
    for (int i = 0; i < 4; i++) {
        int e = tid + i*128;
        int o = e >> 2, cq = e & 3;
        *(uint4*)&As[0][o][cq*8] = *(const uint4*)(Am + (size_t)(o0+o)*CH + cq*8);
    }
    #pragma unroll
    for (int i = 0; i < 4; i++) {
        int e = tid + i*128;
        int n = e >> 2, cq = e & 3;
        *(uint4*)&Bs[0][n][cq*8] = *(const uint4*)(Qt + (size_t)(n0+n)*256 + cq*8);
    }

    for (int kc = 0; kc < 8; kc++) {
        __syncthreads();
        int buf = kc & 1;
        if (kc + 1 < 8) {
            int cb = (kc + 1) * 32;
            #pragma unroll
            for (int i = 0; i < 4; i++) {
                int e = tid + i*128;
                int o = e >> 2, cq = e & 3;
                *(uint4*)&As[buf^1][o][cq*8] = *(const uint4*)(Am + (size_t)(o0+o)*CH + cb + cq*8);
            }
            #pragma unroll
            for (int i = 0; i < 4; i++) {
                int e = tid + i*128;
                int n = e >> 2, cq = e & 3;
                *(uint4*)&Bs[buf^1][n][cq*8] = *(const uint4*)(Qt + (size_t)(n0+n)*256 + cb + cq*8);
            }
        }
        MMA_CHUNK4(&As[buf][0][0], LDA, &Bs[buf][0][0], LDA, 0, acc, lane, wm, wn);
    }

    __nv_bfloat16* ob = g_attnbf + (size_t)b*CH*NPIX;
    const int r0 = lane >> 2, c2 = (lane & 3)*2;
    #pragma unroll
    for (int mi = 0; mi < 4; mi++) {
        int o_lo = o0 + wm*64 + mi*16 + r0;
        int o_hi = o_lo + 8;
        float rvlo = g_rv[b*CH + o_lo], rvhi = g_rv[b*CH + o_hi];
        float rblo = rb[o_lo], rbhi = rb[o_hi];
        #pragma unroll
        for (int nj = 0; nj < 8; nj++) {
            int n = n0 + wn*64 + nj*8 + c2;
            float iq0 = g_invQ[b*NPIX + n],     dn0 = g_denom[b*NPIX + n];
            float iq1 = g_invQ[b*NPIX + n + 1], dn1 = g_denom[b*NPIX + n + 1];
            __nv_bfloat162 vlo, vhi;
            vlo.x = __float2bfloat16(fmaf(fmaf(iq0, acc[mi][nj][0], rvlo), dn0, rblo));
            vlo.y = __float2bfloat16(fmaf(fmaf(iq1, acc[mi][nj][1], rvlo), dn1, rblo));
            vhi.x = __float2bfloat16(fmaf(fmaf(iq0, acc[mi][nj][2], rvhi), dn0, rbhi));
            vhi.y = __float2bfloat16(fmaf(fmaf(iq1, acc[mi][nj][3], rvhi), dn1, rbhi));
            *(__nv_bfloat162*)(ob + (size_t)o_lo*NPIX + n) = vlo;
            *(__nv_bfloat162*)(ob + (size_t)o_hi*NPIX + n) = vhi;
        }
    }
}

// ---------------- bf16 MMA 3x3 conv: 4 warps, 64x64 warp tiles ----------------
#define CONV_BW_WORDS (8*GST)
#define CONV_A_BYTES  (9*128*LDA*2)
#define CONV_SMEM     (CONV_A_BYTES + CONV_BW_WORDS*4)

__device__ __forceinline__ void conv_fillB4(uint32_t* __restrict__ Bw,
                                            const __nv_bfloat16* __restrict__ inb,
                                            int cbase, int pr0, int tid)
{
    #pragma unroll
    for (int it = 0; it < 4; it++) {
        int e = tid + it*128;
        int kw = e >> 5;
        int row = (e >> 3) & 3;
        int seg = e & 7;
        int g = (kw & 3) + ((kw >> 3) << 2);
        int s = (kw >> 2) & 1;
        int gr = pr0 - 1 + row;
        uint32_t* dst = Bw + g*GST + (row*66 + 1 + seg*8)*2 + s;
        if ((unsigned)gr < IMW) {
            const __nv_bfloat16* q = inb + (size_t)(cbase + kw*2)*NPIX + gr*IMW + seg*8;
            uint4 lo4 = *(const uint4*)q;
            uint4 hi4 = *(const uint4*)(q + NPIX);
            const unsigned short* ls = (const unsigned short*)&lo4;
            const unsigned short* hs = (const unsigned short*)&hi4;
            #pragma unroll
            for (int j = 0; j < 8; j++)
                dst[j*2] = (uint32_t)ls[j] | ((uint32_t)hs[j] << 16);
        } else {
            #pragma unroll
            for (int j = 0; j < 8; j++) dst[j*2] = 0u;
        }
    }
}

__global__ __launch_bounds__(128) void k_conv_tc(const __nv_bfloat16* __restrict__ in,
                                                 const __nv_bfloat16* __restrict__ wt,
                                                 const float* __restrict__ bias,
                                                 const float* __restrict__ xres,
                                                 float* __restrict__ out_f,
                                                 __nv_bfloat16* __restrict__ out_bf,
                                                 int fuse)
{
    extern __shared__ __align__(16) char dsm[];
    __nv_bfloat16* Asm = (__nv_bfloat16*)dsm;
    uint32_t* Bw = (uint32_t*)(dsm + CONV_A_BYTES);
    const int b   = blockIdx.z;
    const int o0  = blockIdx.y * 128;
    const int pr0 = blockIdx.x * 2;
    const __nv_bfloat16* inb = in + (size_t)b*CH*NPIX;
    const int tid = threadIdx.x;
    const int wid = tid >> 5, lane = tid & 31;
    const int wm = wid & 1;
    const int wn = wid >> 1;

    float acc[4][8][4];
    ACC_ZERO4(acc);

    {
        int kw = tid >> 3;
        int row = (tid >> 1) & 3;
        int side = tid & 1;
        int g = (kw & 3) + ((kw >> 3) << 2);
        int s = (kw >> 2) & 1;
        Bw[g*GST + (row*66 + side*65)*2 + s] = 0u;
    }

    for (int cb = 0; cb < 8; cb++) {
        __syncthreads();
        #pragma unroll
        for (int i = 0; i < 36; i++) {
            int e = tid + i*128;
            int t = e >> 9;
            int rem = e & 511;
            int o = rem >> 2, cq = rem & 3;
            *(uint4*)(Asm + ((size_t)t*128 + o)*LDA + cq*8) =
                *(const uint4*)(wt + ((size_t)t*256 + o0 + o)*256 + cb*32 + cq*8);
        }
        conv_fillB4(Bw, inb, cb*32, pr0, tid);
        __syncthreads();
        #pragma unroll
        for (int t = 0; t < 9; t++) {
            const int dy = t / 3 - 1, dx = t % 3 - 1;
            const int pos0 = (1 + wn + dy) * 66 + 1 + dx;
            #pragma unroll
            for (int ks = 0; ks < 2; ks++) {
                uint32_t a_[4][4];
                #pragma unroll
                for (int mi = 0; mi < 4; mi++)
                    ldsm_x4(a_[mi], smem_u32(Asm + ((size_t)t*128 + wm*64 + mi*16 + (lane&15))*LDA
                                             + ks*16 + (lane>>4)*8));
                const uint32_t* bp = Bw + ((lane&3) + ks*4)*GST
                                   + (pos0 + (lane>>2))*2;
                #pragma unroll
                for (int f = 0; f < 8; f++) {
                    uint2 bb = *(const uint2*)(bp + f*16);
                    #pragma unroll
                    for (int mi = 0; mi < 4; mi++)
                        mma16816(acc[mi][f], a_[mi], bb.x, bb.y);
                }
            }
        }
    }

    const int r0 = lane >> 2, c2 = (lane & 3)*2;
    const int pxbase = pr0*64;
    if (fuse) {
        const float* xb = xres + (size_t)b*CH*NPIX;
        float* ob = out_f + (size_t)b*CH*NPIX;
        #pragma unroll
        for (int mi = 0; mi < 4; mi++) {
            int o_lo = o0 + wm*64 + mi*16 + r0;
            int o_hi = o_lo + 8;
            float blo = bias[o_lo], bhi = bias[o_hi];
            #pragma unroll
            for (int f = 0; f < 8; f++) {
                int px = pxbase + wn*64 + f*8 + c2;
                float a0 = acc[mi][f][0] + blo, a1 = acc[mi][f][1] + blo;
                float a2 = acc[mi][f][2] + bhi, a3 = acc[mi][f][3] + bhi;
                float2 xlo = *(const float2*)(xb + (size_t)o_lo*NPIX + px);
                float2 xhi = *(const float2*)(xb + (size_t)o_hi*NPIX + px);
                a0 = fmaf(a0, xlo.x, xlo.x);
                a1 = fmaf(a1, xlo.y, xlo.y);
                a2 = fmaf(a2, xhi.x, xhi.x);
                a3 = fmaf(a3, xhi.y, xhi.y);
                *(float2*)(ob + (size_t)o_lo*NPIX + px) = make_float2(a0, a1);
                *(float2*)(ob + (size_t)o_hi*NPIX + px) = make_float2(a2, a3);
            }
        }
    } else {
        __nv_bfloat16* ob = out_bf + (size_t)b*CH*NPIX;
        #pragma unroll
        for (int mi = 0; mi < 4; mi++) {
            int o_lo = o0 + wm*64 + mi*16 + r0;
            int o_hi = o_lo + 8;
            float blo = bias[o_lo], bhi = bias[o_hi];
            #pragma unroll
            for (int f = 0; f < 8; f++) {
                int px = pxbase + wn*64 + f*8 + c2;
                __nv_bfloat162 vlo, vhi;
                vlo.x = __float2bfloat16(acc[mi][f][0] + blo);
                vlo.y = __float2bfloat16(acc[mi][f][1] + blo);
                vhi.x = __float2bfloat16(acc[mi][f][2] + bhi);
                vhi.y = __float2bfloat16(acc[mi][f][3] + bhi);
                *(__nv_bfloat162*)(ob + (size_t)o_lo*NPIX + px) = vlo;
                *(__nv_bfloat162*)(ob + (size_t)o_hi*NPIX + px) = vhi;
            }
        }
    }
}

// ---------------- launcher ----------------
extern "C" void kernel_launch(void* const* d_in, const int* in_sizes, int n_in,
                              void* d_out, int out_size)
{
    (void)in_sizes; (void)n_in; (void)out_size;
    const float* x   = (const float*)d_in[0];
    const float* qw  = (const float*)d_in[1];
    const float* qb  = (const float*)d_in[2];
    const float* kw  = (const float*)d_in[3];
    const float* kb  = (const float*)d_in[4];
    const float* vw  = (const float*)d_in[5];
    const float* vb  = (const float*)d_in[6];
    const float* rw  = (const float*)d_in[7];
    const float* rb  = (const float*)d_in[8];
    const float* c1w = (const float*)d_in[9];
    const float* c1b = (const float*)d_in[10];
    const float* c2w = (const float*)d_in[11];
    const float* c2b = (const float*)d_in[12];
    float* out = (float*)d_out;

    __nv_bfloat16 *pKbf, *pVbf, *pattnbf, *ph1bf, *pAbf, *pwqkv, *pwc1, *pwc2;
    cudaGetSymbolAddress((void**)&pKbf,   g_Kbf);
    cudaGetSymbolAddress((void**)&pVbf,   g_Vbf);
    cudaGetSymbolAddress((void**)&pattnbf,g_attnbf);
    cudaGetSymbolAddress((void**)&ph1bf,  g_h1bf);
    cudaGetSymbolAddress((void**)&pAbf,   g_Abf);
    cudaGetSymbolAddress((void**)&pwqkv,  g_wqkv);
    cudaGetSymbolAddress((void**)&pwc1,   g_wc1b);
    cudaGetSymbolAddress((void**)&pwc2,   g_wc2b);

    static int attr_set = 0;
    if (!attr_set) {
        cudaFuncSetAttribute(k_proj3,   cudaFuncAttributeMaxDynamicSharedMemorySize, P3_SMEM);
        cudaFuncSetAttribute(k_conv_tc, cudaFuncAttributeMaxDynamicSharedMemorySize, CONV_SMEM);
        attr_set = 1;
    }

    dim3 gproj(32, 2, BSZ);
    dim3 gnt(4, 4, BSZ);
    dim3 gconv(32, 2, BSZ);

    k_prep<<<PREP_TOT, 256>>>(x, qw, kw, vw, c1w, c2w);
    k_proj3<<<gproj, 128, P3_SMEM>>>(pwqkv, qb, kb, vb, pKbf, pVbf);
    k_mid<<<(BSZ*NPIX/2)/256, 256>>>();
    k_colsums<<<BSZ*CH, 256>>>();
    k_post<<<POST_TOT, 256>>>(rw);
    k_nt<<<gnt, 256>>>(rw, pAbf);
    k_attn_tc<<<gproj, 128>>>(rb);
    k_conv_tc<<<gconv, 128, CONV_SMEM>>>(pattnbf, pwc1, c1b, (const float*)0, (float*)0, ph1bf, 0);
    k_conv_tc<<<gconv, 128, CONV_SMEM>>>(ph1bf, pwc2, c2b, x, out, (__nv_bfloat16*)0, 1);
}